// round 1
// baseline (speedup 1.0000x reference)
#include <cuda_runtime.h>
#include <math.h>

// Problem constants
#define BSZ 32
#define SL  512
#define HD  1024
#define DE  1024
#define DT  64
#define ROWS (BSZ*SL)          // 16384

// Scratch (alloc-free: __device__ globals)
__device__ float g_cat[(size_t)ROWS * 2048];   // [:, :1024]=cas_hidden, [:,1024:]=depend
__device__ float g_head[(size_t)ROWS * HD];    // head, later reused for prod=map1*time_inf
__device__ float g_tail[(size_t)ROWS * HD];    // tail, later reused for time_inf
__device__ float g_logits[(size_t)BSZ * SL * SL];
__device__ float g_enc[(size_t)ROWS * HD];     // encoding
__device__ float g_m[ROWS];
__device__ float g_a[ROWS];

__device__ __forceinline__ float eluf(float x) {
    return x > 0.f ? x : expm1f(x);
}

// ---------------------------------------------------------------------------
// Generic tiled SGEMM: C = epilogue(A @ B(^T) + bias)
// BM=BN=128, BK=8, 256 threads, 8x8 per-thread tile.
// EPI: 0=none, 1=bias, 2=elu*rowmask, 3=sigmoid-gate-blend, 4=elu, 5=elu*aux
// NT: if true, B is [N,K] row-major (C = A @ B^T)
// ---------------------------------------------------------------------------
template<int EPI, bool NT>
__global__ __launch_bounds__(256)
void gemm_k(const float* A, const float* B, float* C,
            int M, int N, int K, int lda, int ldb, int ldc,
            long sA, long sB, long sC,
            const float* bias, const float* rowmask,
            const float* aux, int auxld, int auxoff)
{
    constexpr int BM = 128, BN = 128, BK = 8;
    int z = blockIdx.z;
    A += (size_t)z * sA;
    B += (size_t)z * sB;
    C += (size_t)z * sC;

    int row0 = blockIdx.y * BM;
    int col0 = blockIdx.x * BN;

    __shared__ float As[BK][BM];
    __shared__ float Bs[BK][BN];

    int tid = threadIdx.x;
    int tx = tid & 15;        // 16 cols of threads
    int ty = tid >> 4;        // 16 rows of threads

    float acc[8][8];
#pragma unroll
    for (int i = 0; i < 8; i++)
#pragma unroll
        for (int j = 0; j < 8; j++) acc[i][j] = 0.f;

    const int ar = tid >> 1;          // 0..127
    const int ac = (tid & 1) * 4;     // 0 or 4

    for (int k0 = 0; k0 < K; k0 += BK) {
        // A tile: 128 rows x 8 k, transposed into As[k][m]
        float4 av = *(const float4*)(A + (size_t)(row0 + ar) * lda + (k0 + ac));
        As[ac + 0][ar] = av.x; As[ac + 1][ar] = av.y;
        As[ac + 2][ar] = av.z; As[ac + 3][ar] = av.w;

        if (NT) {
            // B is [N,K]: load 128 n-rows x 8 k, transpose into Bs[k][n]
            float4 bv = *(const float4*)(B + (size_t)(col0 + ar) * ldb + (k0 + ac));
            Bs[ac + 0][ar] = bv.x; Bs[ac + 1][ar] = bv.y;
            Bs[ac + 2][ar] = bv.z; Bs[ac + 3][ar] = bv.w;
        } else {
            // B is [K,N]: load 8 k-rows x 128 n, direct
            int br = tid >> 5;            // 0..7
            int bc = (tid & 31) * 4;      // 0..124
            float4 bv = *(const float4*)(B + (size_t)(k0 + br) * ldb + (col0 + bc));
            *(float4*)&Bs[br][bc] = bv;
        }
        __syncthreads();

#pragma unroll
        for (int k = 0; k < BK; k++) {
            float a[8], b[8];
            *(float4*)(a)     = *(const float4*)&As[k][ty * 8];
            *(float4*)(a + 4) = *(const float4*)&As[k][ty * 8 + 4];
            *(float4*)(b)     = *(const float4*)&Bs[k][tx * 8];
            *(float4*)(b + 4) = *(const float4*)&Bs[k][tx * 8 + 4];
#pragma unroll
            for (int i = 0; i < 8; i++)
#pragma unroll
                for (int j = 0; j < 8; j++)
                    acc[i][j] = fmaf(a[i], b[j], acc[i][j]);
        }
        __syncthreads();
    }

    // Epilogue
#pragma unroll
    for (int i = 0; i < 8; i++) {
        int m = row0 + ty * 8 + i;
        float rm = 1.f;
        if (EPI == 2 || EPI == 3) rm = rowmask[m];
        float out[8];
#pragma unroll
        for (int j = 0; j < 8; j++) {
            int n = col0 + tx * 8 + j;
            float v = acc[i][j];
            if (EPI != 0) v += bias[n];
            if (EPI == 2) {
                v = eluf(v) * rm;
            } else if (EPI == 3) {
                float g = 1.f / (1.f + expf(-v));
                float h = aux[(size_t)m * auxld + n];
                float d = aux[(size_t)m * auxld + n + auxoff];
                v = (g * h + (1.f - g) * d) * rm;
            } else if (EPI == 4) {
                v = eluf(v);
            } else if (EPI == 5) {
                v = eluf(v) * aux[(size_t)m * auxld + n];
            }
            out[j] = v;
        }
        *(float4*)&C[(size_t)m * ldc + col0 + tx * 8]     = *(float4*)(out);
        *(float4*)&C[(size_t)m * ldc + col0 + tx * 8 + 4] = *(float4*)(out + 4);
    }
}

// ---------------------------------------------------------------------------
// Block reduction (max or sum), works for 256 or 512 threads
// ---------------------------------------------------------------------------
__device__ __forceinline__ float blockReduce(float v, bool isMax)
{
    __shared__ float sh[32];
    int lane = threadIdx.x & 31;
    int w = threadIdx.x >> 5;
    int nw = blockDim.x >> 5;
#pragma unroll
    for (int o = 16; o; o >>= 1) {
        float u = __shfl_xor_sync(0xffffffffu, v, o);
        v = isMax ? fmaxf(v, u) : v + u;
    }
    if (lane == 0) sh[w] = v;
    __syncthreads();
    if (w == 0) {
        v = (lane < nw) ? sh[lane] : (isMax ? -INFINITY : 0.f);
#pragma unroll
        for (int o = 16; o; o >>= 1) {
            float u = __shfl_xor_sync(0xffffffffu, v, o);
            v = isMax ? fmaxf(v, u) : v + u;
        }
        if (lane == 0) sh[0] = v;
    }
    __syncthreads();
    v = sh[0];
    __syncthreads();  // protect sh before a subsequent call
    return v;
}

// Masked causal softmax over attention logits rows (in place). 256 thr/row.
__global__ void attn_softmax_k(float* logits, const float* mask)
{
    int row = blockIdx.x;            // b*512 + i
    int b = row >> 9;
    int i = row & 511;
    const float* mrow = mask + ((size_t)b << 9);
    float* L = logits + ((size_t)row << 9);
    int t = threadIdx.x;
    int j0 = t, j1 = t + 256;
    bool a0 = (i > j0) && (mrow[j0] > 0.f);
    bool a1 = (i > j1) && (mrow[j1] > 0.f);
    float x0 = L[j0] + (a0 ? 0.f : -1e30f);
    float x1 = L[j1] + (a1 ? 0.f : -1e30f);
    float mx = blockReduce(fmaxf(x0, x1), true);
    float e0 = expf(x0 - mx);
    float e1 = expf(x1 - mx);
    float s = blockReduce(e0 + e1, false);
    float inv = 1.f / s;
    L[j0] = a0 ? e0 * inv : 0.f;
    L[j1] = a1 ? e1 * inv : 0.f;
}

// m[row] = dot(prod[row,:], Wm2) + bm2
__global__ void rowdot_k(const float* prod, const float* w, const float* b, float* m)
{
    int row = blockIdx.x;
    const float* p = prod + ((size_t)row << 10);
    float s = 0.f;
    for (int h = threadIdx.x; h < HD; h += 256) s = fmaf(p[h], w[h], s);
    s = blockReduce(s, false);
    if (threadIdx.x == 0) m[row] = s + b[0];
}

// Per-batch masked softmax along sequence. 512 thr/batch.
__global__ void seq_softmax_k(const float* m, const float* mask, float* a)
{
    int b = blockIdx.x;
    int t = threadIdx.x;
    size_t idx = ((size_t)b << 9) + t;
    float msk = mask[idx];
    float x = m[idx] + (msk > 0.f ? 0.f : -1e30f);
    float mx = blockReduce(x, true);
    float e = expf(x - mx);
    float s = blockReduce(e, false);
    a[idx] = (msk > 0.f) ? e / s : 0.f;
}

// out = a[row] * encoding  (float4, one element per thread)
__global__ void scale_k(const float* a, const float* enc, float* out)
{
    size_t i = (size_t)blockIdx.x * blockDim.x + threadIdx.x;  // float4 index
    float4 e = ((const float4*)enc)[i];
    float s = a[(i * 4) >> 10];
    float4 o;
    o.x = e.x * s; o.y = e.y * s; o.z = e.z * s; o.w = e.w * s;
    ((float4*)out)[i] = o;
}

extern "C" void kernel_launch(void* const* d_in, const int* in_sizes, int n_in,
                              void* d_out, int out_size)
{
    const float* cas_emb     = (const float*)d_in[0];
    const float* cas_mask    = (const float*)d_in[1];   // [32,512,1] -> 16384 floats
    const float* time_weight = (const float*)d_in[2];
    const float* W1  = (const float*)d_in[3];
    const float* b1  = (const float*)d_in[4];
    const float* Wh  = (const float*)d_in[5];
    const float* bh  = (const float*)d_in[6];
    const float* Wt  = (const float*)d_in[7];
    const float* bt  = (const float*)d_in[8];
    const float* Wg  = (const float*)d_in[9];
    const float* bg  = (const float*)d_in[10];
    const float* Wm1 = (const float*)d_in[11];
    const float* bm1 = (const float*)d_in[12];
    const float* Wti = (const float*)d_in[13];
    const float* bti = (const float*)d_in[14];
    const float* Wm2 = (const float*)d_in[15];
    const float* bm2 = (const float*)d_in[16];
    float* out = (float*)d_out;

    float *cat, *head, *tail, *logits, *enc, *mvec, *avec;
    cudaGetSymbolAddress((void**)&cat,    g_cat);
    cudaGetSymbolAddress((void**)&head,   g_head);
    cudaGetSymbolAddress((void**)&tail,   g_tail);
    cudaGetSymbolAddress((void**)&logits, g_logits);
    cudaGetSymbolAddress((void**)&enc,    g_enc);
    cudaGetSymbolAddress((void**)&mvec,   g_m);
    cudaGetSymbolAddress((void**)&avec,   g_a);

    dim3 blk(256);

    // 1) cas_hidden = elu(cas_emb @ W1 + b1) * mask -> cat[:, :1024]
    gemm_k<2, false><<<dim3(HD/128, ROWS/128, 1), blk>>>(
        cas_emb, W1, cat, ROWS, HD, DE, DE, HD, 2048,
        0, 0, 0, b1, cas_mask, nullptr, 0, 0);

    // 2) head = cas_hidden @ Wh + bh
    gemm_k<1, false><<<dim3(HD/128, ROWS/128, 1), blk>>>(
        cat, Wh, head, ROWS, HD, HD, 2048, HD, HD,
        0, 0, 0, bh, nullptr, nullptr, 0, 0);

    // 3) tail = cas_hidden @ Wt + bt
    gemm_k<1, false><<<dim3(HD/128, ROWS/128, 1), blk>>>(
        cat, Wt, tail, ROWS, HD, HD, 2048, HD, HD,
        0, 0, 0, bt, nullptr, nullptr, 0, 0);

    // 4) logits[b] = head_b @ tail_b^T   (batched NT)
    gemm_k<0, true><<<dim3(SL/128, SL/128, BSZ), blk>>>(
        head, tail, logits, SL, SL, HD, HD, HD, SL,
        (long)SL * HD, (long)SL * HD, (long)SL * SL,
        nullptr, nullptr, nullptr, 0, 0);

    // 5) masked causal softmax (in place) -> score
    attn_softmax_k<<<ROWS, 256>>>(logits, cas_mask);

    // 6) depend[b] = score_b @ cas_hidden_b -> cat[:, 1024:]
    gemm_k<0, false><<<dim3(HD/128, SL/128, BSZ), blk>>>(
        logits, cat, cat + 1024, SL, HD, SL, SL, 2048, 2048,
        (long)SL * SL, (long)SL * 2048, (long)SL * 2048,
        nullptr, nullptr, nullptr, 0, 0);

    // 7) gate + blend: enc = (g*h + (1-g)*d) * mask, g = sigmoid(cat @ Wg + bg)
    gemm_k<3, false><<<dim3(HD/128, ROWS/128, 1), blk>>>(
        cat, Wg, enc, ROWS, HD, 2048, 2048, HD, HD,
        0, 0, 0, bg, cas_mask, cat, 2048, 1024);

    // 8) time_inf = elu(time_weight @ Wti + bti) -> tail (reuse)
    gemm_k<4, false><<<dim3(HD/128, ROWS/128, 1), blk>>>(
        time_weight, Wti, tail, ROWS, HD, DT, DT, HD, HD,
        0, 0, 0, bti, nullptr, nullptr, 0, 0);

    // 9) prod = elu(enc @ Wm1 + bm1) * time_inf -> head (reuse)
    gemm_k<5, false><<<dim3(HD/128, ROWS/128, 1), blk>>>(
        enc, Wm1, head, ROWS, HD, HD, HD, HD, HD,
        0, 0, 0, bm1, nullptr, tail, HD, 0);

    // 10) m = prod @ Wm2 + bm2
    rowdot_k<<<ROWS, 256>>>(head, Wm2, bm2, mvec);

    // 11) a = masked softmax over sequence
    seq_softmax_k<<<BSZ, 512>>>(mvec, cas_mask, avec);

    // 12) out = a * encoding
    scale_k<<<(ROWS * HD / 4) / 256, 256>>>(avec, enc, out);
}

// round 2
// speedup vs baseline: 2.3117x; 2.3117x over previous
#include <cuda_runtime.h>
#include <math.h>
#include <stdint.h>

// Problem constants
#define BSZ 32
#define SL  512
#define HD  1024
#define DE  1024
#define DT  64
#define ROWS (BSZ*SL)          // 16384

// Scratch (alloc-free: __device__ globals)
__device__ float g_cat[(size_t)ROWS * 2048];   // [:, :1024]=cas_hidden, [:,1024:]=depend
__device__ float g_head[(size_t)ROWS * HD];    // head, later reused for prod
__device__ float g_tail[(size_t)ROWS * HD];    // tail, later reused for time_inf
__device__ float g_logits[(size_t)BSZ * SL * SL];
__device__ float g_enc[(size_t)ROWS * HD];     // encoding
__device__ float g_m[ROWS];
__device__ float g_a[ROWS];

__device__ __forceinline__ float eluf(float x) {
    return x > 0.f ? x : expm1f(x);
}

__device__ __forceinline__ uint32_t f2tf(float x) {
    uint32_t r;
    asm("cvt.rna.tf32.f32 %0, %1;" : "=r"(r) : "f"(x));
    return r;
}

__device__ __forceinline__ void mma_tf32(float c[4], const uint32_t a[4], const uint32_t b[2]) {
    asm volatile(
        "mma.sync.aligned.m16n8k8.row.col.f32.tf32.tf32.f32 "
        "{%0,%1,%2,%3},{%4,%5,%6,%7},{%8,%9},{%0,%1,%2,%3};"
        : "+f"(c[0]), "+f"(c[1]), "+f"(c[2]), "+f"(c[3])
        : "r"(a[0]), "r"(a[1]), "r"(a[2]), "r"(a[3]), "r"(b[0]), "r"(b[1]));
}

#define CP16(dst, src) \
    asm volatile("cp.async.cg.shared.global [%0], [%1], 16;" :: "r"(dst), "l"(src))
#define CP_COMMIT asm volatile("cp.async.commit_group;")
#define CP_WAIT1  asm volatile("cp.async.wait_group 1;")
#define CP_WAIT0  asm volatile("cp.async.wait_group 0;")

// ---------------------------------------------------------------------------
// TF32 tensor-core GEMM: C = epilogue(A @ B(^T) + bias)
// BM=BN=128, BK=32, 256 threads (8 warps in 2x4), warp tile 64x32,
// mma.m16n8k8 tf32, cp.async double buffering.
// EPI: 0=none, 1=bias, 2=elu*rowmask, 3=sigmoid-gate-blend, 4=elu, 5=elu*aux
// NT: if true, B is [N,K] row-major (C = A @ B^T)
// Bank-conflict-free smem layouts:
//   A : [128][36]  (row-major, pad 4; 36 mod 32 = 4 -> bank = 4*group+tig, all distinct)
//   B NN: [32][136] (k-major, pad 8; 136 mod 32 = 8 -> bank = 8*tig+group, all distinct)
//   B NT: [128][36] (n-major = native mma col-major layout; 4*group+tig)
// ---------------------------------------------------------------------------
template<int EPI, bool NT>
__global__ __launch_bounds__(256)
void gemm_tc(const float* __restrict__ A, const float* __restrict__ B, float* __restrict__ C,
             int M, int N, int K, int lda, int ldb, int ldc,
             long sA, long sB, long sC,
             const float* __restrict__ bias, const float* __restrict__ rowmask,
             const float* __restrict__ aux, int auxld, int auxoff)
{
    constexpr int BK  = 32;
    constexpr int AST = 36;                    // A smem row stride
    constexpr int BST = NT ? 36 : 136;         // B smem row stride
    constexpr int ABUF = 128 * 36;             // 4608 floats per buffer
    constexpr int BBUF = 128 * 36;             // reserve max for either layout

    extern __shared__ float sm[];
    float* As = sm;                  // [2][ABUF]
    float* Bs = sm + 2 * ABUF;       // [2][BBUF]

    int z = blockIdx.z;
    A += (size_t)z * sA;
    B += (size_t)z * sB;
    C += (size_t)z * sC;

    const int row0 = blockIdx.y * 128;
    const int col0 = blockIdx.x * 128;
    const int tid  = threadIdx.x;
    const int lane = tid & 31;
    const int wid  = tid >> 5;
    const int wr   = wid >> 2;       // 0..1
    const int wc   = wid & 3;        // 0..3
    const int group = lane >> 2;     // 0..7
    const int tig   = lane & 3;      // 0..3

    float acc[4][4][4];
#pragma unroll
    for (int i = 0; i < 4; i++)
#pragma unroll
        for (int j = 0; j < 4; j++)
#pragma unroll
            for (int c = 0; c < 4; c++) acc[i][j][c] = 0.f;

    // ---- async tile loaders ----
    auto loadA = [&](int buf, int k0) {
        float* dst = As + buf * ABUF;
#pragma unroll
        for (int p = 0; p < 4; p++) {
            int idx = tid + p * 256;
            int r = idx >> 3;             // 0..127
            int c = (idx & 7) * 4;        // 0..28
            uint32_t s = (uint32_t)__cvta_generic_to_shared(dst + r * AST + c);
            const float* g = A + (size_t)(row0 + r) * lda + k0 + c;
            CP16(s, g);
        }
    };
    auto loadB = [&](int buf, int k0) {
        float* dst = Bs + buf * BBUF;
        if (NT) {
#pragma unroll
            for (int p = 0; p < 4; p++) {
                int idx = tid + p * 256;
                int r = idx >> 3;         // n: 0..127
                int c = (idx & 7) * 4;    // k: 0..28
                uint32_t s = (uint32_t)__cvta_generic_to_shared(dst + r * BST + c);
                const float* g = B + (size_t)(col0 + r) * ldb + k0 + c;
                CP16(s, g);
            }
        } else {
#pragma unroll
            for (int p = 0; p < 4; p++) {
                int idx = tid + p * 256;
                int r = idx >> 5;          // k: 0..31
                int c = (idx & 31) * 4;    // n: 0..124
                uint32_t s = (uint32_t)__cvta_generic_to_shared(dst + r * BST + c);
                const float* g = B + (size_t)(k0 + r) * ldb + col0 + c;
                CP16(s, g);
            }
        }
    };

    const int nt = K / BK;
    loadA(0, 0); loadB(0, 0); CP_COMMIT;

    for (int t = 0; t < nt; t++) {
        if (t + 1 < nt) {
            loadA((t + 1) & 1, (t + 1) * BK);
            loadB((t + 1) & 1, (t + 1) * BK);
            CP_COMMIT;
            CP_WAIT1;
        } else {
            CP_WAIT0;
        }
        __syncthreads();

        const float* as = As + (t & 1) * ABUF;
        const float* bs = Bs + (t & 1) * BBUF;

#pragma unroll
        for (int kk = 0; kk < BK; kk += 8) {
            uint32_t af[4][4];
#pragma unroll
            for (int mf = 0; mf < 4; mf++) {
                int m = wr * 64 + mf * 16 + group;
                af[mf][0] = f2tf(as[(m)     * AST + kk + tig]);
                af[mf][1] = f2tf(as[(m + 8) * AST + kk + tig]);
                af[mf][2] = f2tf(as[(m)     * AST + kk + tig + 4]);
                af[mf][3] = f2tf(as[(m + 8) * AST + kk + tig + 4]);
            }
            uint32_t bf[4][2];
#pragma unroll
            for (int nf = 0; nf < 4; nf++) {
                int n = wc * 32 + nf * 8 + group;
                if (NT) {
                    bf[nf][0] = f2tf(bs[n * BST + kk + tig]);
                    bf[nf][1] = f2tf(bs[n * BST + kk + tig + 4]);
                } else {
                    bf[nf][0] = f2tf(bs[(kk + tig)     * BST + n]);
                    bf[nf][1] = f2tf(bs[(kk + tig + 4) * BST + n]);
                }
            }
#pragma unroll
            for (int mf = 0; mf < 4; mf++)
#pragma unroll
                for (int nf = 0; nf < 4; nf++)
                    mma_tf32(acc[mf][nf], af[mf], bf[nf]);
        }
        __syncthreads();
    }

    // ---- fused epilogue ----
#pragma unroll
    for (int mf = 0; mf < 4; mf++) {
        int rbase = row0 + wr * 64 + mf * 16 + group;
#pragma unroll
        for (int half = 0; half < 2; half++) {
            int m = rbase + half * 8;
            float rm = 1.f;
            if (EPI == 2 || EPI == 3) rm = rowmask[m];
#pragma unroll
            for (int nf = 0; nf < 4; nf++) {
                int n = col0 + wc * 32 + nf * 8 + 2 * tig;
                float v0 = acc[mf][nf][half * 2 + 0];
                float v1 = acc[mf][nf][half * 2 + 1];
                if (EPI != 0) { v0 += bias[n]; v1 += bias[n + 1]; }
                if (EPI == 2) {
                    v0 = eluf(v0) * rm;
                    v1 = eluf(v1) * rm;
                } else if (EPI == 3) {
                    float2 h = *(const float2*)&aux[(size_t)m * auxld + n];
                    float2 d = *(const float2*)&aux[(size_t)m * auxld + n + auxoff];
                    float g0 = 1.f / (1.f + expf(-v0));
                    float g1 = 1.f / (1.f + expf(-v1));
                    v0 = (g0 * h.x + (1.f - g0) * d.x) * rm;
                    v1 = (g1 * h.y + (1.f - g1) * d.y) * rm;
                } else if (EPI == 4) {
                    v0 = eluf(v0);
                    v1 = eluf(v1);
                } else if (EPI == 5) {
                    float2 ax = *(const float2*)&aux[(size_t)m * auxld + n];
                    v0 = eluf(v0) * ax.x;
                    v1 = eluf(v1) * ax.y;
                }
                *(float2*)&C[(size_t)m * ldc + n] = make_float2(v0, v1);
            }
        }
    }
}

// ---------------------------------------------------------------------------
// Block reduction (max or sum)
// ---------------------------------------------------------------------------
__device__ __forceinline__ float blockReduce(float v, bool isMax)
{
    __shared__ float sh[32];
    int lane = threadIdx.x & 31;
    int w = threadIdx.x >> 5;
    int nw = blockDim.x >> 5;
#pragma unroll
    for (int o = 16; o; o >>= 1) {
        float u = __shfl_xor_sync(0xffffffffu, v, o);
        v = isMax ? fmaxf(v, u) : v + u;
    }
    if (lane == 0) sh[w] = v;
    __syncthreads();
    if (w == 0) {
        v = (lane < nw) ? sh[lane] : (isMax ? -INFINITY : 0.f);
#pragma unroll
        for (int o = 16; o; o >>= 1) {
            float u = __shfl_xor_sync(0xffffffffu, v, o);
            v = isMax ? fmaxf(v, u) : v + u;
        }
        if (lane == 0) sh[0] = v;
    }
    __syncthreads();
    v = sh[0];
    __syncthreads();
    return v;
}

// Masked causal softmax over attention logits rows (in place). 256 thr/row.
__global__ void attn_softmax_k(float* logits, const float* mask)
{
    int row = blockIdx.x;            // b*512 + i
    int b = row >> 9;
    int i = row & 511;
    const float* mrow = mask + ((size_t)b << 9);
    float* L = logits + ((size_t)row << 9);
    int t = threadIdx.x;
    int j0 = t, j1 = t + 256;
    bool a0 = (i > j0) && (mrow[j0] > 0.f);
    bool a1 = (i > j1) && (mrow[j1] > 0.f);
    float x0 = L[j0] + (a0 ? 0.f : -1e30f);
    float x1 = L[j1] + (a1 ? 0.f : -1e30f);
    float mx = blockReduce(fmaxf(x0, x1), true);
    float e0 = expf(x0 - mx);
    float e1 = expf(x1 - mx);
    float s = blockReduce(e0 + e1, false);
    float inv = 1.f / s;
    L[j0] = a0 ? e0 * inv : 0.f;
    L[j1] = a1 ? e1 * inv : 0.f;
}

// m[row] = dot(prod[row,:], Wm2) + bm2
__global__ void rowdot_k(const float* prod, const float* w, const float* b, float* m)
{
    int row = blockIdx.x;
    const float* p = prod + ((size_t)row << 10);
    float s = 0.f;
    for (int h = threadIdx.x; h < HD; h += 256) s = fmaf(p[h], w[h], s);
    s = blockReduce(s, false);
    if (threadIdx.x == 0) m[row] = s + b[0];
}

// Per-batch masked softmax along sequence. 512 thr/batch.
__global__ void seq_softmax_k(const float* m, const float* mask, float* a)
{
    int b = blockIdx.x;
    int t = threadIdx.x;
    size_t idx = ((size_t)b << 9) + t;
    float msk = mask[idx];
    float x = m[idx] + (msk > 0.f ? 0.f : -1e30f);
    float mx = blockReduce(x, true);
    float e = expf(x - mx);
    float s = blockReduce(e, false);
    a[idx] = (msk > 0.f) ? e / s : 0.f;
}

// out = a[row] * encoding
__global__ void scale_k(const float* a, const float* enc, float* out)
{
    size_t i = (size_t)blockIdx.x * blockDim.x + threadIdx.x;  // float4 index
    float4 e = ((const float4*)enc)[i];
    float s = a[(i * 4) >> 10];
    float4 o;
    o.x = e.x * s; o.y = e.y * s; o.z = e.z * s; o.w = e.w * s;
    ((float4*)out)[i] = o;
}

static const int SMEM_BYTES = 4 * 4608 * 4;   // 73728

extern "C" void kernel_launch(void* const* d_in, const int* in_sizes, int n_in,
                              void* d_out, int out_size)
{
    const float* cas_emb     = (const float*)d_in[0];
    const float* cas_mask    = (const float*)d_in[1];
    const float* time_weight = (const float*)d_in[2];
    const float* W1  = (const float*)d_in[3];
    const float* b1  = (const float*)d_in[4];
    const float* Wh  = (const float*)d_in[5];
    const float* bh  = (const float*)d_in[6];
    const float* Wt  = (const float*)d_in[7];
    const float* bt  = (const float*)d_in[8];
    const float* Wg  = (const float*)d_in[9];
    const float* bg  = (const float*)d_in[10];
    const float* Wm1 = (const float*)d_in[11];
    const float* bm1 = (const float*)d_in[12];
    const float* Wti = (const float*)d_in[13];
    const float* bti = (const float*)d_in[14];
    const float* Wm2 = (const float*)d_in[15];
    const float* bm2 = (const float*)d_in[16];
    float* out = (float*)d_out;

    float *cat, *head, *tail, *logits, *enc, *mvec, *avec;
    cudaGetSymbolAddress((void**)&cat,    g_cat);
    cudaGetSymbolAddress((void**)&head,   g_head);
    cudaGetSymbolAddress((void**)&tail,   g_tail);
    cudaGetSymbolAddress((void**)&logits, g_logits);
    cudaGetSymbolAddress((void**)&enc,    g_enc);
    cudaGetSymbolAddress((void**)&mvec,   g_m);
    cudaGetSymbolAddress((void**)&avec,   g_a);

    cudaFuncSetAttribute(gemm_tc<0,false>, cudaFuncAttributeMaxDynamicSharedMemorySize, SMEM_BYTES);
    cudaFuncSetAttribute(gemm_tc<0,true >, cudaFuncAttributeMaxDynamicSharedMemorySize, SMEM_BYTES);
    cudaFuncSetAttribute(gemm_tc<1,false>, cudaFuncAttributeMaxDynamicSharedMemorySize, SMEM_BYTES);
    cudaFuncSetAttribute(gemm_tc<2,false>, cudaFuncAttributeMaxDynamicSharedMemorySize, SMEM_BYTES);
    cudaFuncSetAttribute(gemm_tc<3,false>, cudaFuncAttributeMaxDynamicSharedMemorySize, SMEM_BYTES);
    cudaFuncSetAttribute(gemm_tc<4,false>, cudaFuncAttributeMaxDynamicSharedMemorySize, SMEM_BYTES);
    cudaFuncSetAttribute(gemm_tc<5,false>, cudaFuncAttributeMaxDynamicSharedMemorySize, SMEM_BYTES);

    dim3 blk(256);

    // 1) cas_hidden = elu(cas_emb @ W1 + b1) * mask -> cat[:, :1024]
    gemm_tc<2, false><<<dim3(HD/128, ROWS/128, 1), blk, SMEM_BYTES>>>(
        cas_emb, W1, cat, ROWS, HD, DE, DE, HD, 2048,
        0, 0, 0, b1, cas_mask, nullptr, 0, 0);

    // 2) head = cas_hidden @ Wh + bh
    gemm_tc<1, false><<<dim3(HD/128, ROWS/128, 1), blk, SMEM_BYTES>>>(
        cat, Wh, head, ROWS, HD, HD, 2048, HD, HD,
        0, 0, 0, bh, nullptr, nullptr, 0, 0);

    // 3) tail = cas_hidden @ Wt + bt
    gemm_tc<1, false><<<dim3(HD/128, ROWS/128, 1), blk, SMEM_BYTES>>>(
        cat, Wt, tail, ROWS, HD, HD, 2048, HD, HD,
        0, 0, 0, bt, nullptr, nullptr, 0, 0);

    // 4) logits[b] = head_b @ tail_b^T   (batched NT)
    gemm_tc<0, true><<<dim3(SL/128, SL/128, BSZ), blk, SMEM_BYTES>>>(
        head, tail, logits, SL, SL, HD, HD, HD, SL,
        (long)SL * HD, (long)SL * HD, (long)SL * SL,
        nullptr, nullptr, nullptr, 0, 0);

    // 5) masked causal softmax (in place) -> score
    attn_softmax_k<<<ROWS, 256>>>(logits, cas_mask);

    // 6) depend[b] = score_b @ cas_hidden_b -> cat[:, 1024:]
    gemm_tc<0, false><<<dim3(HD/128, SL/128, BSZ), blk, SMEM_BYTES>>>(
        logits, cat, cat + 1024, SL, HD, SL, SL, 2048, 2048,
        (long)SL * SL, (long)SL * 2048, (long)SL * 2048,
        nullptr, nullptr, nullptr, 0, 0);

    // 7) gate + blend: enc = (g*h + (1-g)*d) * mask
    gemm_tc<3, false><<<dim3(HD/128, ROWS/128, 1), blk, SMEM_BYTES>>>(
        cat, Wg, enc, ROWS, HD, 2048, 2048, HD, HD,
        0, 0, 0, bg, cas_mask, cat, 2048, 1024);

    // 8) time_inf = elu(time_weight @ Wti + bti) -> tail (reuse)
    gemm_tc<4, false><<<dim3(HD/128, ROWS/128, 1), blk, SMEM_BYTES>>>(
        time_weight, Wti, tail, ROWS, HD, DT, DT, HD, HD,
        0, 0, 0, bti, nullptr, nullptr, 0, 0);

    // 9) prod = elu(enc @ Wm1 + bm1) * time_inf -> head (reuse)
    gemm_tc<5, false><<<dim3(HD/128, ROWS/128, 1), blk, SMEM_BYTES>>>(
        enc, Wm1, head, ROWS, HD, HD, HD, HD, HD,
        0, 0, 0, bm1, nullptr, tail, HD, 0);

    // 10) m = prod @ Wm2 + bm2
    rowdot_k<<<ROWS, 256>>>(head, Wm2, bm2, mvec);

    // 11) a = masked softmax over sequence
    seq_softmax_k<<<BSZ, 512>>>(mvec, cas_mask, avec);

    // 12) out = a * encoding
    scale_k<<<(ROWS * HD / 4) / 256, 256>>>(avec, enc, out);
}

// round 4
// speedup vs baseline: 2.3286x; 1.0073x over previous
#include <cuda_runtime.h>
#include <math.h>
#include <stdint.h>

// Problem constants
#define BSZ 32
#define SL  512
#define HD  1024
#define DE  1024
#define DT  64
#define ROWS (BSZ*SL)          // 16384

// Scratch (alloc-free: __device__ globals)
__device__ float g_cat[(size_t)ROWS * 2048];    // full: [:, :1024]=cas_hidden, [:,1024:]=depend
__device__ float g_catr[(size_t)ROWS * 2048];   // tf32-rounded copy of g_cat
__device__ float g_head[(size_t)ROWS * HD];     // head (rounded), later prod (full)
__device__ float g_tail[(size_t)ROWS * HD];     // tail (rounded), later time_inf (full)
__device__ float g_logits[(size_t)BSZ * SL * SL];
__device__ float g_enc[(size_t)ROWS * HD];      // encoding (full)
__device__ float g_encr[(size_t)ROWS * HD];     // encoding (rounded)
__device__ float g_embr[(size_t)ROWS * DE];     // rounded cas_emb
__device__ float g_twr[(size_t)ROWS * DT];      // rounded time_weight
__device__ float g_wr[6356992];                 // rounded weights, packed
__device__ float g_m[ROWS];
__device__ float g_a[ROWS];

// weight offsets in g_wr
#define OFF_W1  0
#define OFF_Wh  1048576
#define OFF_Wt  2097152
#define OFF_Wg  3145728
#define OFF_Wm1 5242880
#define OFF_Wti 6291456

__device__ __forceinline__ float eluf(float x) {
    return x > 0.f ? x : expm1f(x);
}

__device__ __forceinline__ uint32_t f2tf(float x) {
    uint32_t r;
    asm("cvt.rna.tf32.f32 %0, %1;" : "=r"(r) : "f"(x));
    return r;
}
__device__ __forceinline__ float roundtf(float x) {
    return __uint_as_float(f2tf(x));
}

__device__ __forceinline__ void mma_tf32(float c[4], const uint32_t a[4], const uint32_t b[2]) {
    asm volatile(
        "mma.sync.aligned.m16n8k8.row.col.f32.tf32.tf32.f32 "
        "{%0,%1,%2,%3},{%4,%5,%6,%7},{%8,%9},{%0,%1,%2,%3};"
        : "+f"(c[0]), "+f"(c[1]), "+f"(c[2]), "+f"(c[3])
        : "r"(a[0]), "r"(a[1]), "r"(a[2]), "r"(a[3]), "r"(b[0]), "r"(b[1]));
}

#define CP16(dst, src) \
    asm volatile("cp.async.cg.shared.global [%0], [%1], 16;" :: "r"(dst), "l"(src))
#define CP_COMMIT asm volatile("cp.async.commit_group;")
#define CP_WAIT1  asm volatile("cp.async.wait_group 1;")
#define CP_WAIT0  asm volatile("cp.async.wait_group 0;")

// ---------------------------------------------------------------------------
// TF32 tensor-core GEMM: C = epilogue(A @ B(^T) + bias)
// Operands in memory are ALREADY tf32-rounded -> mainloop has no cvt.
// BM=BN=128, BK=32, 256 threads (8 warps 2x4), warp tile 64x32, m16n8k8.
// EPI: 0=none, 1=bias, 2=elu*rowmask, 3=sigmoid-gate-blend, 4=elu, 5=elu*aux
// NT : B is [N,K] row-major (C = A @ B^T)
// RND: round main C output to tf32. C2 (optional): rounded secondary output.
// ---------------------------------------------------------------------------
template<int EPI, bool NT, bool RND>
__global__ __launch_bounds__(256, 2)
void gemm_tc(const float* __restrict__ A, const float* __restrict__ B, float* __restrict__ C,
             float* __restrict__ C2,
             int M, int N, int K, int lda, int ldb, int ldc,
             long sA, long sB, long sC,
             const float* __restrict__ bias, const float* __restrict__ rowmask,
             const float* __restrict__ aux, int auxld, int auxoff)
{
    constexpr int BK  = 32;
    constexpr int AST = 36;                    // A smem row stride
    constexpr int BST = NT ? 36 : 136;         // B smem row stride
    constexpr int ABUF = 128 * 36;
    constexpr int BBUF = 128 * 36;

    extern __shared__ float sm[];
    float* As = sm;                  // [2][ABUF]
    float* Bs = sm + 2 * ABUF;       // [2][BBUF]

    int z = blockIdx.z;
    A += (size_t)z * sA;
    B += (size_t)z * sB;
    C += (size_t)z * sC;

    const int row0 = blockIdx.y * 128;
    const int col0 = blockIdx.x * 128;
    const int tid  = threadIdx.x;
    const int lane = tid & 31;
    const int wid  = tid >> 5;
    const int wr   = wid >> 2;       // 0..1
    const int wc   = wid & 3;        // 0..3
    const int group = lane >> 2;     // 0..7
    const int tig   = lane & 3;      // 0..3

    float acc[4][4][4];
#pragma unroll
    for (int i = 0; i < 4; i++)
#pragma unroll
        for (int j = 0; j < 4; j++)
#pragma unroll
            for (int c = 0; c < 4; c++) acc[i][j][c] = 0.f;

    auto loadA = [&](int buf, int k0) {
        float* dst = As + buf * ABUF;
#pragma unroll
        for (int p = 0; p < 4; p++) {
            int idx = tid + p * 256;
            int r = idx >> 3;
            int c = (idx & 7) * 4;
            uint32_t s = (uint32_t)__cvta_generic_to_shared(dst + r * AST + c);
            const float* g = A + (size_t)(row0 + r) * lda + k0 + c;
            CP16(s, g);
        }
    };
    auto loadB = [&](int buf, int k0) {
        float* dst = Bs + buf * BBUF;
        if (NT) {
#pragma unroll
            for (int p = 0; p < 4; p++) {
                int idx = tid + p * 256;
                int r = idx >> 3;
                int c = (idx & 7) * 4;
                uint32_t s = (uint32_t)__cvta_generic_to_shared(dst + r * BST + c);
                const float* g = B + (size_t)(col0 + r) * ldb + k0 + c;
                CP16(s, g);
            }
        } else {
#pragma unroll
            for (int p = 0; p < 4; p++) {
                int idx = tid + p * 256;
                int r = idx >> 5;
                int c = (idx & 31) * 4;
                uint32_t s = (uint32_t)__cvta_generic_to_shared(dst + r * BST + c);
                const float* g = B + (size_t)(k0 + r) * ldb + col0 + c;
                CP16(s, g);
            }
        }
    };

    const int nt = K / BK;
    loadA(0, 0); loadB(0, 0); CP_COMMIT;

    for (int t = 0; t < nt; t++) {
        if (t + 1 < nt) {
            loadA((t + 1) & 1, (t + 1) * BK);
            loadB((t + 1) & 1, (t + 1) * BK);
            CP_COMMIT;
            CP_WAIT1;
        } else {
            CP_WAIT0;
        }
        __syncthreads();

        const uint32_t* as = (const uint32_t*)(As + (t & 1) * ABUF);
        const uint32_t* bs = (const uint32_t*)(Bs + (t & 1) * BBUF);

#pragma unroll
        for (int kk = 0; kk < BK; kk += 8) {
            uint32_t af[4][4];
#pragma unroll
            for (int mf = 0; mf < 4; mf++) {
                int m = wr * 64 + mf * 16 + group;
                af[mf][0] = as[(m)     * AST + kk + tig];
                af[mf][1] = as[(m + 8) * AST + kk + tig];
                af[mf][2] = as[(m)     * AST + kk + tig + 4];
                af[mf][3] = as[(m + 8) * AST + kk + tig + 4];
            }
            uint32_t bf[4][2];
#pragma unroll
            for (int nf = 0; nf < 4; nf++) {
                int n = wc * 32 + nf * 8 + group;
                if (NT) {
                    bf[nf][0] = bs[n * BST + kk + tig];
                    bf[nf][1] = bs[n * BST + kk + tig + 4];
                } else {
                    bf[nf][0] = bs[(kk + tig)     * BST + n];
                    bf[nf][1] = bs[(kk + tig + 4) * BST + n];
                }
            }
#pragma unroll
            for (int mf = 0; mf < 4; mf++)
#pragma unroll
                for (int nf = 0; nf < 4; nf++)
                    mma_tf32(acc[mf][nf], af[mf], bf[nf]);
        }
        __syncthreads();
    }

    // ---- fused epilogue ----
#pragma unroll
    for (int mf = 0; mf < 4; mf++) {
        int rbase = row0 + wr * 64 + mf * 16 + group;
#pragma unroll
        for (int half = 0; half < 2; half++) {
            int m = rbase + half * 8;
            float rm = 1.f;
            if (EPI == 2 || EPI == 3) rm = rowmask[m];
#pragma unroll
            for (int nf = 0; nf < 4; nf++) {
                int n = col0 + wc * 32 + nf * 8 + 2 * tig;
                float v0 = acc[mf][nf][half * 2 + 0];
                float v1 = acc[mf][nf][half * 2 + 1];
                if (EPI != 0) { v0 += bias[n]; v1 += bias[n + 1]; }
                if (EPI == 2) {
                    v0 = eluf(v0) * rm;
                    v1 = eluf(v1) * rm;
                } else if (EPI == 3) {
                    float2 h = *(const float2*)&aux[(size_t)m * auxld + n];
                    float2 d = *(const float2*)&aux[(size_t)m * auxld + n + auxoff];
                    float g0 = 1.f / (1.f + expf(-v0));
                    float g1 = 1.f / (1.f + expf(-v1));
                    v0 = (g0 * h.x + (1.f - g0) * d.x) * rm;
                    v1 = (g1 * h.y + (1.f - g1) * d.y) * rm;
                } else if (EPI == 4) {
                    v0 = eluf(v0);
                    v1 = eluf(v1);
                } else if (EPI == 5) {
                    float2 ax = *(const float2*)&aux[(size_t)m * auxld + n];
                    v0 = eluf(v0) * ax.x;
                    v1 = eluf(v1) * ax.y;
                }
                float w0 = RND ? roundtf(v0) : v0;
                float w1 = RND ? roundtf(v1) : v1;
                *(float2*)&C[(size_t)m * ldc + n] = make_float2(w0, w1);
                if (C2) {
                    *(float2*)&C2[(size_t)z * sC + (size_t)m * ldc + n] =
                        make_float2(roundtf(v0), roundtf(v1));
                }
            }
        }
    }
}

// round a buffer to tf32 (float4)
__global__ void round_k(const float* __restrict__ src, float* __restrict__ dst)
{
    size_t i = (size_t)blockIdx.x * blockDim.x + threadIdx.x;
    float4 v = ((const float4*)src)[i];
    v.x = roundtf(v.x); v.y = roundtf(v.y);
    v.z = roundtf(v.z); v.w = roundtf(v.w);
    ((float4*)dst)[i] = v;
}

// ---------------------------------------------------------------------------
__device__ __forceinline__ float blockReduce(float v, bool isMax)
{
    __shared__ float sh[32];
    int lane = threadIdx.x & 31;
    int w = threadIdx.x >> 5;
    int nw = blockDim.x >> 5;
#pragma unroll
    for (int o = 16; o; o >>= 1) {
        float u = __shfl_xor_sync(0xffffffffu, v, o);
        v = isMax ? fmaxf(v, u) : v + u;
    }
    if (lane == 0) sh[w] = v;
    __syncthreads();
    if (w == 0) {
        v = (lane < nw) ? sh[lane] : (isMax ? -INFINITY : 0.f);
#pragma unroll
        for (int o = 16; o; o >>= 1) {
            float u = __shfl_xor_sync(0xffffffffu, v, o);
            v = isMax ? fmaxf(v, u) : v + u;
        }
        if (lane == 0) sh[0] = v;
    }
    __syncthreads();
    v = sh[0];
    __syncthreads();
    return v;
}

// Masked causal softmax (in place), writes tf32-rounded scores. 256 thr/row.
__global__ void attn_softmax_k(float* logits, const float* mask)
{
    int row = blockIdx.x;
    int b = row >> 9;
    int i = row & 511;
    const float* mrow = mask + ((size_t)b << 9);
    float* L = logits + ((size_t)row << 9);
    int t = threadIdx.x;
    int j0 = t, j1 = t + 256;
    bool a0 = (i > j0) && (mrow[j0] > 0.f);
    bool a1 = (i > j1) && (mrow[j1] > 0.f);
    float x0 = L[j0] + (a0 ? 0.f : -1e30f);
    float x1 = L[j1] + (a1 ? 0.f : -1e30f);
    float mx = blockReduce(fmaxf(x0, x1), true);
    float e0 = expf(x0 - mx);
    float e1 = expf(x1 - mx);
    float s = blockReduce(e0 + e1, false);
    float inv = 1.f / s;
    L[j0] = a0 ? roundtf(e0 * inv) : 0.f;
    L[j1] = a1 ? roundtf(e1 * inv) : 0.f;
}

// m[row] = dot(prod[row,:], Wm2) + bm2
__global__ void rowdot_k(const float* prod, const float* w, const float* b, float* m)
{
    int row = blockIdx.x;
    const float* p = prod + ((size_t)row << 10);
    float s = 0.f;
    for (int h = threadIdx.x; h < HD; h += 256) s = fmaf(p[h], w[h], s);
    s = blockReduce(s, false);
    if (threadIdx.x == 0) m[row] = s + b[0];
}

// Per-batch masked softmax along sequence. 512 thr/batch.
__global__ void seq_softmax_k(const float* m, const float* mask, float* a)
{
    int b = blockIdx.x;
    int t = threadIdx.x;
    size_t idx = ((size_t)b << 9) + t;
    float msk = mask[idx];
    float x = m[idx] + (msk > 0.f ? 0.f : -1e30f);
    float mx = blockReduce(x, true);
    float e = expf(x - mx);
    float s = blockReduce(e, false);
    a[idx] = (msk > 0.f) ? e / s : 0.f;
}

// out = a[row] * encoding
__global__ void scale_k(const float* a, const float* enc, float* out)
{
    size_t i = (size_t)blockIdx.x * blockDim.x + threadIdx.x;
    float4 e = ((const float4*)enc)[i];
    float s = a[(i * 4) >> 10];
    float4 o;
    o.x = e.x * s; o.y = e.y * s; o.z = e.z * s; o.w = e.w * s;
    ((float4*)out)[i] = o;
}

static const int SMEM_BYTES = 4 * 4608 * 4;   // 73728

extern "C" void kernel_launch(void* const* d_in, const int* in_sizes, int n_in,
                              void* d_out, int out_size)
{
    const float* cas_emb     = (const float*)d_in[0];
    const float* cas_mask    = (const float*)d_in[1];
    const float* time_weight = (const float*)d_in[2];
    const float* W1  = (const float*)d_in[3];
    const float* b1  = (const float*)d_in[4];
    const float* Wh  = (const float*)d_in[5];
    const float* bh  = (const float*)d_in[6];
    const float* Wt  = (const float*)d_in[7];
    const float* bt  = (const float*)d_in[8];
    const float* Wg  = (const float*)d_in[9];
    const float* bg  = (const float*)d_in[10];
    const float* Wm1 = (const float*)d_in[11];
    const float* bm1 = (const float*)d_in[12];
    const float* Wti = (const float*)d_in[13];
    const float* bti = (const float*)d_in[14];
    const float* Wm2 = (const float*)d_in[15];
    const float* bm2 = (const float*)d_in[16];
    float* out = (float*)d_out;

    float *cat, *catr, *head, *tail, *logits, *enc, *encr, *embr, *twr, *wr, *mvec, *avec;
    cudaGetSymbolAddress((void**)&cat,    g_cat);
    cudaGetSymbolAddress((void**)&catr,   g_catr);
    cudaGetSymbolAddress((void**)&head,   g_head);
    cudaGetSymbolAddress((void**)&tail,   g_tail);
    cudaGetSymbolAddress((void**)&logits, g_logits);
    cudaGetSymbolAddress((void**)&enc,    g_enc);
    cudaGetSymbolAddress((void**)&encr,   g_encr);
    cudaGetSymbolAddress((void**)&embr,   g_embr);
    cudaGetSymbolAddress((void**)&twr,    g_twr);
    cudaGetSymbolAddress((void**)&wr,     g_wr);
    cudaGetSymbolAddress((void**)&mvec,   g_m);
    cudaGetSymbolAddress((void**)&avec,   g_a);

    cudaFuncSetAttribute(gemm_tc<0,false,false>, cudaFuncAttributeMaxDynamicSharedMemorySize, SMEM_BYTES);
    cudaFuncSetAttribute(gemm_tc<0,true ,true >, cudaFuncAttributeMaxDynamicSharedMemorySize, SMEM_BYTES);
    cudaFuncSetAttribute(gemm_tc<1,false,true >, cudaFuncAttributeMaxDynamicSharedMemorySize, SMEM_BYTES);
    cudaFuncSetAttribute(gemm_tc<2,false,false>, cudaFuncAttributeMaxDynamicSharedMemorySize, SMEM_BYTES);
    cudaFuncSetAttribute(gemm_tc<3,false,false>, cudaFuncAttributeMaxDynamicSharedMemorySize, SMEM_BYTES);
    cudaFuncSetAttribute(gemm_tc<4,false,false>, cudaFuncAttributeMaxDynamicSharedMemorySize, SMEM_BYTES);
    cudaFuncSetAttribute(gemm_tc<5,false,false>, cudaFuncAttributeMaxDynamicSharedMemorySize, SMEM_BYTES);

    dim3 blk(256);

    // 0) pre-round inputs + weights to tf32
    round_k<<<(ROWS*DE/4)/256, 256>>>(cas_emb, embr);
    round_k<<<(ROWS*DT/4)/256, 256>>>(time_weight, twr);
    round_k<<<(DE*HD/4)/256, 256>>>(W1,  wr + OFF_W1);
    round_k<<<(HD*HD/4)/256, 256>>>(Wh,  wr + OFF_Wh);
    round_k<<<(HD*HD/4)/256, 256>>>(Wt,  wr + OFF_Wt);
    round_k<<<(2*HD*HD/4)/256, 256>>>(Wg, wr + OFF_Wg);
    round_k<<<(HD*HD/4)/256, 256>>>(Wm1, wr + OFF_Wm1);
    round_k<<<(DT*HD/4)/256, 256>>>(Wti, wr + OFF_Wti);

    // 1) cas_hidden = elu(emb @ W1 + b1)*mask -> cat[:, :1024] (full) + catr (rounded)
    gemm_tc<2, false, false><<<dim3(HD/128, ROWS/128, 1), blk, SMEM_BYTES>>>(
        embr, wr + OFF_W1, cat, catr, ROWS, HD, DE, DE, HD, 2048,
        0, 0, 0, b1, cas_mask, nullptr, 0, 0);

    // 2) head = round(cas_hidden @ Wh + bh)
    gemm_tc<1, false, true><<<dim3(HD/128, ROWS/128, 1), blk, SMEM_BYTES>>>(
        catr, wr + OFF_Wh, head, nullptr, ROWS, HD, HD, 2048, HD, HD,
        0, 0, 0, bh, nullptr, nullptr, 0, 0);

    // 3) tail = round(cas_hidden @ Wt + bt)
    gemm_tc<1, false, true><<<dim3(HD/128, ROWS/128, 1), blk, SMEM_BYTES>>>(
        catr, wr + OFF_Wt, tail, nullptr, ROWS, HD, HD, 2048, HD, HD,
        0, 0, 0, bt, nullptr, nullptr, 0, 0);

    // 4) logits[b] = head_b @ tail_b^T
    gemm_tc<0, true, true><<<dim3(SL/128, SL/128, BSZ), blk, SMEM_BYTES>>>(
        head, tail, logits, nullptr, SL, SL, HD, HD, HD, SL,
        (long)SL * HD, (long)SL * HD, (long)SL * SL,
        nullptr, nullptr, nullptr, 0, 0);

    // 5) masked causal softmax (in place, rounded)
    attn_softmax_k<<<ROWS, 256>>>(logits, cas_mask);

    // 6) depend[b] = score_b @ cas_hidden_b -> cat[:,1024:] (full) + catr (rounded)
    gemm_tc<0, false, false><<<dim3(HD/128, SL/128, BSZ), blk, SMEM_BYTES>>>(
        logits, catr, cat + 1024, catr + 1024, SL, HD, SL, SL, 2048, 2048,
        (long)SL * SL, (long)SL * 2048, (long)SL * 2048,
        nullptr, nullptr, nullptr, 0, 0);

    // 7) enc = (g*h + (1-g)*d)*mask -> enc (full) + encr (rounded)
    gemm_tc<3, false, false><<<dim3(HD/128, ROWS/128, 1), blk, SMEM_BYTES>>>(
        catr, wr + OFF_Wg, enc, encr, ROWS, HD, 2048, 2048, HD, HD,
        0, 0, 0, bg, cas_mask, cat, 2048, 1024);

    // 8) time_inf = elu(tw @ Wti + bti) -> tail (full; elementwise consumer only)
    gemm_tc<4, false, false><<<dim3(HD/128, ROWS/128, 1), blk, SMEM_BYTES>>>(
        twr, wr + OFF_Wti, tail, nullptr, ROWS, HD, DT, DT, HD, HD,
        0, 0, 0, bti, nullptr, nullptr, 0, 0);

    // 9) prod = elu(enc @ Wm1 + bm1) * time_inf -> head (full)
    gemm_tc<5, false, false><<<dim3(HD/128, ROWS/128, 1), blk, SMEM_BYTES>>>(
        encr, wr + OFF_Wm1, head, nullptr, ROWS, HD, HD, HD, HD, HD,
        0, 0, 0, bm1, nullptr, tail, HD, 0);

    // 10) m = prod @ Wm2 + bm2
    rowdot_k<<<ROWS, 256>>>(head, Wm2, bm2, mvec);

    // 11) a = masked softmax over sequence
    seq_softmax_k<<<BSZ, 512>>>(mvec, cas_mask, avec);

    // 12) out = a * encoding
    scale_k<<<(ROWS * HD / 4) / 256, 256>>>(avec, enc, out);
}

// round 7
// speedup vs baseline: 5.6768x; 2.4379x over previous
#include <cuda_runtime.h>
#include <cuda_fp16.h>
#include <math.h>
#include <stdint.h>

// Problem constants
#define BSZ 32
#define SL  512
#define HD  1024
#define DE  1024
#define DT  64
#define ROWS (BSZ*SL)          // 16384

// ---------------- scratch (__device__ globals, alloc-free) ----------------
__device__ float  g_cat[(size_t)ROWS * 2048];     // f32: [:, :1024]=cas_hidden, [:,1024:]=depend
__device__ __half g_cath[(size_t)ROWS * 2048];    // half copy (GEMM operand)
__device__ __half g_catT[(size_t)BSZ * HD * SL];  // per-batch transposed hidden [h][j] half
__device__ float  g_head[(size_t)ROWS * HD];      // f32: prod (stage 9 output)
__device__ float  g_tail[(size_t)ROWS * HD];      // f32: time_inf
__device__ __half g_headh[(size_t)ROWS * HD];     // half head
__device__ __half g_tailh[(size_t)ROWS * HD];     // half tail
__device__ float  g_logits[(size_t)BSZ * SL * SL];
__device__ __half g_scoreh[(size_t)BSZ * SL * SL];
__device__ float  g_enc[(size_t)ROWS * HD];
__device__ __half g_ench[(size_t)ROWS * HD];
__device__ __half g_embh[(size_t)ROWS * DE];
__device__ __half g_twh[(size_t)ROWS * DT];
__device__ __half g_wth[6356992];                 // transposed half weights, packed
__device__ float  g_m[ROWS];
__device__ float  g_a[ROWS];

#define OFF_W1  0
#define OFF_Wh  1048576
#define OFF_Wt  2097152
#define OFF_Wg  3145728
#define OFF_Wm1 5242880
#define OFF_Wti 6291456

__device__ __forceinline__ float eluf(float x) { return x > 0.f ? x : expm1f(x); }

__device__ __forceinline__ void mma_f16(float c[4], const uint32_t a[4], const uint32_t b[2]) {
    asm volatile(
        "mma.sync.aligned.m16n8k16.row.col.f32.f16.f16.f32 "
        "{%0,%1,%2,%3},{%4,%5,%6,%7},{%8,%9},{%0,%1,%2,%3};"
        : "+f"(c[0]), "+f"(c[1]), "+f"(c[2]), "+f"(c[3])
        : "r"(a[0]), "r"(a[1]), "r"(a[2]), "r"(a[3]), "r"(b[0]), "r"(b[1]));
}
#define LDSM4(r0, r1, r2, r3, addr) \
    asm volatile("ldmatrix.sync.aligned.m8n8.x4.shared.b16 {%0,%1,%2,%3}, [%4];" \
                 : "=r"(r0), "=r"(r1), "=r"(r2), "=r"(r3) : "r"(addr))
#define CP16(dst, src) \
    asm volatile("cp.async.cg.shared.global [%0], [%1], 16;" :: "r"(dst), "l"(src))
#define CP_COMMIT asm volatile("cp.async.commit_group;")
#define CP_WAIT1  asm volatile("cp.async.wait_group 1;" ::: "memory")
#define CP_WAIT0  asm volatile("cp.async.wait_group 0;" ::: "memory")

// ---------------------------------------------------------------------------
// fp16 tensor-core GEMM: C[M,N] = epi(A[M,K] @ B[N,K]^T + bias)
// A half [M,K] K-major, B half [N,K] K-major (= NT). fp32 accumulate.
// CTA tile 128x128, BK=64, 2-stage cp.async, 8 warps (2x4), warp 64x32.
// SMEM rows padded to 144B -> conflict-free cp.async + ldmatrix.
// EPI: 0=none, 1=bias, 2=elu*rowmask, 3=sigmoid-gate-blend, 4=elu, 5=elu*aux
// C (f32, optional), C2 (half, optional) share ldc/sC indexing.
// ---------------------------------------------------------------------------
template<int EPI>
__global__ __launch_bounds__(256)
void gemm_h(const __half* __restrict__ A, const __half* __restrict__ B,
            float* __restrict__ C, __half* __restrict__ C2,
            int K, int lda, int ldb, int ldc,
            long sA, long sB, long sC,
            const float* __restrict__ bias, const float* __restrict__ rowmask,
            const float* __restrict__ aux, int auxld, int auxoff)
{
    constexpr int STAGE_B = 2 * 128 * 144;      // A+B tile bytes per stage = 36864
    extern __shared__ char smem[];
    uint32_t sb;
    asm("{ .reg .u64 t; cvta.to.shared.u64 t, %1; cvt.u32.u64 %0, t; }" : "=r"(sb) : "l"(smem));

    const int z = blockIdx.z;
    A += (size_t)z * sA;
    B += (size_t)z * sB;

    const int row0 = blockIdx.y * 128;
    const int col0 = blockIdx.x * 128;
    const int tid = threadIdx.x, lane = tid & 31, wid = tid >> 5;
    const int wr = wid >> 2, wc = wid & 3;        // 2x4 warp grid
    const int group = lane >> 2, tig = lane & 3;

    float acc[4][4][4];
#pragma unroll
    for (int i = 0; i < 4; i++)
#pragma unroll
        for (int j = 0; j < 4; j++)
#pragma unroll
            for (int c = 0; c < 4; c++) acc[i][j][c] = 0.f;

    auto load = [&](int s, int k0) {
        const uint32_t ab = sb + s * STAGE_B;
        const uint32_t bb = ab + 128 * 144;
#pragma unroll
        for (int p = 0; p < 4; p++) {
            int idx = tid + (p << 8);
            int r = idx >> 3;               // 0..127
            int c8 = (idx & 7) << 3;        // half offset 0..56
            uint32_t d = r * 144 + (c8 << 1);
            CP16(ab + d, A + (size_t)(row0 + r) * lda + k0 + c8);
            CP16(bb + d, B + (size_t)(col0 + r) * ldb + k0 + c8);
        }
    };

    const int nt = K >> 6;                  // BK = 64
    load(0, 0); CP_COMMIT;

    for (int t = 0; t < nt; t++) {
        if (t + 1 < nt) { load((t + 1) & 1, (t + 1) << 6); CP_COMMIT; CP_WAIT1; }
        else            { CP_WAIT0; }
        __syncthreads();

        const uint32_t ab = sb + (t & 1) * STAGE_B;
        const uint32_t bb = ab + 128 * 144;
        const uint32_t koff = ((lane >> 4) << 4);      // 0 or 16 bytes (k+8)
        const int rsel = lane & 15;

#pragma unroll
        for (int kk4 = 0; kk4 < 4; kk4++) {            // kk = 16*kk4
            const uint32_t kb = (kk4 << 5) + koff;     // byte offset in row
            uint32_t af[4][4];
#pragma unroll
            for (int mf = 0; mf < 4; mf++) {
                uint32_t addr = ab + (uint32_t)(wr * 64 + mf * 16 + rsel) * 144 + kb;
                LDSM4(af[mf][0], af[mf][1], af[mf][2], af[mf][3], addr);
            }
            uint32_t bf[4][2];
#pragma unroll
            for (int g = 0; g < 2; g++) {
                uint32_t r0, r1, r2, r3;
                uint32_t addr = bb + (uint32_t)(wc * 32 + g * 16 + rsel) * 144 + kb;
                LDSM4(r0, r1, r2, r3, addr);
                bf[2 * g][0] = r0; bf[2 * g][1] = r2;
                bf[2 * g + 1][0] = r1; bf[2 * g + 1][1] = r3;
            }
#pragma unroll
            for (int mf = 0; mf < 4; mf++)
#pragma unroll
                for (int nf = 0; nf < 4; nf++)
                    mma_f16(acc[mf][nf], af[mf], bf[nf]);
        }
        __syncthreads();
    }

    // ---- fused epilogue ----
#pragma unroll
    for (int mf = 0; mf < 4; mf++) {
        int rbase = row0 + wr * 64 + mf * 16 + group;
#pragma unroll
        for (int half = 0; half < 2; half++) {
            int m = rbase + half * 8;
            float rm = 1.f;
            if (EPI == 2 || EPI == 3) rm = rowmask[m];
#pragma unroll
            for (int nf = 0; nf < 4; nf++) {
                int n = col0 + wc * 32 + nf * 8 + 2 * tig;
                float v0 = acc[mf][nf][half * 2 + 0];
                float v1 = acc[mf][nf][half * 2 + 1];
                if (EPI != 0) { v0 += bias[n]; v1 += bias[n + 1]; }
                if (EPI == 2) {
                    v0 = eluf(v0) * rm;
                    v1 = eluf(v1) * rm;
                } else if (EPI == 3) {
                    float2 h = *(const float2*)&aux[(size_t)m * auxld + n];
                    float2 d = *(const float2*)&aux[(size_t)m * auxld + n + auxoff];
                    float g0 = 1.f / (1.f + expf(-v0));
                    float g1 = 1.f / (1.f + expf(-v1));
                    v0 = (g0 * h.x + (1.f - g0) * d.x) * rm;
                    v1 = (g1 * h.y + (1.f - g1) * d.y) * rm;
                } else if (EPI == 4) {
                    v0 = eluf(v0);
                    v1 = eluf(v1);
                } else if (EPI == 5) {
                    float2 ax = *(const float2*)&aux[(size_t)m * auxld + n];
                    v0 = eluf(v0) * ax.x;
                    v1 = eluf(v1) * ax.y;
                }
                size_t off = (size_t)z * sC + (size_t)m * ldc + n;
                if (C)  *(float2*)&C[off] = make_float2(v0, v1);
                if (C2) *(__half2*)&C2[off] = __floats2half2_rn(v0, v1);
            }
        }
    }
}

// ---------------------------------------------------------------------------
// f32 -> f16 convert (4 elems/thread)
__global__ void tohalf_k(const float* __restrict__ src, __half* __restrict__ dst)
{
    size_t i = (size_t)blockIdx.x * blockDim.x + threadIdx.x;
    float4 v = ((const float4*)src)[i];
    ((__half2*)dst)[2 * i]     = __floats2half2_rn(v.x, v.y);
    ((__half2*)dst)[2 * i + 1] = __floats2half2_rn(v.z, v.w);
}

// transpose f32 [R,C] (row stride sld) -> half [C,R] (row stride dld), batched
__global__ void transpose_h_k(const float* __restrict__ src, __half* __restrict__ dst,
                              int sld, int dld, long zs, long zd)
{
    __shared__ float t[32][33];
    const float* S = src + (size_t)blockIdx.z * zs;
    __half* D = dst + (size_t)blockIdx.z * zd;
    int c0 = blockIdx.x * 32;
    int r0 = blockIdx.y * 32;
    int x = threadIdx.x, y = threadIdx.y;
#pragma unroll
    for (int i = 0; i < 4; i++)
        t[y + 8 * i][x] = S[(size_t)(r0 + y + 8 * i) * sld + c0 + x];
    __syncthreads();
#pragma unroll
    for (int i = 0; i < 4; i++)
        D[(size_t)(c0 + y + 8 * i) * dld + r0 + x] = __float2half_rn(t[x][y + 8 * i]);
}

// ---------------------------------------------------------------------------
__device__ __forceinline__ float blockReduce(float v, bool isMax)
{
    __shared__ float sh[32];
    int lane = threadIdx.x & 31;
    int w = threadIdx.x >> 5;
    int nw = blockDim.x >> 5;
#pragma unroll
    for (int o = 16; o; o >>= 1) {
        float u = __shfl_xor_sync(0xffffffffu, v, o);
        v = isMax ? fmaxf(v, u) : v + u;
    }
    if (lane == 0) sh[w] = v;
    __syncthreads();
    if (w == 0) {
        v = (lane < nw) ? sh[lane] : (isMax ? -INFINITY : 0.f);
#pragma unroll
        for (int o = 16; o; o >>= 1) {
            float u = __shfl_xor_sync(0xffffffffu, v, o);
            v = isMax ? fmaxf(v, u) : v + u;
        }
        if (lane == 0) sh[0] = v;
    }
    __syncthreads();
    v = sh[0];
    __syncthreads();
    return v;
}

// Masked causal softmax: reads f32 logits, writes half scores. 256 thr/row.
__global__ void attn_softmax_k(const float* __restrict__ logits,
                               const float* __restrict__ mask,
                               __half* __restrict__ score)
{
    int row = blockIdx.x;
    int b = row >> 9;
    int i = row & 511;
    const float* mrow = mask + ((size_t)b << 9);
    const float* L = logits + ((size_t)row << 9);
    __half* S = score + ((size_t)row << 9);
    int t = threadIdx.x;
    int j0 = t, j1 = t + 256;
    bool a0 = (i > j0) && (mrow[j0] > 0.f);
    bool a1 = (i > j1) && (mrow[j1] > 0.f);
    float x0 = L[j0] + (a0 ? 0.f : -1e30f);
    float x1 = L[j1] + (a1 ? 0.f : -1e30f);
    float mx = blockReduce(fmaxf(x0, x1), true);
    float e0 = expf(x0 - mx);
    float e1 = expf(x1 - mx);
    float s = blockReduce(e0 + e1, false);
    float inv = 1.f / s;
    S[j0] = __float2half_rn(a0 ? e0 * inv : 0.f);
    S[j1] = __float2half_rn(a1 ? e1 * inv : 0.f);
}

// m[row] = dot(prod[row,:], Wm2) + bm2
__global__ void rowdot_k(const float* prod, const float* w, const float* b, float* m)
{
    int row = blockIdx.x;
    const float* p = prod + ((size_t)row << 10);
    float s = 0.f;
    for (int h = threadIdx.x; h < HD; h += 256) s = fmaf(p[h], w[h], s);
    s = blockReduce(s, false);
    if (threadIdx.x == 0) m[row] = s + b[0];
}

// Per-batch masked softmax along sequence. 512 thr/batch.
__global__ void seq_softmax_k(const float* m, const float* mask, float* a)
{
    int b = blockIdx.x;
    int t = threadIdx.x;
    size_t idx = ((size_t)b << 9) + t;
    float msk = mask[idx];
    float x = m[idx] + (msk > 0.f ? 0.f : -1e30f);
    float mx = blockReduce(x, true);
    float e = expf(x - mx);
    float s = blockReduce(e, false);
    a[idx] = (msk > 0.f) ? e / s : 0.f;
}

// out = a[row] * encoding
__global__ void scale_k(const float* a, const float* enc, float* out)
{
    size_t i = (size_t)blockIdx.x * blockDim.x + threadIdx.x;
    float4 e = ((const float4*)enc)[i];
    float s = a[(i * 4) >> 10];
    float4 o;
    o.x = e.x * s; o.y = e.y * s; o.z = e.z * s; o.w = e.w * s;
    ((float4*)out)[i] = o;
}

static const int SMEM_H = 2 * 2 * 128 * 144;   // 73728

extern "C" void kernel_launch(void* const* d_in, const int* in_sizes, int n_in,
                              void* d_out, int out_size)
{
    const float* cas_emb     = (const float*)d_in[0];
    const float* cas_mask    = (const float*)d_in[1];
    const float* time_weight = (const float*)d_in[2];
    const float* W1  = (const float*)d_in[3];
    const float* b1  = (const float*)d_in[4];
    const float* Wh  = (const float*)d_in[5];
    const float* bh  = (const float*)d_in[6];
    const float* Wt  = (const float*)d_in[7];
    const float* bt  = (const float*)d_in[8];
    const float* Wg  = (const float*)d_in[9];
    const float* bg  = (const float*)d_in[10];
    const float* Wm1 = (const float*)d_in[11];
    const float* bm1 = (const float*)d_in[12];
    const float* Wti = (const float*)d_in[13];
    const float* bti = (const float*)d_in[14];
    const float* Wm2 = (const float*)d_in[15];
    const float* bm2 = (const float*)d_in[16];
    float* out = (float*)d_out;

    float  *cat, *head, *tail, *logits, *enc, *mvec, *avec;
    __half *cath, *catT, *headh, *tailh, *scoreh, *ench, *embh, *twh, *wth;
    cudaGetSymbolAddress((void**)&cat,    g_cat);
    cudaGetSymbolAddress((void**)&cath,   g_cath);
    cudaGetSymbolAddress((void**)&catT,   g_catT);
    cudaGetSymbolAddress((void**)&head,   g_head);
    cudaGetSymbolAddress((void**)&tail,   g_tail);
    cudaGetSymbolAddress((void**)&headh,  g_headh);
    cudaGetSymbolAddress((void**)&tailh,  g_tailh);
    cudaGetSymbolAddress((void**)&logits, g_logits);
    cudaGetSymbolAddress((void**)&scoreh, g_scoreh);
    cudaGetSymbolAddress((void**)&enc,    g_enc);
    cudaGetSymbolAddress((void**)&ench,   g_ench);
    cudaGetSymbolAddress((void**)&embh,   g_embh);
    cudaGetSymbolAddress((void**)&twh,    g_twh);
    cudaGetSymbolAddress((void**)&wth,    g_wth);
    cudaGetSymbolAddress((void**)&mvec,   g_m);
    cudaGetSymbolAddress((void**)&avec,   g_a);

    cudaFuncSetAttribute(gemm_h<0>, cudaFuncAttributeMaxDynamicSharedMemorySize, SMEM_H);
    cudaFuncSetAttribute(gemm_h<1>, cudaFuncAttributeMaxDynamicSharedMemorySize, SMEM_H);
    cudaFuncSetAttribute(gemm_h<2>, cudaFuncAttributeMaxDynamicSharedMemorySize, SMEM_H);
    cudaFuncSetAttribute(gemm_h<3>, cudaFuncAttributeMaxDynamicSharedMemorySize, SMEM_H);
    cudaFuncSetAttribute(gemm_h<4>, cudaFuncAttributeMaxDynamicSharedMemorySize, SMEM_H);
    cudaFuncSetAttribute(gemm_h<5>, cudaFuncAttributeMaxDynamicSharedMemorySize, SMEM_H);

    dim3 blk(256);
    dim3 tb(32, 8);

    // conversions needed before GEMM1 (5 launches, so ncu -s 5 lands on GEMM1)
    tohalf_k<<<(ROWS*DE/4)/256, 256>>>(cas_emb, embh);
    tohalf_k<<<(ROWS*DT/4)/256, 256>>>(time_weight, twh);
    transpose_h_k<<<dim3(32,32,1), tb>>>(W1, wth + OFF_W1, 1024, 1024, 0, 0);
    transpose_h_k<<<dim3(32,32,1), tb>>>(Wh, wth + OFF_Wh, 1024, 1024, 0, 0);
    transpose_h_k<<<dim3(32,32,1), tb>>>(Wt, wth + OFF_Wt, 1024, 1024, 0, 0);

    // 1) cas_hidden = elu(emb @ W1 + b1)*mask -> cat f32 + cath half
    gemm_h<2><<<dim3(8,128,1), blk, SMEM_H>>>(
        embh, wth + OFF_W1, cat, cath, DE, DE, DE, 2048,
        0, 0, 0, b1, cas_mask, nullptr, 0, 0);

    // remaining weight transposes
    transpose_h_k<<<dim3(32,64,1), tb>>>(Wg,  wth + OFF_Wg,  1024, 2048, 0, 0);
    transpose_h_k<<<dim3(32,32,1), tb>>>(Wm1, wth + OFF_Wm1, 1024, 1024, 0, 0);
    transpose_h_k<<<dim3(32,2,1),  tb>>>(Wti, wth + OFF_Wti, 1024, 64,   0, 0);

    // 1.5) catT[b] = transpose(cas_hidden[b]) (half) for GEMM6's B operand
    transpose_h_k<<<dim3(32,16,32), tb>>>(
        cat, catT, 2048, 512, (long)SL * 2048, (long)HD * SL);

    // 2) head (half only)
    gemm_h<1><<<dim3(8,128,1), blk, SMEM_H>>>(
        cath, wth + OFF_Wh, nullptr, headh, HD, 2048, HD, HD,
        0, 0, 0, bh, nullptr, nullptr, 0, 0);

    // 3) tail (half only)
    gemm_h<1><<<dim3(8,128,1), blk, SMEM_H>>>(
        cath, wth + OFF_Wt, nullptr, tailh, HD, 2048, HD, HD,
        0, 0, 0, bt, nullptr, nullptr, 0, 0);

    // 4) logits[b] = head_b @ tail_b^T (f32 out)
    gemm_h<0><<<dim3(4,4,BSZ), blk, SMEM_H>>>(
        headh, tailh, logits, nullptr, HD, HD, HD, SL,
        (long)SL * HD, (long)SL * HD, (long)SL * SL,
        nullptr, nullptr, nullptr, 0, 0);

    // 5) masked causal softmax -> half scores
    attn_softmax_k<<<ROWS, 256>>>(logits, cas_mask, scoreh);

    // 6) depend[b] = score_b @ hidden_b -> cat[:,1024:] f32 + cath[:,1024:] half
    gemm_h<0><<<dim3(8,4,BSZ), blk, SMEM_H>>>(
        scoreh, catT, cat + 1024, cath + 1024, SL, SL, SL, 2048,
        (long)SL * SL, (long)HD * SL, (long)SL * 2048,
        nullptr, nullptr, nullptr, 0, 0);

    // 7) enc = (g*h + (1-g)*d)*mask -> enc f32 + ench half
    gemm_h<3><<<dim3(8,128,1), blk, SMEM_H>>>(
        cath, wth + OFF_Wg, enc, ench, 2048, 2048, 2048, HD,
        0, 0, 0, bg, cas_mask, cat, 2048, 1024);

    // 8) time_inf = elu(tw @ Wti + bti) -> tail f32 (elementwise use only)
    gemm_h<4><<<dim3(8,128,1), blk, SMEM_H>>>(
        twh, wth + OFF_Wti, tail, nullptr, DT, DT, DT, HD,
        0, 0, 0, bti, nullptr, nullptr, 0, 0);

    // 9) prod = elu(enc @ Wm1 + bm1) * time_inf -> head f32
    gemm_h<5><<<dim3(8,128,1), blk, SMEM_H>>>(
        ench, wth + OFF_Wm1, head, nullptr, HD, HD, HD, HD,
        0, 0, 0, bm1, nullptr, tail, HD, 0);

    // 10) m = prod @ Wm2 + bm2
    rowdot_k<<<ROWS, 256>>>(head, Wm2, bm2, mvec);

    // 11) a = masked softmax over sequence
    seq_softmax_k<<<BSZ, 512>>>(mvec, cas_mask, avec);

    // 12) out = a * encoding
    scale_k<<<(ROWS * HD / 4) / 256, 256>>>(avec, enc, out);
}

// round 9
// speedup vs baseline: 6.7506x; 1.1892x over previous
#include <cuda_runtime.h>
#include <cuda_fp16.h>
#include <math.h>
#include <stdint.h>

// Problem constants
#define BSZ 32
#define SL  512
#define HD  1024
#define DE  1024
#define DT  64
#define ROWS (BSZ*SL)          // 16384

// ---------------- scratch (__device__ globals, alloc-free) ----------------
__device__ float  g_cat[(size_t)ROWS * 2048];     // f32: [:, :1024]=cas_hidden, [:,1024:]=depend
__device__ __half g_cath[(size_t)ROWS * 2048];    // half copy (GEMM operand)
__device__ __half g_catT[(size_t)BSZ * HD * SL];  // per-batch transposed hidden [h][j] half
__device__ float  g_head[(size_t)ROWS * HD];      // f32: prod (stage 9 output)
__device__ float  g_tail[(size_t)ROWS * HD];      // f32: time_inf
__device__ __half g_headh[(size_t)ROWS * HD];     // half head
__device__ __half g_tailh[(size_t)ROWS * HD];     // half tail
__device__ float  g_logits[(size_t)BSZ * SL * SL];
__device__ __half g_scoreh[(size_t)BSZ * SL * SL];
__device__ float  g_enc[(size_t)ROWS * HD];
__device__ __half g_ench[(size_t)ROWS * HD];
__device__ __half g_embh[(size_t)ROWS * DE];
__device__ __half g_twh[(size_t)ROWS * DT];
__device__ __half g_wth[6356992];                 // transposed half weights, packed
__device__ float  g_m[ROWS];
__device__ float  g_a[ROWS];

#define OFF_W1  0
#define OFF_Wh  1048576
#define OFF_Wt  2097152
#define OFF_Wg  3145728
#define OFF_Wm1 5242880
#define OFF_Wti 6291456

__device__ __forceinline__ float eluf(float x) { return x > 0.f ? x : expm1f(x); }

__device__ __forceinline__ void mma_f16(float c[4], const uint32_t a[4], const uint32_t b[2]) {
    asm volatile(
        "mma.sync.aligned.m16n8k16.row.col.f32.f16.f16.f32 "
        "{%0,%1,%2,%3},{%4,%5,%6,%7},{%8,%9},{%0,%1,%2,%3};"
        : "+f"(c[0]), "+f"(c[1]), "+f"(c[2]), "+f"(c[3])
        : "r"(a[0]), "r"(a[1]), "r"(a[2]), "r"(a[3]), "r"(b[0]), "r"(b[1]));
}
#define LDSM4(r0, r1, r2, r3, addr) \
    asm volatile("ldmatrix.sync.aligned.m8n8.x4.shared.b16 {%0,%1,%2,%3}, [%4];" \
                 : "=r"(r0), "=r"(r1), "=r"(r2), "=r"(r3) : "r"(addr))
#define CP16(dst, src) \
    asm volatile("cp.async.cg.shared.global [%0], [%1], 16;" :: "r"(dst), "l"(src))
#define CP_COMMIT asm volatile("cp.async.commit_group;")
#define CP_WAIT1  asm volatile("cp.async.wait_group 1;" ::: "memory")
#define CP_WAIT0  asm volatile("cp.async.wait_group 0;" ::: "memory")

// ---------------------------------------------------------------------------
// fp16 tensor-core GEMM: C[M,N] = epi(A[M,K] @ B[N,K]^T + bias)
// CTA tile 128x128, BK=64, 2-stage cp.async, 8 warps (2x4), ldmatrix.x4.
// EPI: 0=none, 1=bias, 2=elu*rowmask, 3=sigmoid-gate-blend, 4=elu, 5=elu*aux
// CM bitmask: 1=row-tile mask gate, 2=col-tile mask gate (batched),
//             4=causal tile skip (x>y), 8=causal K truncation (K<=row0+128)
// gmask indexed as gmask[z*mstride + tile0] (prefix mask -> first row decides).
// ---------------------------------------------------------------------------
template<int EPI, int CM>
__global__ __launch_bounds__(256)
void gemm_h(const __half* __restrict__ A, const __half* __restrict__ B,
            float* __restrict__ C, __half* __restrict__ C2,
            int K, int lda, int ldb, int ldc,
            long sA, long sB, long sC,
            const float* __restrict__ bias, const float* __restrict__ rowmask,
            const float* __restrict__ aux, int auxld, int auxoff,
            const float* __restrict__ gmask, int mstride)
{
    const int z = blockIdx.z;
    const int row0 = blockIdx.y * 128;
    const int col0 = blockIdx.x * 128;

    if (CM & 4) { if (blockIdx.x > blockIdx.y) return; }
    if (CM & 1) { if (gmask[(size_t)z * mstride + row0] == 0.f) return; }
    if (CM & 2) { if (gmask[(size_t)z * mstride + col0] == 0.f) return; }

    constexpr int STAGE_B = 2 * 128 * 144;      // A+B tile bytes per stage
    extern __shared__ char smem[];
    uint32_t sb;
    asm("{ .reg .u64 t; cvta.to.shared.u64 t, %1; cvt.u32.u64 %0, t; }" : "=r"(sb) : "l"(smem));

    A += (size_t)z * sA;
    B += (size_t)z * sB;

    const int tid = threadIdx.x, lane = tid & 31, wid = tid >> 5;
    const int wr = wid >> 2, wc = wid & 3;
    const int group = lane >> 2, tig = lane & 3;

    float acc[4][4][4];
#pragma unroll
    for (int i = 0; i < 4; i++)
#pragma unroll
        for (int j = 0; j < 4; j++)
#pragma unroll
            for (int c = 0; c < 4; c++) acc[i][j][c] = 0.f;

    auto load = [&](int s, int k0) {
        const uint32_t ab = sb + s * STAGE_B;
        const uint32_t bb = ab + 128 * 144;
#pragma unroll
        for (int p = 0; p < 4; p++) {
            int idx = tid + (p << 8);
            int r = idx >> 3;
            int c8 = (idx & 7) << 3;
            uint32_t d = r * 144 + (c8 << 1);
            CP16(ab + d, A + (size_t)(row0 + r) * lda + k0 + c8);
            CP16(bb + d, B + (size_t)(col0 + r) * ldb + k0 + c8);
        }
    };

    const int Keff = (CM & 8) ? ((row0 + 128 < K) ? row0 + 128 : K) : K;
    const int nt = Keff >> 6;
    load(0, 0); CP_COMMIT;

    for (int t = 0; t < nt; t++) {
        if (t + 1 < nt) { load((t + 1) & 1, (t + 1) << 6); CP_COMMIT; CP_WAIT1; }
        else            { CP_WAIT0; }
        __syncthreads();

        const uint32_t ab = sb + (t & 1) * STAGE_B;
        const uint32_t bb = ab + 128 * 144;
        const uint32_t koff = ((lane >> 4) << 4);
        const int rsel = lane & 15;

#pragma unroll
        for (int kk4 = 0; kk4 < 4; kk4++) {
            const uint32_t kb = (kk4 << 5) + koff;
            uint32_t af[4][4];
#pragma unroll
            for (int mf = 0; mf < 4; mf++) {
                uint32_t addr = ab + (uint32_t)(wr * 64 + mf * 16 + rsel) * 144 + kb;
                LDSM4(af[mf][0], af[mf][1], af[mf][2], af[mf][3], addr);
            }
            uint32_t bf[4][2];
#pragma unroll
            for (int g = 0; g < 2; g++) {
                uint32_t r0, r1, r2, r3;
                uint32_t addr = bb + (uint32_t)(wc * 32 + g * 16 + rsel) * 144 + kb;
                LDSM4(r0, r1, r2, r3, addr);
                bf[2 * g][0] = r0; bf[2 * g][1] = r2;
                bf[2 * g + 1][0] = r1; bf[2 * g + 1][1] = r3;
            }
#pragma unroll
            for (int mf = 0; mf < 4; mf++)
#pragma unroll
                for (int nf = 0; nf < 4; nf++)
                    mma_f16(acc[mf][nf], af[mf], bf[nf]);
        }
        __syncthreads();
    }

    // ---- fused epilogue ----
#pragma unroll
    for (int mf = 0; mf < 4; mf++) {
        int rbase = row0 + wr * 64 + mf * 16 + group;
#pragma unroll
        for (int half = 0; half < 2; half++) {
            int m = rbase + half * 8;
            float rm = 1.f;
            if (EPI == 2 || EPI == 3) rm = rowmask[m];
#pragma unroll
            for (int nf = 0; nf < 4; nf++) {
                int n = col0 + wc * 32 + nf * 8 + 2 * tig;
                float v0 = acc[mf][nf][half * 2 + 0];
                float v1 = acc[mf][nf][half * 2 + 1];
                if (EPI != 0) { v0 += bias[n]; v1 += bias[n + 1]; }
                if (EPI == 2) {
                    v0 = eluf(v0) * rm;
                    v1 = eluf(v1) * rm;
                } else if (EPI == 3) {
                    float2 h = *(const float2*)&aux[(size_t)m * auxld + n];
                    float2 d = *(const float2*)&aux[(size_t)m * auxld + n + auxoff];
                    float g0 = 1.f / (1.f + expf(-v0));
                    float g1 = 1.f / (1.f + expf(-v1));
                    v0 = (g0 * h.x + (1.f - g0) * d.x) * rm;
                    v1 = (g1 * h.y + (1.f - g1) * d.y) * rm;
                } else if (EPI == 4) {
                    v0 = eluf(v0);
                    v1 = eluf(v1);
                } else if (EPI == 5) {
                    float2 ax = *(const float2*)&aux[(size_t)m * auxld + n];
                    v0 = eluf(v0) * ax.x;
                    v1 = eluf(v1) * ax.y;
                }
                size_t off = (size_t)z * sC + (size_t)m * ldc + n;
                if (C)  *(float2*)&C[off] = make_float2(v0, v1);
                if (C2) *(__half2*)&C2[off] = __floats2half2_rn(v0, v1);
            }
        }
    }
}

// ---------------------------------------------------------------------------
// f32 -> f16 convert (4 elems/thread)
__global__ void tohalf_k(const float* __restrict__ src, __half* __restrict__ dst)
{
    size_t i = (size_t)blockIdx.x * blockDim.x + threadIdx.x;
    float4 v = ((const float4*)src)[i];
    ((__half2*)dst)[2 * i]     = __floats2half2_rn(v.x, v.y);
    ((__half2*)dst)[2 * i + 1] = __floats2half2_rn(v.z, v.w);
}

// transpose f32 [R,C] (row stride sld) -> half [C,R] (row stride dld), batched
__global__ void transpose_h_k(const float* __restrict__ src, __half* __restrict__ dst,
                              int sld, int dld, long zs, long zd)
{
    __shared__ float t[32][33];
    const float* S = src + (size_t)blockIdx.z * zs;
    __half* D = dst + (size_t)blockIdx.z * zd;
    int c0 = blockIdx.x * 32;
    int r0 = blockIdx.y * 32;
    int x = threadIdx.x, y = threadIdx.y;
#pragma unroll
    for (int i = 0; i < 4; i++)
        t[y + 8 * i][x] = S[(size_t)(r0 + y + 8 * i) * sld + c0 + x];
    __syncthreads();
#pragma unroll
    for (int i = 0; i < 4; i++)
        D[(size_t)(c0 + y + 8 * i) * dld + r0 + x] = __float2half_rn(t[x][y + 8 * i]);
}

// ---------------------------------------------------------------------------
__device__ __forceinline__ float blockReduce(float v, bool isMax)
{
    __shared__ float sh[32];
    int lane = threadIdx.x & 31;
    int w = threadIdx.x >> 5;
    int nw = blockDim.x >> 5;
#pragma unroll
    for (int o = 16; o; o >>= 1) {
        float u = __shfl_xor_sync(0xffffffffu, v, o);
        v = isMax ? fmaxf(v, u) : v + u;
    }
    if (lane == 0) sh[w] = v;
    __syncthreads();
    if (w == 0) {
        v = (lane < nw) ? sh[lane] : (isMax ? -INFINITY : 0.f);
#pragma unroll
        for (int o = 16; o; o >>= 1) {
            float u = __shfl_xor_sync(0xffffffffu, v, o);
            v = isMax ? fmaxf(v, u) : v + u;
        }
        if (lane == 0) sh[0] = v;
    }
    __syncthreads();
    v = sh[0];
    __syncthreads();
    return v;
}

// Masked causal softmax: f32 logits -> half scores. 256 thr/row.
// Dead rows (mask[i]==0) early-out: their score rows are never consumed
// (the consuming GEMM row-tiles are mask-gated).
__global__ void attn_softmax_k(const float* __restrict__ logits,
                               const float* __restrict__ mask,
                               __half* __restrict__ score)
{
    int row = blockIdx.x;
    int b = row >> 9;
    int i = row & 511;
    const float* mrow = mask + ((size_t)b << 9);
    if (mrow[i] == 0.f) return;
    const float* L = logits + ((size_t)row << 9);
    __half* S = score + ((size_t)row << 9);
    int t = threadIdx.x;
    int j0 = t, j1 = t + 256;
    bool a0 = (i > j0) && (mrow[j0] > 0.f);
    bool a1 = (i > j1) && (mrow[j1] > 0.f);
    float x0 = L[j0] + (a0 ? 0.f : -1e30f);
    float x1 = L[j1] + (a1 ? 0.f : -1e30f);
    float mx = blockReduce(fmaxf(x0, x1), true);
    float e0 = expf(x0 - mx);
    float e1 = expf(x1 - mx);
    float s = blockReduce(e0 + e1, false);
    float inv = 1.f / s;
    S[j0] = __float2half_rn(a0 ? e0 * inv : 0.f);
    S[j1] = __float2half_rn(a1 ? e1 * inv : 0.f);
}

// m[row] = dot(prod[row,:], Wm2) + bm2; dead rows skipped (masked later)
__global__ void rowdot_k(const float* prod, const float* w, const float* b,
                         const float* mask, float* m)
{
    int row = blockIdx.x;
    if (mask[row] == 0.f) { if (threadIdx.x == 0) m[row] = 0.f; return; }
    const float* p = prod + ((size_t)row << 10);
    float s = 0.f;
    for (int h = threadIdx.x; h < HD; h += 256) s = fmaf(p[h], w[h], s);
    s = blockReduce(s, false);
    if (threadIdx.x == 0) m[row] = s + b[0];
}

// Per-batch masked softmax along sequence. 512 thr/batch.
__global__ void seq_softmax_k(const float* m, const float* mask, float* a)
{
    int b = blockIdx.x;
    int t = threadIdx.x;
    size_t idx = ((size_t)b << 9) + t;
    float msk = mask[idx];
    float x = m[idx] + (msk > 0.f ? 0.f : -1e30f);
    float mx = blockReduce(x, true);
    float e = expf(x - mx);
    float s = blockReduce(e, false);
    a[idx] = (msk > 0.f) ? e / s : 0.f;
}

// out = a[row] * encoding (writes ALL rows; a=0 kills stale enc on dead rows)
__global__ void scale_k(const float* a, const float* enc, float* out)
{
    size_t i = (size_t)blockIdx.x * blockDim.x + threadIdx.x;
    float4 e = ((const float4*)enc)[i];
    float s = a[(i * 4) >> 10];
    float4 o;
    o.x = e.x * s; o.y = e.y * s; o.z = e.z * s; o.w = e.w * s;
    ((float4*)out)[i] = o;
}

static const int SMEM_H = 2 * 2 * 128 * 144;   // 73728

extern "C" void kernel_launch(void* const* d_in, const int* in_sizes, int n_in,
                              void* d_out, int out_size)
{
    const float* cas_emb     = (const float*)d_in[0];
    const float* cas_mask    = (const float*)d_in[1];
    const float* time_weight = (const float*)d_in[2];
    const float* W1  = (const float*)d_in[3];
    const float* b1  = (const float*)d_in[4];
    const float* Wh  = (const float*)d_in[5];
    const float* bh  = (const float*)d_in[6];
    const float* Wt  = (const float*)d_in[7];
    const float* bt  = (const float*)d_in[8];
    const float* Wg  = (const float*)d_in[9];
    const float* bg  = (const float*)d_in[10];
    const float* Wm1 = (const float*)d_in[11];
    const float* bm1 = (const float*)d_in[12];
    const float* Wti = (const float*)d_in[13];
    const float* bti = (const float*)d_in[14];
    const float* Wm2 = (const float*)d_in[15];
    const float* bm2 = (const float*)d_in[16];
    float* out = (float*)d_out;

    float  *cat, *head, *tail, *logits, *enc, *mvec, *avec;
    __half *cath, *catT, *headh, *tailh, *scoreh, *ench, *embh, *twh, *wth;
    cudaGetSymbolAddress((void**)&cat,    g_cat);
    cudaGetSymbolAddress((void**)&cath,   g_cath);
    cudaGetSymbolAddress((void**)&catT,   g_catT);
    cudaGetSymbolAddress((void**)&head,   g_head);
    cudaGetSymbolAddress((void**)&tail,   g_tail);
    cudaGetSymbolAddress((void**)&headh,  g_headh);
    cudaGetSymbolAddress((void**)&tailh,  g_tailh);
    cudaGetSymbolAddress((void**)&logits, g_logits);
    cudaGetSymbolAddress((void**)&scoreh, g_scoreh);
    cudaGetSymbolAddress((void**)&enc,    g_enc);
    cudaGetSymbolAddress((void**)&ench,   g_ench);
    cudaGetSymbolAddress((void**)&embh,   g_embh);
    cudaGetSymbolAddress((void**)&twh,    g_twh);
    cudaGetSymbolAddress((void**)&wth,    g_wth);
    cudaGetSymbolAddress((void**)&mvec,   g_m);
    cudaGetSymbolAddress((void**)&avec,   g_a);

    cudaFuncSetAttribute(gemm_h<0,7>, cudaFuncAttributeMaxDynamicSharedMemorySize, SMEM_H);
    cudaFuncSetAttribute(gemm_h<0,9>, cudaFuncAttributeMaxDynamicSharedMemorySize, SMEM_H);
    cudaFuncSetAttribute(gemm_h<1,1>, cudaFuncAttributeMaxDynamicSharedMemorySize, SMEM_H);
    cudaFuncSetAttribute(gemm_h<2,1>, cudaFuncAttributeMaxDynamicSharedMemorySize, SMEM_H);
    cudaFuncSetAttribute(gemm_h<3,1>, cudaFuncAttributeMaxDynamicSharedMemorySize, SMEM_H);
    cudaFuncSetAttribute(gemm_h<4,1>, cudaFuncAttributeMaxDynamicSharedMemorySize, SMEM_H);
    cudaFuncSetAttribute(gemm_h<5,1>, cudaFuncAttributeMaxDynamicSharedMemorySize, SMEM_H);

    dim3 blk(256);
    dim3 tb(32, 8);

    tohalf_k<<<(ROWS*DE/4)/256, 256>>>(cas_emb, embh);
    tohalf_k<<<(ROWS*DT/4)/256, 256>>>(time_weight, twh);
    transpose_h_k<<<dim3(32,32,1), tb>>>(W1, wth + OFF_W1, 1024, 1024, 0, 0);
    transpose_h_k<<<dim3(32,32,1), tb>>>(Wh, wth + OFF_Wh, 1024, 1024, 0, 0);
    transpose_h_k<<<dim3(32,32,1), tb>>>(Wt, wth + OFF_Wt, 1024, 1024, 0, 0);

    // 1) cas_hidden = elu(emb @ W1 + b1)*mask -> cat f32 + cath half
    gemm_h<2,1><<<dim3(8,128,1), blk, SMEM_H>>>(
        embh, wth + OFF_W1, cat, cath, DE, DE, DE, 2048,
        0, 0, 0, b1, cas_mask, nullptr, 0, 0, cas_mask, 0);

    transpose_h_k<<<dim3(32,64,1), tb>>>(Wg,  wth + OFF_Wg,  1024, 2048, 0, 0);
    transpose_h_k<<<dim3(32,32,1), tb>>>(Wm1, wth + OFF_Wm1, 1024, 1024, 0, 0);
    transpose_h_k<<<dim3(32,2,1),  tb>>>(Wti, wth + OFF_Wti, 1024, 64,   0, 0);

    // 1.5) catT[b] = transpose(cas_hidden[b]) (half)
    transpose_h_k<<<dim3(32,16,32), tb>>>(
        cat, catT, 2048, 512, (long)SL * 2048, (long)HD * SL);

    // 2) head (half only)
    gemm_h<1,1><<<dim3(8,128,1), blk, SMEM_H>>>(
        cath, wth + OFF_Wh, nullptr, headh, HD, 2048, HD, HD,
        0, 0, 0, bh, nullptr, nullptr, 0, 0, cas_mask, 0);

    // 3) tail (half only)
    gemm_h<1,1><<<dim3(8,128,1), blk, SMEM_H>>>(
        cath, wth + OFF_Wt, nullptr, tailh, HD, 2048, HD, HD,
        0, 0, 0, bt, nullptr, nullptr, 0, 0, cas_mask, 0);

    // 4) logits[b] = head_b @ tail_b^T — causal tile skip + row/col mask gates
    gemm_h<0,7><<<dim3(4,4,BSZ), blk, SMEM_H>>>(
        headh, tailh, logits, nullptr, HD, HD, HD, SL,
        (long)SL * HD, (long)SL * HD, (long)SL * SL,
        nullptr, nullptr, nullptr, 0, 0, cas_mask, SL);

    // 5) masked causal softmax -> half scores
    attn_softmax_k<<<ROWS, 256>>>(logits, cas_mask, scoreh);

    // 6) depend[b] = score_b @ hidden_b — row gate + causal K-trunc
    gemm_h<0,9><<<dim3(8,4,BSZ), blk, SMEM_H>>>(
        scoreh, catT, cat + 1024, cath + 1024, SL, SL, SL, 2048,
        (long)SL * SL, (long)HD * SL, (long)SL * 2048,
        nullptr, nullptr, nullptr, 0, 0, cas_mask, SL);

    // 7) enc = (g*h + (1-g)*d)*mask -> enc f32 + ench half
    gemm_h<3,1><<<dim3(8,128,1), blk, SMEM_H>>>(
        cath, wth + OFF_Wg, enc, ench, 2048, 2048, 2048, HD,
        0, 0, 0, bg, cas_mask, cat, 2048, 1024, cas_mask, 0);

    // 8) time_inf = elu(tw @ Wti + bti) -> tail f32
    gemm_h<4,1><<<dim3(8,128,1), blk, SMEM_H>>>(
        twh, wth + OFF_Wti, tail, nullptr, DT, DT, DT, HD,
        0, 0, 0, bti, nullptr, nullptr, 0, 0, cas_mask, 0);

    // 9) prod = elu(enc @ Wm1 + bm1) * time_inf -> head f32
    gemm_h<5,1><<<dim3(8,128,1), blk, SMEM_H>>>(
        ench, wth + OFF_Wm1, head, nullptr, HD, HD, HD, HD,
        0, 0, 0, bm1, nullptr, tail, HD, 0, cas_mask, 0);

    // 10) m = prod @ Wm2 + bm2
    rowdot_k<<<ROWS, 256>>>(head, Wm2, bm2, cas_mask, mvec);

    // 11) a = masked softmax over sequence
    seq_softmax_k<<<BSZ, 512>>>(mvec, cas_mask, avec);

    // 12) out = a * encoding
    scale_k<<<(ROWS * HD / 4) / 256, 256>>>(avec, enc, out);
}

// round 11
// speedup vs baseline: 6.8058x; 1.0082x over previous
#include <cuda_runtime.h>
#include <cuda_fp16.h>
#include <math.h>
#include <stdint.h>

// Problem constants
#define BSZ 32
#define SL  512
#define HD  1024
#define DE  1024
#define DT  64
#define ROWS (BSZ*SL)          // 16384

// ---------------- scratch (__device__ globals, alloc-free) ----------------
__device__ float  g_cat[(size_t)ROWS * 2048];     // f32: [:, :1024]=cas_hidden, [:,1024:]=depend
__device__ __half g_cath[(size_t)ROWS * 2048];    // half copy (GEMM operand)
__device__ __half g_catT[(size_t)BSZ * HD * SL];  // per-batch transposed hidden [h][j] half
__device__ float  g_head[(size_t)ROWS * HD];      // f32: prod (stage 9 output)
__device__ float  g_tail[(size_t)ROWS * HD];      // f32: time_inf
__device__ __half g_hth[(size_t)ROWS * 2048];     // half: [:, :1024]=head, [:,1024:]=tail
__device__ float  g_logits[(size_t)BSZ * SL * SL];
__device__ __half g_scoreh[(size_t)BSZ * SL * SL];
__device__ float  g_enc[(size_t)ROWS * HD];
__device__ __half g_ench[(size_t)ROWS * HD];
__device__ __half g_embh[(size_t)ROWS * DE];
__device__ __half g_twh[(size_t)ROWS * DT];
__device__ __half g_wth[6356992];                 // transposed half weights, packed
__device__ float  g_bht[2048];                    // packed bias [bh | bt]
__device__ float  g_m[ROWS];
__device__ float  g_a[ROWS];

#define OFF_W1  0
#define OFF_Wh  1048576
#define OFF_Wt  2097152
#define OFF_Wg  3145728
#define OFF_Wm1 5242880
#define OFF_Wti 6291456

__device__ __forceinline__ float eluf(float x) { return x > 0.f ? x : expm1f(x); }

__device__ __forceinline__ void mma_f16(float c[4], const uint32_t a[4], const uint32_t b[2]) {
    asm volatile(
        "mma.sync.aligned.m16n8k16.row.col.f32.f16.f16.f32 "
        "{%0,%1,%2,%3},{%4,%5,%6,%7},{%8,%9},{%0,%1,%2,%3};"
        : "+f"(c[0]), "+f"(c[1]), "+f"(c[2]), "+f"(c[3])
        : "r"(a[0]), "r"(a[1]), "r"(a[2]), "r"(a[3]), "r"(b[0]), "r"(b[1]));
}
#define LDSM4(r0, r1, r2, r3, addr) \
    asm volatile("ldmatrix.sync.aligned.m8n8.x4.shared.b16 {%0,%1,%2,%3}, [%4];" \
                 : "=r"(r0), "=r"(r1), "=r"(r2), "=r"(r3) : "r"(addr))
#define CP16(dst, src) \
    asm volatile("cp.async.cg.shared.global [%0], [%1], 16;" :: "r"(dst), "l"(src))
#define CP_COMMIT asm volatile("cp.async.commit_group;")
#define CP_WAIT2  asm volatile("cp.async.wait_group 2;" ::: "memory")

// ---------------------------------------------------------------------------
// fp16 tensor-core GEMM: C[M,N] = epi(A[M,K] @ B[N,K]^T + bias)
// CTA tile 128x128, BK=64, 3-stage cp.async, 8 warps (2x4), ldmatrix.x4.
// 2 CTAs/SM (regs capped at 124).
// EPI: 0=none, 1=bias, 2=elu*rowmask, 3=sigmoid-gate-blend, 4=elu, 5=elu*aux
// CM bitmask: 1=row-tile mask gate, 2=col-tile mask gate (batched),
//             4=causal tile skip (x>y), 8=causal K truncation (K<=row0+128)
// ---------------------------------------------------------------------------
template<int EPI, int CM>
__global__ __launch_bounds__(256, 2)
void gemm_h(const __half* __restrict__ A, const __half* __restrict__ B,
            float* __restrict__ C, __half* __restrict__ C2,
            int K, int lda, int ldb, int ldc,
            long sA, long sB, long sC,
            const float* __restrict__ bias, const float* __restrict__ rowmask,
            const float* __restrict__ aux, int auxld, int auxoff,
            const float* __restrict__ gmask, int mstride)
{
    const int z = blockIdx.z;
    const int row0 = blockIdx.y * 128;
    const int col0 = blockIdx.x * 128;

    if (CM & 4) { if (blockIdx.x > blockIdx.y) return; }
    if (CM & 1) { if (gmask[(size_t)z * mstride + row0] == 0.f) return; }
    if (CM & 2) { if (gmask[(size_t)z * mstride + col0] == 0.f) return; }

    constexpr int STAGE_B = 2 * 128 * 144;      // A+B tile bytes per stage
    extern __shared__ char smem[];
    uint32_t sb;
    asm("{ .reg .u64 t; cvta.to.shared.u64 t, %1; cvt.u32.u64 %0, t; }" : "=r"(sb) : "l"(smem));

    A += (size_t)z * sA;
    B += (size_t)z * sB;

    const int tid = threadIdx.x, lane = tid & 31, wid = tid >> 5;
    const int wr = wid >> 2, wc = wid & 3;
    const int group = lane >> 2, tig = lane & 3;

    float acc[4][4][4];
#pragma unroll
    for (int i = 0; i < 4; i++)
#pragma unroll
        for (int j = 0; j < 4; j++)
#pragma unroll
            for (int c = 0; c < 4; c++) acc[i][j][c] = 0.f;

    auto load = [&](int s, int kt) {
        const int k0 = kt << 6;
        const uint32_t ab = sb + s * STAGE_B;
        const uint32_t bb = ab + 128 * 144;
#pragma unroll
        for (int p = 0; p < 4; p++) {
            int idx = tid + (p << 8);
            int r = idx >> 3;
            int c8 = (idx & 7) << 3;
            uint32_t d = r * 144 + (c8 << 1);
            CP16(ab + d, A + (size_t)(row0 + r) * lda + k0 + c8);
            CP16(bb + d, B + (size_t)(col0 + r) * ldb + k0 + c8);
        }
    };

    const int Keff = (CM & 8) ? ((row0 + 128 < K) ? row0 + 128 : K) : K;
    const int nt = Keff >> 6;                   // BK = 64

    // 3-stage prologue: always exactly 2 commit groups
    load(0, 0); CP_COMMIT;
    if (nt > 1) load(1, 1);
    CP_COMMIT;

    for (int t = 0; t < nt; t++) {
        if (t + 2 < nt) load((t + 2) % 3, t + 2);
        CP_COMMIT;                               // one group per iter (may be empty)
        CP_WAIT2;                                // tile t's group drained
        __syncthreads();

        const uint32_t ab = sb + (t % 3) * STAGE_B;
        const uint32_t bb = ab + 128 * 144;
        const uint32_t koff = ((lane >> 4) << 4);
        const int rsel = lane & 15;

#pragma unroll
        for (int kk4 = 0; kk4 < 4; kk4++) {
            const uint32_t kb = (kk4 << 5) + koff;
            uint32_t af[4][4];
#pragma unroll
            for (int mf = 0; mf < 4; mf++) {
                uint32_t addr = ab + (uint32_t)(wr * 64 + mf * 16 + rsel) * 144 + kb;
                LDSM4(af[mf][0], af[mf][1], af[mf][2], af[mf][3], addr);
            }
            uint32_t bf[4][2];
#pragma unroll
            for (int g = 0; g < 2; g++) {
                uint32_t r0, r1, r2, r3;
                uint32_t addr = bb + (uint32_t)(wc * 32 + g * 16 + rsel) * 144 + kb;
                LDSM4(r0, r1, r2, r3, addr);
                bf[2 * g][0] = r0; bf[2 * g][1] = r2;
                bf[2 * g + 1][0] = r1; bf[2 * g + 1][1] = r3;
            }
#pragma unroll
            for (int mf = 0; mf < 4; mf++)
#pragma unroll
                for (int nf = 0; nf < 4; nf++)
                    mma_f16(acc[mf][nf], af[mf], bf[nf]);
        }
        __syncthreads();
    }

    // ---- fused epilogue ----
#pragma unroll
    for (int mf = 0; mf < 4; mf++) {
        int rbase = row0 + wr * 64 + mf * 16 + group;
#pragma unroll
        for (int half = 0; half < 2; half++) {
            int m = rbase + half * 8;
            float rm = 1.f;
            if (EPI == 2 || EPI == 3) rm = rowmask[m];
#pragma unroll
            for (int nf = 0; nf < 4; nf++) {
                int n = col0 + wc * 32 + nf * 8 + 2 * tig;
                float v0 = acc[mf][nf][half * 2 + 0];
                float v1 = acc[mf][nf][half * 2 + 1];
                if (EPI != 0) { v0 += bias[n]; v1 += bias[n + 1]; }
                if (EPI == 2) {
                    v0 = eluf(v0) * rm;
                    v1 = eluf(v1) * rm;
                } else if (EPI == 3) {
                    float2 h = *(const float2*)&aux[(size_t)m * auxld + n];
                    float2 d = *(const float2*)&aux[(size_t)m * auxld + n + auxoff];
                    float g0 = 1.f / (1.f + expf(-v0));
                    float g1 = 1.f / (1.f + expf(-v1));
                    v0 = (g0 * h.x + (1.f - g0) * d.x) * rm;
                    v1 = (g1 * h.y + (1.f - g1) * d.y) * rm;
                } else if (EPI == 4) {
                    v0 = eluf(v0);
                    v1 = eluf(v1);
                } else if (EPI == 5) {
                    float2 ax = *(const float2*)&aux[(size_t)m * auxld + n];
                    v0 = eluf(v0) * ax.x;
                    v1 = eluf(v1) * ax.y;
                }
                size_t off = (size_t)z * sC + (size_t)m * ldc + n;
                if (C)  *(float2*)&C[off] = make_float2(v0, v1);
                if (C2) *(__half2*)&C2[off] = __floats2half2_rn(v0, v1);
            }
        }
    }
}

// ---------------------------------------------------------------------------
// f32 -> f16 convert (4 elems/thread)
__global__ void tohalf_k(const float* __restrict__ src, __half* __restrict__ dst)
{
    size_t i = (size_t)blockIdx.x * blockDim.x + threadIdx.x;
    float4 v = ((const float4*)src)[i];
    ((__half2*)dst)[2 * i]     = __floats2half2_rn(v.x, v.y);
    ((__half2*)dst)[2 * i + 1] = __floats2half2_rn(v.z, v.w);
}

// transpose f32 [R,C] (row stride sld) -> half [C,R] (row stride dld), batched
__global__ void transpose_h_k(const float* __restrict__ src, __half* __restrict__ dst,
                              int sld, int dld, long zs, long zd)
{
    __shared__ float t[32][33];
    const float* S = src + (size_t)blockIdx.z * zs;
    __half* D = dst + (size_t)blockIdx.z * zd;
    int c0 = blockIdx.x * 32;
    int r0 = blockIdx.y * 32;
    int x = threadIdx.x, y = threadIdx.y;
#pragma unroll
    for (int i = 0; i < 4; i++)
        t[y + 8 * i][x] = S[(size_t)(r0 + y + 8 * i) * sld + c0 + x];
    __syncthreads();
#pragma unroll
    for (int i = 0; i < 4; i++)
        D[(size_t)(c0 + y + 8 * i) * dld + r0 + x] = __float2half_rn(t[x][y + 8 * i]);
}

// ---------------------------------------------------------------------------
__device__ __forceinline__ float blockReduce(float v, bool isMax)
{
    __shared__ float sh[32];
    int lane = threadIdx.x & 31;
    int w = threadIdx.x >> 5;
    int nw = blockDim.x >> 5;
#pragma unroll
    for (int o = 16; o; o >>= 1) {
        float u = __shfl_xor_sync(0xffffffffu, v, o);
        v = isMax ? fmaxf(v, u) : v + u;
    }
    if (lane == 0) sh[w] = v;
    __syncthreads();
    if (w == 0) {
        v = (lane < nw) ? sh[lane] : (isMax ? -INFINITY : 0.f);
#pragma unroll
        for (int o = 16; o; o >>= 1) {
            float u = __shfl_xor_sync(0xffffffffu, v, o);
            v = isMax ? fmaxf(v, u) : v + u;
        }
        if (lane == 0) sh[0] = v;
    }
    __syncthreads();
    v = sh[0];
    __syncthreads();
    return v;
}

// Masked causal softmax: f32 logits -> half scores. 256 thr/row.
__global__ void attn_softmax_k(const float* __restrict__ logits,
                               const float* __restrict__ mask,
                               __half* __restrict__ score)
{
    int row = blockIdx.x;
    int b = row >> 9;
    int i = row & 511;
    const float* mrow = mask + ((size_t)b << 9);
    if (mrow[i] == 0.f) return;
    const float* L = logits + ((size_t)row << 9);
    __half* S = score + ((size_t)row << 9);
    int t = threadIdx.x;
    int j0 = t, j1 = t + 256;
    bool a0 = (i > j0) && (mrow[j0] > 0.f);
    bool a1 = (i > j1) && (mrow[j1] > 0.f);
    float x0 = L[j0] + (a0 ? 0.f : -1e30f);
    float x1 = L[j1] + (a1 ? 0.f : -1e30f);
    float mx = blockReduce(fmaxf(x0, x1), true);
    float e0 = expf(x0 - mx);
    float e1 = expf(x1 - mx);
    float s = blockReduce(e0 + e1, false);
    float inv = 1.f / s;
    S[j0] = __float2half_rn(a0 ? e0 * inv : 0.f);
    S[j1] = __float2half_rn(a1 ? e1 * inv : 0.f);
}

// m[row] = dot(prod[row,:], Wm2) + bm2; dead rows skipped (masked later)
__global__ void rowdot_k(const float* prod, const float* w, const float* b,
                         const float* mask, float* m)
{
    int row = blockIdx.x;
    if (mask[row] == 0.f) { if (threadIdx.x == 0) m[row] = 0.f; return; }
    const float* p = prod + ((size_t)row << 10);
    float s = 0.f;
    for (int h = threadIdx.x; h < HD; h += 256) s = fmaf(p[h], w[h], s);
    s = blockReduce(s, false);
    if (threadIdx.x == 0) m[row] = s + b[0];
}

// Per-batch masked softmax along sequence. 512 thr/batch.
__global__ void seq_softmax_k(const float* m, const float* mask, float* a)
{
    int b = blockIdx.x;
    int t = threadIdx.x;
    size_t idx = ((size_t)b << 9) + t;
    float msk = mask[idx];
    float x = m[idx] + (msk > 0.f ? 0.f : -1e30f);
    float mx = blockReduce(x, true);
    float e = expf(x - mx);
    float s = blockReduce(e, false);
    a[idx] = (msk > 0.f) ? e / s : 0.f;
}

// out = a[row] * encoding (writes ALL rows; a=0 kills stale enc on dead rows)
__global__ void scale_k(const float* a, const float* enc, float* out)
{
    size_t i = (size_t)blockIdx.x * blockDim.x + threadIdx.x;
    float4 e = ((const float4*)enc)[i];
    float s = a[(i * 4) >> 10];
    float4 o;
    o.x = e.x * s; o.y = e.y * s; o.z = e.z * s; o.w = e.w * s;
    ((float4*)out)[i] = o;
}

static const int SMEM_H = 3 * 2 * 128 * 144;   // 110592

extern "C" void kernel_launch(void* const* d_in, const int* in_sizes, int n_in,
                              void* d_out, int out_size)
{
    const float* cas_emb     = (const float*)d_in[0];
    const float* cas_mask    = (const float*)d_in[1];
    const float* time_weight = (const float*)d_in[2];
    const float* W1  = (const float*)d_in[3];
    const float* b1  = (const float*)d_in[4];
    const float* Wh  = (const float*)d_in[5];
    const float* bh  = (const float*)d_in[6];
    const float* Wt  = (const float*)d_in[7];
    const float* bt  = (const float*)d_in[8];
    const float* Wg  = (const float*)d_in[9];
    const float* bg  = (const float*)d_in[10];
    const float* Wm1 = (const float*)d_in[11];
    const float* bm1 = (const float*)d_in[12];
    const float* Wti = (const float*)d_in[13];
    const float* bti = (const float*)d_in[14];
    const float* Wm2 = (const float*)d_in[15];
    const float* bm2 = (const float*)d_in[16];
    float* out = (float*)d_out;

    float  *cat, *head, *tail, *logits, *enc, *mvec, *avec, *bht;
    __half *cath, *catT, *hth, *scoreh, *ench, *embh, *twh, *wth;
    cudaGetSymbolAddress((void**)&cat,    g_cat);
    cudaGetSymbolAddress((void**)&cath,   g_cath);
    cudaGetSymbolAddress((void**)&catT,   g_catT);
    cudaGetSymbolAddress((void**)&head,   g_head);
    cudaGetSymbolAddress((void**)&tail,   g_tail);
    cudaGetSymbolAddress((void**)&hth,    g_hth);
    cudaGetSymbolAddress((void**)&logits, g_logits);
    cudaGetSymbolAddress((void**)&scoreh, g_scoreh);
    cudaGetSymbolAddress((void**)&enc,    g_enc);
    cudaGetSymbolAddress((void**)&ench,   g_ench);
    cudaGetSymbolAddress((void**)&embh,   g_embh);
    cudaGetSymbolAddress((void**)&twh,    g_twh);
    cudaGetSymbolAddress((void**)&wth,    g_wth);
    cudaGetSymbolAddress((void**)&bht,    g_bht);
    cudaGetSymbolAddress((void**)&mvec,   g_m);
    cudaGetSymbolAddress((void**)&avec,   g_a);

    cudaFuncSetAttribute(gemm_h<0,7>, cudaFuncAttributeMaxDynamicSharedMemorySize, SMEM_H);
    cudaFuncSetAttribute(gemm_h<0,9>, cudaFuncAttributeMaxDynamicSharedMemorySize, SMEM_H);
    cudaFuncSetAttribute(gemm_h<1,1>, cudaFuncAttributeMaxDynamicSharedMemorySize, SMEM_H);
    cudaFuncSetAttribute(gemm_h<2,1>, cudaFuncAttributeMaxDynamicSharedMemorySize, SMEM_H);
    cudaFuncSetAttribute(gemm_h<3,1>, cudaFuncAttributeMaxDynamicSharedMemorySize, SMEM_H);
    cudaFuncSetAttribute(gemm_h<4,1>, cudaFuncAttributeMaxDynamicSharedMemorySize, SMEM_H);
    cudaFuncSetAttribute(gemm_h<5,1>, cudaFuncAttributeMaxDynamicSharedMemorySize, SMEM_H);

    dim3 blk(256);
    dim3 tb(32, 8);

    // packed bias for fused head|tail GEMM
    cudaMemcpyAsync(bht,        bh, HD * sizeof(float), cudaMemcpyDeviceToDevice);
    cudaMemcpyAsync(bht + 1024, bt, HD * sizeof(float), cudaMemcpyDeviceToDevice);

    tohalf_k<<<(ROWS*DE/4)/256, 256>>>(cas_emb, embh);
    tohalf_k<<<(ROWS*DT/4)/256, 256>>>(time_weight, twh);
    transpose_h_k<<<dim3(32,32,1), tb>>>(W1, wth + OFF_W1, 1024, 1024, 0, 0);
    transpose_h_k<<<dim3(32,32,1), tb>>>(Wh, wth + OFF_Wh, 1024, 1024, 0, 0);
    transpose_h_k<<<dim3(32,32,1), tb>>>(Wt, wth + OFF_Wt, 1024, 1024, 0, 0);

    // 1) cas_hidden = elu(emb @ W1 + b1)*mask -> cat f32 + cath half
    gemm_h<2,1><<<dim3(8,128,1), blk, SMEM_H>>>(
        embh, wth + OFF_W1, cat, cath, DE, DE, DE, 2048,
        0, 0, 0, b1, cas_mask, nullptr, 0, 0, cas_mask, 0);

    transpose_h_k<<<dim3(32,64,1), tb>>>(Wg,  wth + OFF_Wg,  1024, 2048, 0, 0);
    transpose_h_k<<<dim3(32,32,1), tb>>>(Wm1, wth + OFF_Wm1, 1024, 1024, 0, 0);
    transpose_h_k<<<dim3(32,2,1),  tb>>>(Wti, wth + OFF_Wti, 1024, 64,   0, 0);

    // 1.5) catT[b] = transpose(cas_hidden[b]) (half)
    transpose_h_k<<<dim3(32,16,32), tb>>>(
        cat, catT, 2048, 512, (long)SL * 2048, (long)HD * SL);

    // 2+3) fused head|tail: hth = round(cas_hidden @ [Wh|Wt] + [bh|bt]), N=2048
    gemm_h<1,1><<<dim3(16,128,1), blk, SMEM_H>>>(
        cath, wth + OFF_Wh, nullptr, hth, HD, 2048, HD, 2048,
        0, 0, 0, bht, nullptr, nullptr, 0, 0, cas_mask, 0);

    // 4) logits[b] = head_b @ tail_b^T — causal tile skip + row/col mask gates
    gemm_h<0,7><<<dim3(4,4,BSZ), blk, SMEM_H>>>(
        hth, hth + 1024, logits, nullptr, HD, 2048, 2048, SL,
        (long)SL * 2048, (long)SL * 2048, (long)SL * SL,
        nullptr, nullptr, nullptr, 0, 0, cas_mask, SL);

    // 5) masked causal softmax -> half scores
    attn_softmax_k<<<ROWS, 256>>>(logits, cas_mask, scoreh);

    // 6) depend[b] = score_b @ hidden_b — row gate + causal K-trunc
    gemm_h<0,9><<<dim3(8,4,BSZ), blk, SMEM_H>>>(
        scoreh, catT, cat + 1024, cath + 1024, SL, SL, SL, 2048,
        (long)SL * SL, (long)HD * SL, (long)SL * 2048,
        nullptr, nullptr, nullptr, 0, 0, cas_mask, SL);

    // 7) enc = (g*h + (1-g)*d)*mask -> enc f32 + ench half
    gemm_h<3,1><<<dim3(8,128,1), blk, SMEM_H>>>(
        cath, wth + OFF_Wg, enc, ench, 2048, 2048, 2048, HD,
        0, 0, 0, bg, cas_mask, cat, 2048, 1024, cas_mask, 0);

    // 8) time_inf = elu(tw @ Wti + bti) -> tail f32
    gemm_h<4,1><<<dim3(8,128,1), blk, SMEM_H>>>(
        twh, wth + OFF_Wti, tail, nullptr, DT, DT, DT, HD,
        0, 0, 0, bti, nullptr, nullptr, 0, 0, cas_mask, 0);

    // 9) prod = elu(enc @ Wm1 + bm1) * time_inf -> head f32
    gemm_h<5,1><<<dim3(8,128,1), blk, SMEM_H>>>(
        ench, wth + OFF_Wm1, head, nullptr, HD, HD, HD, HD,
        0, 0, 0, bm1, nullptr, tail, HD, 0, cas_mask, 0);

    // 10) m = prod @ Wm2 + bm2
    rowdot_k<<<ROWS, 256>>>(head, Wm2, bm2, cas_mask, mvec);

    // 11) a = masked softmax over sequence
    seq_softmax_k<<<BSZ, 512>>>(mvec, cas_mask, avec);

    // 12) out = a * encoding
    scale_k<<<(ROWS * HD / 4) / 256, 256>>>(avec, enc, out);
}

// round 13
// speedup vs baseline: 6.8102x; 1.0006x over previous
#include <cuda_runtime.h>
#include <cuda_fp16.h>
#include <math.h>
#include <stdint.h>

// Problem constants
#define BSZ 32
#define SL  512
#define HD  1024
#define DE  1024
#define DT  64
#define ROWS (BSZ*SL)          // 16384

// ---------------- scratch (__device__ globals, alloc-free) ----------------
__device__ float  g_cat[(size_t)ROWS * 2048];     // f32: [:, :1024]=cas_hidden, [:,1024:]=depend
__device__ __half g_cath[(size_t)ROWS * 2048];    // half copy (GEMM operand)
__device__ __half g_catT[(size_t)BSZ * HD * SL];  // per-batch transposed hidden [h][j] half
__device__ float  g_head[(size_t)ROWS * HD];      // f32: prod (stage 9 output)
__device__ float  g_tail[(size_t)ROWS * HD];      // f32: time_inf
__device__ __half g_hth[(size_t)ROWS * 2048];     // half: [:, :1024]=head, [:,1024:]=tail
__device__ float  g_logits[(size_t)BSZ * SL * SL];
__device__ __half g_scoreh[(size_t)BSZ * SL * SL];
__device__ float  g_enc[(size_t)ROWS * HD];
__device__ __half g_ench[(size_t)ROWS * HD];
__device__ __half g_embh[(size_t)ROWS * DE];
__device__ __half g_twh[(size_t)ROWS * DT];
__device__ __half g_wth[6356992];                 // transposed half weights, packed
__device__ float  g_m[ROWS];
__device__ float  g_a[ROWS];

#define OFF_W1  0
#define OFF_Wh  1048576
#define OFF_Wt  2097152
#define OFF_Wg  3145728
#define OFF_Wm1 5242880
#define OFF_Wti 6291456

__device__ __forceinline__ float eluf(float x) { return x > 0.f ? x : expm1f(x); }

__device__ __forceinline__ void mma_f16(float c[4], const uint32_t a[4], const uint32_t b[2]) {
    asm volatile(
        "mma.sync.aligned.m16n8k16.row.col.f32.f16.f16.f32 "
        "{%0,%1,%2,%3},{%4,%5,%6,%7},{%8,%9},{%0,%1,%2,%3};"
        : "+f"(c[0]), "+f"(c[1]), "+f"(c[2]), "+f"(c[3])
        : "r"(a[0]), "r"(a[1]), "r"(a[2]), "r"(a[3]), "r"(b[0]), "r"(b[1]));
}
#define LDSM4(r0, r1, r2, r3, addr) \
    asm volatile("ldmatrix.sync.aligned.m8n8.x4.shared.b16 {%0,%1,%2,%3}, [%4];" \
                 : "=r"(r0), "=r"(r1), "=r"(r2), "=r"(r3) : "r"(addr))
#define CP16(dst, src) \
    asm volatile("cp.async.cg.shared.global [%0], [%1], 16;" :: "r"(dst), "l"(src))
#define CP_COMMIT asm volatile("cp.async.commit_group;")
#define CP_WAIT2  asm volatile("cp.async.wait_group 2;" ::: "memory")

// ---------------------------------------------------------------------------
// fp16 tensor-core GEMM: C[M,N] = epi(A[M,K] @ B[N,K]^T + bias)
// CTA tile 128x128, BK=64, 3-stage cp.async, 8 warps (2x4), ldmatrix.x4.
// 2 CTAs/SM (regs capped at 124).
// EPI: 0=none, 1=bias, 2=elu*rowmask, 3=sigmoid-gate-blend, 4=elu, 5=elu*aux
// CM bitmask: 1=row-tile mask gate, 2=col-tile mask gate (batched),
//             4=causal tile skip (x>y), 8=causal K truncation (K<=row0+128)
// bias2: optional second bias for fused N=2048 outputs (cols >=1024).
// ---------------------------------------------------------------------------
template<int EPI, int CM>
__global__ __launch_bounds__(256, 2)
void gemm_h(const __half* __restrict__ A, const __half* __restrict__ B,
            float* __restrict__ C, __half* __restrict__ C2,
            int K, int lda, int ldb, int ldc,
            long sA, long sB, long sC,
            const float* __restrict__ bias, const float* __restrict__ bias2,
            const float* __restrict__ rowmask,
            const float* __restrict__ aux, int auxld, int auxoff,
            const float* __restrict__ gmask, int mstride)
{
    const int z = blockIdx.z;
    const int row0 = blockIdx.y * 128;
    const int col0 = blockIdx.x * 128;

    if (CM & 4) { if (blockIdx.x > blockIdx.y) return; }
    if (CM & 1) { if (gmask[(size_t)z * mstride + row0] == 0.f) return; }
    if (CM & 2) { if (gmask[(size_t)z * mstride + col0] == 0.f) return; }

    constexpr int STAGE_B = 2 * 128 * 144;      // A+B tile bytes per stage
    extern __shared__ char smem[];
    uint32_t sb;
    asm("{ .reg .u64 t; cvta.to.shared.u64 t, %1; cvt.u32.u64 %0, t; }" : "=r"(sb) : "l"(smem));

    A += (size_t)z * sA;
    B += (size_t)z * sB;

    const int tid = threadIdx.x, lane = tid & 31, wid = tid >> 5;
    const int wr = wid >> 2, wc = wid & 3;
    const int group = lane >> 2, tig = lane & 3;

    float acc[4][4][4];
#pragma unroll
    for (int i = 0; i < 4; i++)
#pragma unroll
        for (int j = 0; j < 4; j++)
#pragma unroll
            for (int c = 0; c < 4; c++) acc[i][j][c] = 0.f;

    auto load = [&](int s, int kt) {
        const int k0 = kt << 6;
        const uint32_t ab = sb + s * STAGE_B;
        const uint32_t bb = ab + 128 * 144;
#pragma unroll
        for (int p = 0; p < 4; p++) {
            int idx = tid + (p << 8);
            int r = idx >> 3;
            int c8 = (idx & 7) << 3;
            uint32_t d = r * 144 + (c8 << 1);
            CP16(ab + d, A + (size_t)(row0 + r) * lda + k0 + c8);
            CP16(bb + d, B + (size_t)(col0 + r) * ldb + k0 + c8);
        }
    };

    const int Keff = (CM & 8) ? ((row0 + 128 < K) ? row0 + 128 : K) : K;
    const int nt = Keff >> 6;                   // BK = 64

    // 3-stage prologue: always exactly 2 commit groups
    load(0, 0); CP_COMMIT;
    if (nt > 1) load(1, 1);
    CP_COMMIT;

    for (int t = 0; t < nt; t++) {
        if (t + 2 < nt) load((t + 2) % 3, t + 2);
        CP_COMMIT;                               // one group per iter (may be empty)
        CP_WAIT2;                                // tile t's group drained
        __syncthreads();

        const uint32_t ab = sb + (t % 3) * STAGE_B;
        const uint32_t bb = ab + 128 * 144;
        const uint32_t koff = ((lane >> 4) << 4);
        const int rsel = lane & 15;

#pragma unroll
        for (int kk4 = 0; kk4 < 4; kk4++) {
            const uint32_t kb = (kk4 << 5) + koff;
            uint32_t af[4][4];
#pragma unroll
            for (int mf = 0; mf < 4; mf++) {
                uint32_t addr = ab + (uint32_t)(wr * 64 + mf * 16 + rsel) * 144 + kb;
                LDSM4(af[mf][0], af[mf][1], af[mf][2], af[mf][3], addr);
            }
            uint32_t bf[4][2];
#pragma unroll
            for (int g = 0; g < 2; g++) {
                uint32_t r0, r1, r2, r3;
                uint32_t addr = bb + (uint32_t)(wc * 32 + g * 16 + rsel) * 144 + kb;
                LDSM4(r0, r1, r2, r3, addr);
                bf[2 * g][0] = r0; bf[2 * g][1] = r2;
                bf[2 * g + 1][0] = r1; bf[2 * g + 1][1] = r3;
            }
#pragma unroll
            for (int mf = 0; mf < 4; mf++)
#pragma unroll
                for (int nf = 0; nf < 4; nf++)
                    mma_f16(acc[mf][nf], af[mf], bf[nf]);
        }
        __syncthreads();
    }

    // ---- fused epilogue ----
#pragma unroll
    for (int mf = 0; mf < 4; mf++) {
        int rbase = row0 + wr * 64 + mf * 16 + group;
#pragma unroll
        for (int half = 0; half < 2; half++) {
            int m = rbase + half * 8;
            float rm = 1.f;
            if (EPI == 2 || EPI == 3) rm = rowmask[m];
#pragma unroll
            for (int nf = 0; nf < 4; nf++) {
                int n = col0 + wc * 32 + nf * 8 + 2 * tig;
                float v0 = acc[mf][nf][half * 2 + 0];
                float v1 = acc[mf][nf][half * 2 + 1];
                if (EPI != 0) {
                    const float* bp = (bias2 && n >= 1024) ? bias2 - 1024 : bias;
                    v0 += bp[n]; v1 += bp[n + 1];
                }
                if (EPI == 2) {
                    v0 = eluf(v0) * rm;
                    v1 = eluf(v1) * rm;
                } else if (EPI == 3) {
                    float2 h = *(const float2*)&aux[(size_t)m * auxld + n];
                    float2 d = *(const float2*)&aux[(size_t)m * auxld + n + auxoff];
                    float g0 = 1.f / (1.f + expf(-v0));
                    float g1 = 1.f / (1.f + expf(-v1));
                    v0 = (g0 * h.x + (1.f - g0) * d.x) * rm;
                    v1 = (g1 * h.y + (1.f - g1) * d.y) * rm;
                } else if (EPI == 4) {
                    v0 = eluf(v0);
                    v1 = eluf(v1);
                } else if (EPI == 5) {
                    float2 ax = *(const float2*)&aux[(size_t)m * auxld + n];
                    v0 = eluf(v0) * ax.x;
                    v1 = eluf(v1) * ax.y;
                }
                size_t off = (size_t)z * sC + (size_t)m * ldc + n;
                if (C)  *(float2*)&C[off] = make_float2(v0, v1);
                if (C2) *(__half2*)&C2[off] = __floats2half2_rn(v0, v1);
            }
        }
    }
}

// ---------------------------------------------------------------------------
// f32 -> f16 convert (4 elems/thread)
__global__ void tohalf_k(const float* __restrict__ src, __half* __restrict__ dst)
{
    size_t i = (size_t)blockIdx.x * blockDim.x + threadIdx.x;
    float4 v = ((const float4*)src)[i];
    ((__half2*)dst)[2 * i]     = __floats2half2_rn(v.x, v.y);
    ((__half2*)dst)[2 * i + 1] = __floats2half2_rn(v.z, v.w);
}

// transpose f32 [R,C] (row stride sld) -> half [C,R] (row stride dld), batched
__global__ void transpose_h_k(const float* __restrict__ src, __half* __restrict__ dst,
                              int sld, int dld, long zs, long zd)
{
    __shared__ float t[32][33];
    const float* S = src + (size_t)blockIdx.z * zs;
    __half* D = dst + (size_t)blockIdx.z * zd;
    int c0 = blockIdx.x * 32;
    int r0 = blockIdx.y * 32;
    int x = threadIdx.x, y = threadIdx.y;
#pragma unroll
    for (int i = 0; i < 4; i++)
        t[y + 8 * i][x] = S[(size_t)(r0 + y + 8 * i) * sld + c0 + x];
    __syncthreads();
#pragma unroll
    for (int i = 0; i < 4; i++)
        D[(size_t)(c0 + y + 8 * i) * dld + r0 + x] = __float2half_rn(t[x][y + 8 * i]);
}

// ---------------------------------------------------------------------------
__device__ __forceinline__ float blockReduce(float v, bool isMax)
{
    __shared__ float sh[32];
    int lane = threadIdx.x & 31;
    int w = threadIdx.x >> 5;
    int nw = blockDim.x >> 5;
#pragma unroll
    for (int o = 16; o; o >>= 1) {
        float u = __shfl_xor_sync(0xffffffffu, v, o);
        v = isMax ? fmaxf(v, u) : v + u;
    }
    if (lane == 0) sh[w] = v;
    __syncthreads();
    if (w == 0) {
        v = (lane < nw) ? sh[lane] : (isMax ? -INFINITY : 0.f);
#pragma unroll
        for (int o = 16; o; o >>= 1) {
            float u = __shfl_xor_sync(0xffffffffu, v, o);
            v = isMax ? fmaxf(v, u) : v + u;
        }
        if (lane == 0) sh[0] = v;
    }
    __syncthreads();
    v = sh[0];
    __syncthreads();
    return v;
}

// Masked causal softmax: f32 logits -> half scores. 256 thr/row.
__global__ void attn_softmax_k(const float* __restrict__ logits,
                               const float* __restrict__ mask,
                               __half* __restrict__ score)
{
    int row = blockIdx.x;
    int b = row >> 9;
    int i = row & 511;
    const float* mrow = mask + ((size_t)b << 9);
    if (mrow[i] == 0.f) return;
    const float* L = logits + ((size_t)row << 9);
    __half* S = score + ((size_t)row << 9);
    int t = threadIdx.x;
    int j0 = t, j1 = t + 256;
    bool a0 = (i > j0) && (mrow[j0] > 0.f);
    bool a1 = (i > j1) && (mrow[j1] > 0.f);
    float x0 = L[j0] + (a0 ? 0.f : -1e30f);
    float x1 = L[j1] + (a1 ? 0.f : -1e30f);
    float mx = blockReduce(fmaxf(x0, x1), true);
    float e0 = expf(x0 - mx);
    float e1 = expf(x1 - mx);
    float s = blockReduce(e0 + e1, false);
    float inv = 1.f / s;
    S[j0] = __float2half_rn(a0 ? e0 * inv : 0.f);
    S[j1] = __float2half_rn(a1 ? e1 * inv : 0.f);
}

// m[row] = dot(prod[row,:], Wm2) + bm2; dead rows skipped (masked later)
__global__ void rowdot_k(const float* prod, const float* w, const float* b,
                         const float* mask, float* m)
{
    int row = blockIdx.x;
    if (mask[row] == 0.f) { if (threadIdx.x == 0) m[row] = 0.f; return; }
    const float* p = prod + ((size_t)row << 10);
    float s = 0.f;
    for (int h = threadIdx.x; h < HD; h += 256) s = fmaf(p[h], w[h], s);
    s = blockReduce(s, false);
    if (threadIdx.x == 0) m[row] = s + b[0];
}

// Per-batch masked softmax along sequence. 512 thr/batch.
__global__ void seq_softmax_k(const float* m, const float* mask, float* a)
{
    int b = blockIdx.x;
    int t = threadIdx.x;
    size_t idx = ((size_t)b << 9) + t;
    float msk = mask[idx];
    float x = m[idx] + (msk > 0.f ? 0.f : -1e30f);
    float mx = blockReduce(x, true);
    float e = expf(x - mx);
    float s = blockReduce(e, false);
    a[idx] = (msk > 0.f) ? e / s : 0.f;
}

// out = a[row] * encoding. One block = one row (1024 elems / 256 thr / f4).
// Dead rows (a==0): write zeros without reading enc (d_out is poisoned).
__global__ void scale_k(const float* a, const float* enc, float* out)
{
    int row = blockIdx.x;
    float s = a[row];
    size_t i = ((size_t)row << 8) + threadIdx.x;   // float4 index
    if (s == 0.f) {
        ((float4*)out)[i] = make_float4(0.f, 0.f, 0.f, 0.f);
        return;
    }
    float4 e = ((const float4*)enc)[i];
    float4 o;
    o.x = e.x * s; o.y = e.y * s; o.z = e.z * s; o.w = e.w * s;
    ((float4*)out)[i] = o;
}

static const int SMEM_H = 3 * 2 * 128 * 144;   // 110592

extern "C" void kernel_launch(void* const* d_in, const int* in_sizes, int n_in,
                              void* d_out, int out_size)
{
    const float* cas_emb     = (const float*)d_in[0];
    const float* cas_mask    = (const float*)d_in[1];
    const float* time_weight = (const float*)d_in[2];
    const float* W1  = (const float*)d_in[3];
    const float* b1  = (const float*)d_in[4];
    const float* Wh  = (const float*)d_in[5];
    const float* bh  = (const float*)d_in[6];
    const float* Wt  = (const float*)d_in[7];
    const float* bt  = (const float*)d_in[8];
    const float* Wg  = (const float*)d_in[9];
    const float* bg  = (const float*)d_in[10];
    const float* Wm1 = (const float*)d_in[11];
    const float* bm1 = (const float*)d_in[12];
    const float* Wti = (const float*)d_in[13];
    const float* bti = (const float*)d_in[14];
    const float* Wm2 = (const float*)d_in[15];
    const float* bm2 = (const float*)d_in[16];
    float* out = (float*)d_out;

    float  *cat, *head, *tail, *logits, *enc, *mvec, *avec;
    __half *cath, *catT, *hth, *scoreh, *ench, *embh, *twh, *wth;
    cudaGetSymbolAddress((void**)&cat,    g_cat);
    cudaGetSymbolAddress((void**)&cath,   g_cath);
    cudaGetSymbolAddress((void**)&catT,   g_catT);
    cudaGetSymbolAddress((void**)&head,   g_head);
    cudaGetSymbolAddress((void**)&tail,   g_tail);
    cudaGetSymbolAddress((void**)&hth,    g_hth);
    cudaGetSymbolAddress((void**)&logits, g_logits);
    cudaGetSymbolAddress((void**)&scoreh, g_scoreh);
    cudaGetSymbolAddress((void**)&enc,    g_enc);
    cudaGetSymbolAddress((void**)&ench,   g_ench);
    cudaGetSymbolAddress((void**)&embh,   g_embh);
    cudaGetSymbolAddress((void**)&twh,    g_twh);
    cudaGetSymbolAddress((void**)&wth,    g_wth);
    cudaGetSymbolAddress((void**)&mvec,   g_m);
    cudaGetSymbolAddress((void**)&avec,   g_a);

    cudaFuncSetAttribute(gemm_h<0,7>, cudaFuncAttributeMaxDynamicSharedMemorySize, SMEM_H);
    cudaFuncSetAttribute(gemm_h<0,9>, cudaFuncAttributeMaxDynamicSharedMemorySize, SMEM_H);
    cudaFuncSetAttribute(gemm_h<1,1>, cudaFuncAttributeMaxDynamicSharedMemorySize, SMEM_H);
    cudaFuncSetAttribute(gemm_h<2,1>, cudaFuncAttributeMaxDynamicSharedMemorySize, SMEM_H);
    cudaFuncSetAttribute(gemm_h<3,1>, cudaFuncAttributeMaxDynamicSharedMemorySize, SMEM_H);
    cudaFuncSetAttribute(gemm_h<4,1>, cudaFuncAttributeMaxDynamicSharedMemorySize, SMEM_H);
    cudaFuncSetAttribute(gemm_h<5,1>, cudaFuncAttributeMaxDynamicSharedMemorySize, SMEM_H);

    dim3 blk(256);
    dim3 tb(32, 8);

    // Kernel launch order is instrumentation-aware: slots 5 and 6 are GEMMs
    // so the ncu per-launch capture (-s 5 -c 1) lands on gemm_h.
    // (1..4) minimal prerequisites for the first two GEMMs
    tohalf_k<<<(ROWS*DE/4)/256, 256>>>(cas_emb, embh);                    // 1
    transpose_h_k<<<dim3(32,32,1), tb>>>(W1, wth + OFF_W1, 1024, 1024, 0, 0); // 2
    transpose_h_k<<<dim3(32,32,1), tb>>>(Wh, wth + OFF_Wh, 1024, 1024, 0, 0); // 3
    transpose_h_k<<<dim3(32,32,1), tb>>>(Wt, wth + OFF_Wt, 1024, 1024, 0, 0); // 4

    // 5) cas_hidden = elu(emb @ W1 + b1)*mask -> cat f32 + cath half
    gemm_h<2,1><<<dim3(8,128,1), blk, SMEM_H>>>(
        embh, wth + OFF_W1, cat, cath, DE, DE, DE, 2048,
        0, 0, 0, b1, nullptr, cas_mask, nullptr, 0, 0, cas_mask, 0);

    // 6) fused head|tail: hth = half(cas_hidden @ [Wh|Wt] + [bh|bt]), N=2048
    gemm_h<1,1><<<dim3(16,128,1), blk, SMEM_H>>>(
        cath, wth + OFF_Wh, nullptr, hth, HD, 2048, HD, 2048,
        0, 0, 0, bh, bt, nullptr, nullptr, 0, 0, cas_mask, 0);

    // remaining preprocessing
    tohalf_k<<<(ROWS*DT/4)/256, 256>>>(time_weight, twh);
    transpose_h_k<<<dim3(32,64,1), tb>>>(Wg,  wth + OFF_Wg,  1024, 2048, 0, 0);
    transpose_h_k<<<dim3(32,32,1), tb>>>(Wm1, wth + OFF_Wm1, 1024, 1024, 0, 0);
    transpose_h_k<<<dim3(32,2,1),  tb>>>(Wti, wth + OFF_Wti, 1024, 64,   0, 0);

    // catT[b] = transpose(cas_hidden[b]) (half) — for GEMM6's B operand
    transpose_h_k<<<dim3(32,16,32), tb>>>(
        cat, catT, 2048, 512, (long)SL * 2048, (long)HD * SL);

    // logits[b] = head_b @ tail_b^T — causal tile skip + row/col mask gates
    gemm_h<0,7><<<dim3(4,4,BSZ), blk, SMEM_H>>>(
        hth, hth + 1024, logits, nullptr, HD, 2048, 2048, SL,
        (long)SL * 2048, (long)SL * 2048, (long)SL * SL,
        nullptr, nullptr, nullptr, nullptr, 0, 0, cas_mask, SL);

    // masked causal softmax -> half scores
    attn_softmax_k<<<ROWS, 256>>>(logits, cas_mask, scoreh);

    // depend[b] = score_b @ hidden_b — row gate + causal K-trunc
    gemm_h<0,9><<<dim3(8,4,BSZ), blk, SMEM_H>>>(
        scoreh, catT, cat + 1024, cath + 1024, SL, SL, SL, 2048,
        (long)SL * SL, (long)HD * SL, (long)SL * 2048,
        nullptr, nullptr, nullptr, nullptr, 0, 0, cas_mask, SL);

    // enc = (g*h + (1-g)*d)*mask -> enc f32 + ench half
    gemm_h<3,1><<<dim3(8,128,1), blk, SMEM_H>>>(
        cath, wth + OFF_Wg, enc, ench, 2048, 2048, 2048, HD,
        0, 0, 0, bg, nullptr, cas_mask, cat, 2048, 1024, cas_mask, 0);

    // time_inf = elu(tw @ Wti + bti) -> tail f32
    gemm_h<4,1><<<dim3(8,128,1), blk, SMEM_H>>>(
        twh, wth + OFF_Wti, tail, nullptr, DT, DT, DT, HD,
        0, 0, 0, bti, nullptr, nullptr, nullptr, 0, 0, cas_mask, 0);

    // prod = elu(enc @ Wm1 + bm1) * time_inf -> head f32
    gemm_h<5,1><<<dim3(8,128,1), blk, SMEM_H>>>(
        ench, wth + OFF_Wm1, head, nullptr, HD, HD, HD, HD,
        0, 0, 0, bm1, nullptr, nullptr, tail, HD, 0, cas_mask, 0);

    // m = prod @ Wm2 + bm2
    rowdot_k<<<ROWS, 256>>>(head, Wm2, bm2, cas_mask, mvec);

    // a = masked softmax over sequence
    seq_softmax_k<<<BSZ, 512>>>(mvec, cas_mask, avec);

    // out = a * encoding (one block per row; dead rows write zeros)
    scale_k<<<ROWS, 256>>>(avec, enc, out);
}

// round 14
// speedup vs baseline: 7.2366x; 1.0626x over previous
#include <cuda_runtime.h>
#include <cuda_fp16.h>
#include <math.h>
#include <stdint.h>

// Problem constants
#define BSZ 32
#define SL  512
#define HD  1024
#define DE  1024
#define DT  64
#define ROWS (BSZ*SL)          // 16384

// ---------------- scratch (__device__ globals, alloc-free) ----------------
__device__ float  g_cat[(size_t)ROWS * 2048];     // f32: [:, :1024]=cas_hidden, [:,1024:]=depend
__device__ __half g_cath[(size_t)ROWS * 2048];    // half copy (GEMM operand)
__device__ float  g_head[(size_t)ROWS * HD];      // f32: prod (stage 9 output)
__device__ float  g_tail[(size_t)ROWS * HD];      // f32: time_inf
__device__ __half g_hth[(size_t)ROWS * 2048];     // half: [:, :1024]=head, [:,1024:]=tail
__device__ float  g_logits[(size_t)BSZ * SL * SL];
__device__ __half g_scoreh[(size_t)BSZ * SL * SL];
__device__ float  g_enc[(size_t)ROWS * HD];
__device__ __half g_ench[(size_t)ROWS * HD];
__device__ __half g_embh[(size_t)ROWS * DE];
__device__ __half g_twh[(size_t)ROWS * DT];
__device__ __half g_wth[6356992];                 // half weights (natural [K,N]), packed
__device__ float  g_m[ROWS];
__device__ float  g_a[ROWS];

// half-offsets in g_wth (all stored [K,N] row-major, NO transpose)
#define OFF_W1   0          // [1024,1024]
#define OFF_Wht  1048576    // [1024,2048] interleaved [Wh | Wt]
#define OFF_Wg   3145728    // [2048,1024]
#define OFF_Wm1  5242880    // [1024,1024]
#define OFF_Wti  6291456    // [64,1024]

__device__ __forceinline__ float eluf(float x) { return x > 0.f ? x : expm1f(x); }

__device__ __forceinline__ void mma_f16(float c[4], const uint32_t a[4], const uint32_t b[2]) {
    asm volatile(
        "mma.sync.aligned.m16n8k16.row.col.f32.f16.f16.f32 "
        "{%0,%1,%2,%3},{%4,%5,%6,%7},{%8,%9},{%0,%1,%2,%3};"
        : "+f"(c[0]), "+f"(c[1]), "+f"(c[2]), "+f"(c[3])
        : "r"(a[0]), "r"(a[1]), "r"(a[2]), "r"(a[3]), "r"(b[0]), "r"(b[1]));
}
#define LDSM4(r0, r1, r2, r3, addr) \
    asm volatile("ldmatrix.sync.aligned.m8n8.x4.shared.b16 {%0,%1,%2,%3}, [%4];" \
                 : "=r"(r0), "=r"(r1), "=r"(r2), "=r"(r3) : "r"(addr))
#define LDSM4T(r0, r1, r2, r3, addr) \
    asm volatile("ldmatrix.sync.aligned.m8n8.x4.trans.shared.b16 {%0,%1,%2,%3}, [%4];" \
                 : "=r"(r0), "=r"(r1), "=r"(r2), "=r"(r3) : "r"(addr))
#define CP16(dst, src) \
    asm volatile("cp.async.cg.shared.global [%0], [%1], 16;" :: "r"(dst), "l"(src))
#define CP_COMMIT asm volatile("cp.async.commit_group;")
#define CP_WAIT2  asm volatile("cp.async.wait_group 2;" ::: "memory")

// ---------------------------------------------------------------------------
// fp16 tensor-core GEMM.
//  BNN=false: C = epi(A[M,K] @ B[N,K]^T)  (B row-major [N,K], NT)
//  BNN=true : C = epi(A[M,K] @ B[K,N])    (B row-major [K,N], NN via ldmatrix.trans)
// CTA tile 128x128, BK=64, 3-stage cp.async, 8 warps (2x4). 2 CTAs/SM.
// EPI: 0=none, 1=bias, 2=elu*rowmask, 3=sigmoid-gate-blend, 4=elu, 5=elu*aux
// CM: 1=row-tile mask gate, 2=col-tile gate, 4=causal tile skip, 8=causal K-trunc
// bias2: second bias for fused N=2048 outputs (cols >= 1024).
// ---------------------------------------------------------------------------
template<int EPI, int CM, bool BNN>
__global__ __launch_bounds__(256, 2)
void gemm_h(const __half* __restrict__ A, const __half* __restrict__ B,
            float* __restrict__ C, __half* __restrict__ C2,
            int K, int lda, int ldb, int ldc,
            long sA, long sB, long sC,
            const float* __restrict__ bias, const float* __restrict__ bias2,
            const float* __restrict__ rowmask,
            const float* __restrict__ aux, int auxld, int auxoff,
            const float* __restrict__ gmask, int mstride)
{
    const int z = blockIdx.z;
    const int row0 = blockIdx.y * 128;
    const int col0 = blockIdx.x * 128;

    if (CM & 4) { if (blockIdx.x > blockIdx.y) return; }
    if (CM & 1) { if (gmask[(size_t)z * mstride + row0] == 0.f) return; }
    if (CM & 2) { if (gmask[(size_t)z * mstride + col0] == 0.f) return; }

    constexpr int STAGE_B = 2 * 128 * 144;      // A tile (128x144B) + B region
    extern __shared__ char smem[];
    uint32_t sb;
    asm("{ .reg .u64 t; cvta.to.shared.u64 t, %1; cvt.u32.u64 %0, t; }" : "=r"(sb) : "l"(smem));

    A += (size_t)z * sA;
    B += (size_t)z * sB;

    const int tid = threadIdx.x, lane = tid & 31, wid = tid >> 5;
    const int wr = wid >> 2, wc = wid & 3;
    const int group = lane >> 2, tig = lane & 3;

    float acc[4][4][4];
#pragma unroll
    for (int i = 0; i < 4; i++)
#pragma unroll
        for (int j = 0; j < 4; j++)
#pragma unroll
            for (int c = 0; c < 4; c++) acc[i][j][c] = 0.f;

    auto load = [&](int s, int kt) {
        const int k0 = kt << 6;
        const uint32_t ab = sb + s * STAGE_B;
        const uint32_t bb = ab + 128 * 144;
#pragma unroll
        for (int p = 0; p < 4; p++) {
            int idx = tid + (p << 8);
            // A: 128 rows x 64 halves (128B), stride 144
            int r = idx >> 3;
            int c8 = (idx & 7) << 3;
            CP16(ab + r * 144 + (c8 << 1), A + (size_t)(row0 + r) * lda + k0 + c8);
            if (BNN) {
                // B: 64 k-rows x 128 halves (256B), stride 272
                int br = idx >> 4;               // 0..63
                int bc16 = (idx & 15) << 4;      // byte col 0..240
                CP16(bb + br * 272 + bc16, B + (size_t)(k0 + br) * ldb + col0 + (bc16 >> 1));
            } else {
                // B: 128 n-rows x 64 halves, stride 144
                CP16(bb + r * 144 + (c8 << 1), B + (size_t)(col0 + r) * ldb + k0 + c8);
            }
        }
    };

    const int Keff = (CM & 8) ? ((row0 + 128 < K) ? row0 + 128 : K) : K;
    const int nt = Keff >> 6;                   // BK = 64

    // 3-stage prologue: always exactly 2 commit groups
    load(0, 0); CP_COMMIT;
    if (nt > 1) load(1, 1);
    CP_COMMIT;

    for (int t = 0; t < nt; t++) {
        if (t + 2 < nt) load((t + 2) % 3, t + 2);
        CP_COMMIT;                               // one group per iter (may be empty)
        CP_WAIT2;                                // tile t's group drained
        __syncthreads();

        const uint32_t ab = sb + (t % 3) * STAGE_B;
        const uint32_t bb = ab + 128 * 144;
        const uint32_t koff = ((lane >> 4) << 4);
        const int rsel = lane & 15;

#pragma unroll
        for (int kk4 = 0; kk4 < 4; kk4++) {
            uint32_t af[4][4];
            {
                const uint32_t kb = (kk4 << 5) + koff;
#pragma unroll
                for (int mf = 0; mf < 4; mf++) {
                    uint32_t addr = ab + (uint32_t)(wr * 64 + mf * 16 + rsel) * 144 + kb;
                    LDSM4(af[mf][0], af[mf][1], af[mf][2], af[mf][3], addr);
                }
            }
            uint32_t bf[4][2];
#pragma unroll
            for (int g = 0; g < 2; g++) {
                uint32_t r0, r1, r2, r3;
                if (BNN) {
                    // k-rows: kk4*16 + (lane&7) + 8*(lane>=16); n-col: +8 for lanes 8-15/24-31
                    uint32_t addr = bb
                        + (uint32_t)(kk4 * 16 + (lane & 7) + ((lane >> 4) << 3)) * 272
                        + (uint32_t)(wc * 32 + g * 16 + ((lane >> 3) & 1) * 8) * 2;
                    LDSM4T(r0, r1, r2, r3, addr);
                } else {
                    const uint32_t kb = (kk4 << 5) + koff;
                    uint32_t addr = bb + (uint32_t)(wc * 32 + g * 16 + rsel) * 144 + kb;
                    LDSM4(r0, r1, r2, r3, addr);
                }
                bf[2 * g][0] = r0; bf[2 * g][1] = r2;
                bf[2 * g + 1][0] = r1; bf[2 * g + 1][1] = r3;
            }
#pragma unroll
            for (int mf = 0; mf < 4; mf++)
#pragma unroll
                for (int nf = 0; nf < 4; nf++)
                    mma_f16(acc[mf][nf], af[mf], bf[nf]);
        }
        __syncthreads();
    }

    // ---- fused epilogue ----
#pragma unroll
    for (int mf = 0; mf < 4; mf++) {
        int rbase = row0 + wr * 64 + mf * 16 + group;
#pragma unroll
        for (int half = 0; half < 2; half++) {
            int m = rbase + half * 8;
            float rm = 1.f;
            if (EPI == 2 || EPI == 3) rm = rowmask[m];
#pragma unroll
            for (int nf = 0; nf < 4; nf++) {
                int n = col0 + wc * 32 + nf * 8 + 2 * tig;
                float v0 = acc[mf][nf][half * 2 + 0];
                float v1 = acc[mf][nf][half * 2 + 1];
                if (EPI != 0) {
                    const float* bp = (bias2 && n >= 1024) ? bias2 - 1024 : bias;
                    v0 += bp[n]; v1 += bp[n + 1];
                }
                if (EPI == 2) {
                    v0 = eluf(v0) * rm;
                    v1 = eluf(v1) * rm;
                } else if (EPI == 3) {
                    float2 h = *(const float2*)&aux[(size_t)m * auxld + n];
                    float2 d = *(const float2*)&aux[(size_t)m * auxld + n + auxoff];
                    float g0 = 1.f / (1.f + expf(-v0));
                    float g1 = 1.f / (1.f + expf(-v1));
                    v0 = (g0 * h.x + (1.f - g0) * d.x) * rm;
                    v1 = (g1 * h.y + (1.f - g1) * d.y) * rm;
                } else if (EPI == 4) {
                    v0 = eluf(v0);
                    v1 = eluf(v1);
                } else if (EPI == 5) {
                    float2 ax = *(const float2*)&aux[(size_t)m * auxld + n];
                    v0 = eluf(v0) * ax.x;
                    v1 = eluf(v1) * ax.y;
                }
                size_t off = (size_t)z * sC + (size_t)m * ldc + n;
                if (C)  *(float2*)&C[off] = make_float2(v0, v1);
                if (C2) *(__half2*)&C2[off] = __floats2half2_rn(v0, v1);
            }
        }
    }
}

// ---------------------------------------------------------------------------
// One-shot preprocessing: convert all f32 inputs to half (no transposes).
// Job ranges by blockIdx.x (each thread handles one float4 = 4 elements).
//  [0,16384)        emb -> embh
//  [16384,17408)    tw  -> twh
//  [17408,18432)    W1  -> wth+OFF_W1
//  [18432,19456)    Wh  -> wth+OFF_Wht, interleaved cols 0-1023
//  [19456,20480)    Wt  -> wth+OFF_Wht, interleaved cols 1024-2047
//  [20480,22528)    Wg  -> wth+OFF_Wg
//  [22528,23552)    Wm1 -> wth+OFF_Wm1
//  [23552,23616)    Wti -> wth+OFF_Wti
__global__ void prep_k(const float* __restrict__ emb, const float* __restrict__ tw,
                       const float* __restrict__ W1, const float* __restrict__ Wh,
                       const float* __restrict__ Wt, const float* __restrict__ Wg,
                       const float* __restrict__ Wm1, const float* __restrict__ Wti,
                       __half* __restrict__ embh, __half* __restrict__ twh,
                       __half* __restrict__ wth)
{
    int b = blockIdx.x;
    const float* src;
    __half* dst;
    size_t i;         // f4 index within job
    bool ilv = false; // Wh/Wt interleave
    size_t ilvoff = 0;

    if (b < 16384)      { src = emb; dst = embh;            i = (size_t)b * 256 + threadIdx.x; }
    else if (b < 17408) { src = tw;  dst = twh;             i = (size_t)(b - 16384) * 256 + threadIdx.x; }
    else if (b < 18432) { src = W1;  dst = wth + OFF_W1;    i = (size_t)(b - 17408) * 256 + threadIdx.x; }
    else if (b < 19456) { src = Wh;  dst = wth + OFF_Wht;   i = (size_t)(b - 18432) * 256 + threadIdx.x; ilv = true; ilvoff = 0; }
    else if (b < 20480) { src = Wt;  dst = wth + OFF_Wht;   i = (size_t)(b - 19456) * 256 + threadIdx.x; ilv = true; ilvoff = 1024; }
    else if (b < 22528) { src = Wg;  dst = wth + OFF_Wg;    i = (size_t)(b - 20480) * 256 + threadIdx.x; }
    else if (b < 23552) { src = Wm1; dst = wth + OFF_Wm1;   i = (size_t)(b - 22528) * 256 + threadIdx.x; }
    else                { src = Wti; dst = wth + OFF_Wti;   i = (size_t)(b - 23552) * 256 + threadIdx.x; }

    float4 v = ((const float4*)src)[i];
    __half2 h0 = __floats2half2_rn(v.x, v.y);
    __half2 h1 = __floats2half2_rn(v.z, v.w);
    size_t e = i * 4;
    if (ilv) {
        size_t k = e >> 10, n = e & 1023;
        e = k * 2048 + ilvoff + n;
    }
    *(__half2*)(dst + e)     = h0;
    *(__half2*)(dst + e + 2) = h1;
}

// ---------------------------------------------------------------------------
__device__ __forceinline__ float blockReduce(float v, bool isMax)
{
    __shared__ float sh[32];
    int lane = threadIdx.x & 31;
    int w = threadIdx.x >> 5;
    int nw = blockDim.x >> 5;
#pragma unroll
    for (int o = 16; o; o >>= 1) {
        float u = __shfl_xor_sync(0xffffffffu, v, o);
        v = isMax ? fmaxf(v, u) : v + u;
    }
    if (lane == 0) sh[w] = v;
    __syncthreads();
    if (w == 0) {
        v = (lane < nw) ? sh[lane] : (isMax ? -INFINITY : 0.f);
#pragma unroll
        for (int o = 16; o; o >>= 1) {
            float u = __shfl_xor_sync(0xffffffffu, v, o);
            v = isMax ? fmaxf(v, u) : v + u;
        }
        if (lane == 0) sh[0] = v;
    }
    __syncthreads();
    v = sh[0];
    __syncthreads();
    return v;
}

// Masked causal softmax: f32 logits -> half scores. 256 thr/row.
__global__ void attn_softmax_k(const float* __restrict__ logits,
                               const float* __restrict__ mask,
                               __half* __restrict__ score)
{
    int row = blockIdx.x;
    int b = row >> 9;
    int i = row & 511;
    const float* mrow = mask + ((size_t)b << 9);
    if (mrow[i] == 0.f) return;
    const float* L = logits + ((size_t)row << 9);
    __half* S = score + ((size_t)row << 9);
    int t = threadIdx.x;
    int j0 = t, j1 = t + 256;
    bool a0 = (i > j0) && (mrow[j0] > 0.f);
    bool a1 = (i > j1) && (mrow[j1] > 0.f);
    float x0 = L[j0] + (a0 ? 0.f : -1e30f);
    float x1 = L[j1] + (a1 ? 0.f : -1e30f);
    float mx = blockReduce(fmaxf(x0, x1), true);
    float e0 = expf(x0 - mx);
    float e1 = expf(x1 - mx);
    float s = blockReduce(e0 + e1, false);
    float inv = 1.f / s;
    S[j0] = __float2half_rn(a0 ? e0 * inv : 0.f);
    S[j1] = __float2half_rn(a1 ? e1 * inv : 0.f);
}

// m[row] = dot(prod[row,:], Wm2) + bm2 — one warp per row.
__global__ void rowdot_k(const float* __restrict__ prod, const float* __restrict__ w,
                         const float* __restrict__ b, const float* __restrict__ mask,
                         float* __restrict__ m)
{
    int row = blockIdx.x * 8 + (threadIdx.x >> 5);
    int lane = threadIdx.x & 31;
    if (mask[row] == 0.f) { if (lane == 0) m[row] = 0.f; return; }
    const float4* p = (const float4*)(prod + ((size_t)row << 10));
    const float4* wv = (const float4*)w;
    float s = 0.f;
#pragma unroll
    for (int h = lane; h < 256; h += 32) {
        float4 a = p[h], c = wv[h];
        s = fmaf(a.x, c.x, fmaf(a.y, c.y, fmaf(a.z, c.z, fmaf(a.w, c.w, s))));
    }
#pragma unroll
    for (int o = 16; o; o >>= 1) s += __shfl_xor_sync(0xffffffffu, s, o);
    if (lane == 0) m[row] = s + b[0];
}

// Per-batch masked softmax along sequence. 512 thr/batch.
__global__ void seq_softmax_k(const float* m, const float* mask, float* a)
{
    int b = blockIdx.x;
    int t = threadIdx.x;
    size_t idx = ((size_t)b << 9) + t;
    float msk = mask[idx];
    float x = m[idx] + (msk > 0.f ? 0.f : -1e30f);
    float mx = blockReduce(x, true);
    float e = expf(x - mx);
    float s = blockReduce(e, false);
    a[idx] = (msk > 0.f) ? e / s : 0.f;
}

// out = a[row] * encoding. One block = one row. Dead rows: write zeros.
__global__ void scale_k(const float* a, const float* enc, float* out)
{
    int row = blockIdx.x;
    float s = a[row];
    size_t i = ((size_t)row << 8) + threadIdx.x;   // float4 index
    if (s == 0.f) {
        ((float4*)out)[i] = make_float4(0.f, 0.f, 0.f, 0.f);
        return;
    }
    float4 e = ((const float4*)enc)[i];
    float4 o;
    o.x = e.x * s; o.y = e.y * s; o.z = e.z * s; o.w = e.w * s;
    ((float4*)out)[i] = o;
}

static const int SMEM_H = 3 * 2 * 128 * 144;   // 110592

extern "C" void kernel_launch(void* const* d_in, const int* in_sizes, int n_in,
                              void* d_out, int out_size)
{
    const float* cas_emb     = (const float*)d_in[0];
    const float* cas_mask    = (const float*)d_in[1];
    const float* time_weight = (const float*)d_in[2];
    const float* W1  = (const float*)d_in[3];
    const float* b1  = (const float*)d_in[4];
    const float* Wh  = (const float*)d_in[5];
    const float* bh  = (const float*)d_in[6];
    const float* Wt  = (const float*)d_in[7];
    const float* bt  = (const float*)d_in[8];
    const float* Wg  = (const float*)d_in[9];
    const float* bg  = (const float*)d_in[10];
    const float* Wm1 = (const float*)d_in[11];
    const float* bm1 = (const float*)d_in[12];
    const float* Wti = (const float*)d_in[13];
    const float* bti = (const float*)d_in[14];
    const float* Wm2 = (const float*)d_in[15];
    const float* bm2 = (const float*)d_in[16];
    float* out = (float*)d_out;

    float  *cat, *head, *tail, *logits, *enc, *mvec, *avec;
    __half *cath, *hth, *scoreh, *ench, *embh, *twh, *wth;
    cudaGetSymbolAddress((void**)&cat,    g_cat);
    cudaGetSymbolAddress((void**)&cath,   g_cath);
    cudaGetSymbolAddress((void**)&head,   g_head);
    cudaGetSymbolAddress((void**)&tail,   g_tail);
    cudaGetSymbolAddress((void**)&hth,    g_hth);
    cudaGetSymbolAddress((void**)&logits, g_logits);
    cudaGetSymbolAddress((void**)&scoreh, g_scoreh);
    cudaGetSymbolAddress((void**)&enc,    g_enc);
    cudaGetSymbolAddress((void**)&ench,   g_ench);
    cudaGetSymbolAddress((void**)&embh,   g_embh);
    cudaGetSymbolAddress((void**)&twh,    g_twh);
    cudaGetSymbolAddress((void**)&wth,    g_wth);
    cudaGetSymbolAddress((void**)&mvec,   g_m);
    cudaGetSymbolAddress((void**)&avec,   g_a);

    cudaFuncSetAttribute(gemm_h<0,7,false>, cudaFuncAttributeMaxDynamicSharedMemorySize, SMEM_H);
    cudaFuncSetAttribute(gemm_h<0,9,true >, cudaFuncAttributeMaxDynamicSharedMemorySize, SMEM_H);
    cudaFuncSetAttribute(gemm_h<1,1,true >, cudaFuncAttributeMaxDynamicSharedMemorySize, SMEM_H);
    cudaFuncSetAttribute(gemm_h<2,1,true >, cudaFuncAttributeMaxDynamicSharedMemorySize, SMEM_H);
    cudaFuncSetAttribute(gemm_h<3,1,true >, cudaFuncAttributeMaxDynamicSharedMemorySize, SMEM_H);
    cudaFuncSetAttribute(gemm_h<4,1,true >, cudaFuncAttributeMaxDynamicSharedMemorySize, SMEM_H);
    cudaFuncSetAttribute(gemm_h<5,1,true >, cudaFuncAttributeMaxDynamicSharedMemorySize, SMEM_H);

    dim3 blk(256);

    // 1) one-shot preprocessing: all f32->f16 converts (no transposes)
    prep_k<<<23616, 256>>>(cas_emb, time_weight, W1, Wh, Wt, Wg, Wm1, Wti,
                           embh, twh, wth);

    // 2) cas_hidden = elu(emb @ W1 + b1)*mask -> cat f32 + cath half  [NN]
    gemm_h<2,1,true><<<dim3(8,128,1), blk, SMEM_H>>>(
        embh, wth + OFF_W1, cat, cath, DE, DE, HD, 2048,
        0, 0, 0, b1, nullptr, cas_mask, nullptr, 0, 0, cas_mask, 0);

    // 3) fused head|tail: hth = half(cas_hidden @ [Wh|Wt] + [bh|bt])  [NN, N=2048]
    gemm_h<1,1,true><<<dim3(16,128,1), blk, SMEM_H>>>(
        cath, wth + OFF_Wht, nullptr, hth, HD, 2048, 2048, 2048,
        0, 0, 0, bh, bt, nullptr, nullptr, 0, 0, cas_mask, 0);

    // 4) logits[b] = head_b @ tail_b^T  [NT] — causal skip + row/col gates
    gemm_h<0,7,false><<<dim3(4,4,BSZ), blk, SMEM_H>>>(
        hth, hth + 1024, logits, nullptr, HD, 2048, 2048, SL,
        (long)SL * 2048, (long)SL * 2048, (long)SL * SL,
        nullptr, nullptr, nullptr, nullptr, 0, 0, cas_mask, SL);

    // 5) masked causal softmax -> half scores
    attn_softmax_k<<<ROWS, 256>>>(logits, cas_mask, scoreh);

    // 6) depend[b] = score_b @ hidden_b  [NN, B=cath] — row gate + K-trunc
    gemm_h<0,9,true><<<dim3(8,4,BSZ), blk, SMEM_H>>>(
        scoreh, cath, cat + 1024, cath + 1024, SL, SL, 2048, 2048,
        (long)SL * SL, (long)SL * 2048, (long)SL * 2048,
        nullptr, nullptr, nullptr, nullptr, 0, 0, cas_mask, SL);

    // 7) enc = (g*h + (1-g)*d)*mask -> enc f32 + ench half  [NN, Wg]
    gemm_h<3,1,true><<<dim3(8,128,1), blk, SMEM_H>>>(
        cath, wth + OFF_Wg, enc, ench, 2048, 2048, HD, HD,
        0, 0, 0, bg, nullptr, cas_mask, cat, 2048, 1024, cas_mask, 0);

    // 8) time_inf = elu(tw @ Wti + bti) -> tail f32  [NN]
    gemm_h<4,1,true><<<dim3(8,128,1), blk, SMEM_H>>>(
        twh, wth + OFF_Wti, tail, nullptr, DT, DT, HD, HD,
        0, 0, 0, bti, nullptr, nullptr, nullptr, 0, 0, cas_mask, 0);

    // 9) prod = elu(enc @ Wm1 + bm1) * time_inf -> head f32  [NN]
    gemm_h<5,1,true><<<dim3(8,128,1), blk, SMEM_H>>>(
        ench, wth + OFF_Wm1, head, nullptr, HD, HD, HD, HD,
        0, 0, 0, bm1, nullptr, nullptr, tail, HD, 0, cas_mask, 0);

    // 10) m = prod @ Wm2 + bm2 (warp per row)
    rowdot_k<<<ROWS / 8, 256>>>(head, Wm2, bm2, cas_mask, mvec);

    // 11) a = masked softmax over sequence
    seq_softmax_k<<<BSZ, 512>>>(mvec, cas_mask, avec);

    // 12) out = a * encoding
    scale_k<<<ROWS, 256>>>(avec, enc, out);
}

// round 15
// speedup vs baseline: 7.2678x; 1.0043x over previous
#include <cuda_runtime.h>
#include <cuda_fp16.h>
#include <math.h>
#include <stdint.h>

// Problem constants
#define BSZ 32
#define SL  512
#define HD  1024
#define DE  1024
#define DT  64
#define ROWS (BSZ*SL)          // 16384

// ---------------- scratch (__device__ globals, alloc-free) ----------------
__device__ float  g_cat[(size_t)ROWS * 2048];     // f32: [:, :1024]=cas_hidden, [:,1024:]=depend
__device__ __half g_cath[(size_t)ROWS * 2048];    // half copy (GEMM operand)
__device__ float  g_head[(size_t)ROWS * HD];      // f32: prod (stage 9 output)
__device__ float  g_tail[(size_t)ROWS * HD];      // f32: time_inf
__device__ __half g_hth[(size_t)ROWS * 2048];     // half: [:, :1024]=head, [:,1024:]=tail
__device__ float  g_logits[(size_t)BSZ * SL * SL];
__device__ __half g_scoreh[(size_t)BSZ * SL * SL];
__device__ float  g_enc[(size_t)ROWS * HD];
__device__ __half g_ench[(size_t)ROWS * HD];
__device__ __half g_embh[(size_t)ROWS * DE];
__device__ __half g_twh[(size_t)ROWS * DT];
__device__ __half g_wth[6356992];                 // half weights (natural [K,N]), packed
__device__ float  g_m[ROWS];
__device__ float  g_a[ROWS];

// half-offsets in g_wth (all stored [K,N] row-major, NO transpose)
#define OFF_W1   0          // [1024,1024]
#define OFF_Wht  1048576    // [1024,2048] interleaved [Wh | Wt]
#define OFF_Wg   3145728    // [2048,1024]
#define OFF_Wm1  5242880    // [1024,1024]
#define OFF_Wti  6291456    // [64,1024]

__device__ __forceinline__ float eluf(float x) { return x > 0.f ? x : expm1f(x); }

__device__ __forceinline__ void mma_f16(float c[4], const uint32_t a[4], const uint32_t b[2]) {
    asm volatile(
        "mma.sync.aligned.m16n8k16.row.col.f32.f16.f16.f32 "
        "{%0,%1,%2,%3},{%4,%5,%6,%7},{%8,%9},{%0,%1,%2,%3};"
        : "+f"(c[0]), "+f"(c[1]), "+f"(c[2]), "+f"(c[3])
        : "r"(a[0]), "r"(a[1]), "r"(a[2]), "r"(a[3]), "r"(b[0]), "r"(b[1]));
}
#define LDSM4(r0, r1, r2, r3, addr) \
    asm volatile("ldmatrix.sync.aligned.m8n8.x4.shared.b16 {%0,%1,%2,%3}, [%4];" \
                 : "=r"(r0), "=r"(r1), "=r"(r2), "=r"(r3) : "r"(addr))
#define LDSM4T(r0, r1, r2, r3, addr) \
    asm volatile("ldmatrix.sync.aligned.m8n8.x4.trans.shared.b16 {%0,%1,%2,%3}, [%4];" \
                 : "=r"(r0), "=r"(r1), "=r"(r2), "=r"(r3) : "r"(addr))
#define CP16(dst, src) \
    asm volatile("cp.async.cg.shared.global [%0], [%1], 16;" :: "r"(dst), "l"(src))
#define CP_COMMIT asm volatile("cp.async.commit_group;")
#define CP_WAIT2  asm volatile("cp.async.wait_group 2;" ::: "memory")

// ---------------------------------------------------------------------------
// fp16 tensor-core GEMM, 512 threads (16 warps, 4x4 grid, 32x32 warp tile).
//  BNN=false: C = epi(A[M,K] @ B[N,K]^T)  (B row-major [N,K], NT)
//  BNN=true : C = epi(A[M,K] @ B[K,N])    (B row-major [K,N], NN via ldmatrix.trans)
// CTA tile 128x128, BK=64, 3-stage cp.async. 2 CTAs/SM -> 32 warps resident.
// EPI: 0=none, 1=bias, 2=elu*rowmask, 3=sigmoid-gate-blend, 4=elu, 5=elu*aux
// CM: 1=row-tile mask gate, 2=col-tile gate, 4=causal tile skip, 8=causal K-trunc
// bias2: second bias for fused N=2048 outputs (cols >= 1024).
// ---------------------------------------------------------------------------
template<int EPI, int CM, bool BNN>
__global__ __launch_bounds__(512, 2)
void gemm_h(const __half* __restrict__ A, const __half* __restrict__ B,
            float* __restrict__ C, __half* __restrict__ C2,
            int K, int lda, int ldb, int ldc,
            long sA, long sB, long sC,
            const float* __restrict__ bias, const float* __restrict__ bias2,
            const float* __restrict__ rowmask,
            const float* __restrict__ aux, int auxld, int auxoff,
            const float* __restrict__ gmask, int mstride)
{
    const int z = blockIdx.z;
    const int row0 = blockIdx.y * 128;
    const int col0 = blockIdx.x * 128;

    if (CM & 4) { if (blockIdx.x > blockIdx.y) return; }
    if (CM & 1) { if (gmask[(size_t)z * mstride + row0] == 0.f) return; }
    if (CM & 2) { if (gmask[(size_t)z * mstride + col0] == 0.f) return; }

    constexpr int STAGE_B = 2 * 128 * 144;      // A tile (128x144B) + B region
    extern __shared__ char smem[];
    uint32_t sb;
    asm("{ .reg .u64 t; cvta.to.shared.u64 t, %1; cvt.u32.u64 %0, t; }" : "=r"(sb) : "l"(smem));

    A += (size_t)z * sA;
    B += (size_t)z * sB;

    const int tid = threadIdx.x, lane = tid & 31, wid = tid >> 5;
    const int wr = wid >> 2, wc = wid & 3;      // 4x4 warp grid
    const int group = lane >> 2, tig = lane & 3;

    float acc[2][4][4];
#pragma unroll
    for (int i = 0; i < 2; i++)
#pragma unroll
        for (int j = 0; j < 4; j++)
#pragma unroll
            for (int c = 0; c < 4; c++) acc[i][j][c] = 0.f;

    auto load = [&](int s, int kt) {
        const int k0 = kt << 6;
        const uint32_t ab = sb + s * STAGE_B;
        const uint32_t bb = ab + 128 * 144;
#pragma unroll
        for (int p = 0; p < 2; p++) {
            int idx = tid + (p << 9);            // 0..1023
            // A: 128 rows x 64 halves (128B), stride 144
            int r = idx >> 3;
            int c8 = (idx & 7) << 3;
            CP16(ab + r * 144 + (c8 << 1), A + (size_t)(row0 + r) * lda + k0 + c8);
            if (BNN) {
                // B: 64 k-rows x 128 halves (256B), stride 272
                int br = idx >> 4;               // 0..63
                int bc16 = (idx & 15) << 4;      // byte col 0..240
                CP16(bb + br * 272 + bc16, B + (size_t)(k0 + br) * ldb + col0 + (bc16 >> 1));
            } else {
                // B: 128 n-rows x 64 halves, stride 144
                CP16(bb + r * 144 + (c8 << 1), B + (size_t)(col0 + r) * ldb + k0 + c8);
            }
        }
    };

    const int Keff = (CM & 8) ? ((row0 + 128 < K) ? row0 + 128 : K) : K;
    const int nt = Keff >> 6;                   // BK = 64

    // 3-stage prologue: always exactly 2 commit groups
    load(0, 0); CP_COMMIT;
    if (nt > 1) load(1, 1);
    CP_COMMIT;

    for (int t = 0; t < nt; t++) {
        if (t + 2 < nt) load((t + 2) % 3, t + 2);
        CP_COMMIT;                               // one group per iter (may be empty)
        CP_WAIT2;                                // tile t's group drained
        __syncthreads();

        const uint32_t ab = sb + (t % 3) * STAGE_B;
        const uint32_t bb = ab + 128 * 144;
        const uint32_t koff = ((lane >> 4) << 4);
        const int rsel = lane & 15;

#pragma unroll
        for (int kk4 = 0; kk4 < 4; kk4++) {
            uint32_t af[2][4];
            {
                const uint32_t kb = (kk4 << 5) + koff;
#pragma unroll
                for (int mf = 0; mf < 2; mf++) {
                    uint32_t addr = ab + (uint32_t)(wr * 32 + mf * 16 + rsel) * 144 + kb;
                    LDSM4(af[mf][0], af[mf][1], af[mf][2], af[mf][3], addr);
                }
            }
            uint32_t bf[4][2];
#pragma unroll
            for (int g = 0; g < 2; g++) {
                uint32_t r0, r1, r2, r3;
                if (BNN) {
                    uint32_t addr = bb
                        + (uint32_t)(kk4 * 16 + (lane & 7) + ((lane >> 4) << 3)) * 272
                        + (uint32_t)(wc * 32 + g * 16 + ((lane >> 3) & 1) * 8) * 2;
                    LDSM4T(r0, r1, r2, r3, addr);
                } else {
                    const uint32_t kb = (kk4 << 5) + koff;
                    uint32_t addr = bb + (uint32_t)(wc * 32 + g * 16 + rsel) * 144 + kb;
                    LDSM4(r0, r1, r2, r3, addr);
                }
                bf[2 * g][0] = r0; bf[2 * g][1] = r2;
                bf[2 * g + 1][0] = r1; bf[2 * g + 1][1] = r3;
            }
#pragma unroll
            for (int mf = 0; mf < 2; mf++)
#pragma unroll
                for (int nf = 0; nf < 4; nf++)
                    mma_f16(acc[mf][nf], af[mf], bf[nf]);
        }
        __syncthreads();
    }

    // ---- fused epilogue ----
#pragma unroll
    for (int mf = 0; mf < 2; mf++) {
        int rbase = row0 + wr * 32 + mf * 16 + group;
#pragma unroll
        for (int half = 0; half < 2; half++) {
            int m = rbase + half * 8;
            float rm = 1.f;
            if (EPI == 2 || EPI == 3) rm = rowmask[m];
#pragma unroll
            for (int nf = 0; nf < 4; nf++) {
                int n = col0 + wc * 32 + nf * 8 + 2 * tig;
                float v0 = acc[mf][nf][half * 2 + 0];
                float v1 = acc[mf][nf][half * 2 + 1];
                if (EPI != 0) {
                    const float* bp = (bias2 && n >= 1024) ? bias2 - 1024 : bias;
                    v0 += bp[n]; v1 += bp[n + 1];
                }
                if (EPI == 2) {
                    v0 = eluf(v0) * rm;
                    v1 = eluf(v1) * rm;
                } else if (EPI == 3) {
                    float2 h = *(const float2*)&aux[(size_t)m * auxld + n];
                    float2 d = *(const float2*)&aux[(size_t)m * auxld + n + auxoff];
                    float g0 = 1.f / (1.f + expf(-v0));
                    float g1 = 1.f / (1.f + expf(-v1));
                    v0 = (g0 * h.x + (1.f - g0) * d.x) * rm;
                    v1 = (g1 * h.y + (1.f - g1) * d.y) * rm;
                } else if (EPI == 4) {
                    v0 = eluf(v0);
                    v1 = eluf(v1);
                } else if (EPI == 5) {
                    float2 ax = *(const float2*)&aux[(size_t)m * auxld + n];
                    v0 = eluf(v0) * ax.x;
                    v1 = eluf(v1) * ax.y;
                }
                size_t off = (size_t)z * sC + (size_t)m * ldc + n;
                if (C)  *(float2*)&C[off] = make_float2(v0, v1);
                if (C2) *(__half2*)&C2[off] = __floats2half2_rn(v0, v1);
            }
        }
    }
}

// ---------------------------------------------------------------------------
// One-shot preprocessing: convert all f32 inputs to half (no transposes).
__global__ void prep_k(const float* __restrict__ emb, const float* __restrict__ tw,
                       const float* __restrict__ W1, const float* __restrict__ Wh,
                       const float* __restrict__ Wt, const float* __restrict__ Wg,
                       const float* __restrict__ Wm1, const float* __restrict__ Wti,
                       __half* __restrict__ embh, __half* __restrict__ twh,
                       __half* __restrict__ wth)
{
    int b = blockIdx.x;
    const float* src;
    __half* dst;
    size_t i;         // f4 index within job
    bool ilv = false; // Wh/Wt interleave
    size_t ilvoff = 0;

    if (b < 16384)      { src = emb; dst = embh;            i = (size_t)b * 256 + threadIdx.x; }
    else if (b < 17408) { src = tw;  dst = twh;             i = (size_t)(b - 16384) * 256 + threadIdx.x; }
    else if (b < 18432) { src = W1;  dst = wth + OFF_W1;    i = (size_t)(b - 17408) * 256 + threadIdx.x; }
    else if (b < 19456) { src = Wh;  dst = wth + OFF_Wht;   i = (size_t)(b - 18432) * 256 + threadIdx.x; ilv = true; ilvoff = 0; }
    else if (b < 20480) { src = Wt;  dst = wth + OFF_Wht;   i = (size_t)(b - 19456) * 256 + threadIdx.x; ilv = true; ilvoff = 1024; }
    else if (b < 22528) { src = Wg;  dst = wth + OFF_Wg;    i = (size_t)(b - 20480) * 256 + threadIdx.x; }
    else if (b < 23552) { src = Wm1; dst = wth + OFF_Wm1;   i = (size_t)(b - 22528) * 256 + threadIdx.x; }
    else                { src = Wti; dst = wth + OFF_Wti;   i = (size_t)(b - 23552) * 256 + threadIdx.x; }

    float4 v = ((const float4*)src)[i];
    __half2 h0 = __floats2half2_rn(v.x, v.y);
    __half2 h1 = __floats2half2_rn(v.z, v.w);
    size_t e = i * 4;
    if (ilv) {
        size_t k = e >> 10, n = e & 1023;
        e = k * 2048 + ilvoff + n;
    }
    *(__half2*)(dst + e)     = h0;
    *(__half2*)(dst + e + 2) = h1;
}

// ---------------------------------------------------------------------------
__device__ __forceinline__ float blockReduce(float v, bool isMax)
{
    __shared__ float sh[32];
    int lane = threadIdx.x & 31;
    int w = threadIdx.x >> 5;
    int nw = blockDim.x >> 5;
#pragma unroll
    for (int o = 16; o; o >>= 1) {
        float u = __shfl_xor_sync(0xffffffffu, v, o);
        v = isMax ? fmaxf(v, u) : v + u;
    }
    if (lane == 0) sh[w] = v;
    __syncthreads();
    if (w == 0) {
        v = (lane < nw) ? sh[lane] : (isMax ? -INFINITY : 0.f);
#pragma unroll
        for (int o = 16; o; o >>= 1) {
            float u = __shfl_xor_sync(0xffffffffu, v, o);
            v = isMax ? fmaxf(v, u) : v + u;
        }
        if (lane == 0) sh[0] = v;
    }
    __syncthreads();
    v = sh[0];
    __syncthreads();
    return v;
}

// Masked causal softmax: f32 logits -> half scores. 256 thr/row.
__global__ void attn_softmax_k(const float* __restrict__ logits,
                               const float* __restrict__ mask,
                               __half* __restrict__ score)
{
    int row = blockIdx.x;
    int b = row >> 9;
    int i = row & 511;
    const float* mrow = mask + ((size_t)b << 9);
    if (mrow[i] == 0.f) return;
    const float* L = logits + ((size_t)row << 9);
    __half* S = score + ((size_t)row << 9);
    int t = threadIdx.x;
    int j0 = t, j1 = t + 256;
    bool a0 = (i > j0) && (mrow[j0] > 0.f);
    bool a1 = (i > j1) && (mrow[j1] > 0.f);
    float x0 = L[j0] + (a0 ? 0.f : -1e30f);
    float x1 = L[j1] + (a1 ? 0.f : -1e30f);
    float mx = blockReduce(fmaxf(x0, x1), true);
    float e0 = expf(x0 - mx);
    float e1 = expf(x1 - mx);
    float s = blockReduce(e0 + e1, false);
    float inv = 1.f / s;
    S[j0] = __float2half_rn(a0 ? e0 * inv : 0.f);
    S[j1] = __float2half_rn(a1 ? e1 * inv : 0.f);
}

// m[row] = dot(prod[row,:], Wm2) + bm2 — one warp per row.
__global__ void rowdot_k(const float* __restrict__ prod, const float* __restrict__ w,
                         const float* __restrict__ b, const float* __restrict__ mask,
                         float* __restrict__ m)
{
    int row = blockIdx.x * 8 + (threadIdx.x >> 5);
    int lane = threadIdx.x & 31;
    if (mask[row] == 0.f) { if (lane == 0) m[row] = 0.f; return; }
    const float4* p = (const float4*)(prod + ((size_t)row << 10));
    const float4* wv = (const float4*)w;
    float s = 0.f;
#pragma unroll
    for (int h = lane; h < 256; h += 32) {
        float4 a = p[h], c = wv[h];
        s = fmaf(a.x, c.x, fmaf(a.y, c.y, fmaf(a.z, c.z, fmaf(a.w, c.w, s))));
    }
#pragma unroll
    for (int o = 16; o; o >>= 1) s += __shfl_xor_sync(0xffffffffu, s, o);
    if (lane == 0) m[row] = s + b[0];
}

// Per-batch masked softmax along sequence. 512 thr/batch.
__global__ void seq_softmax_k(const float* m, const float* mask, float* a)
{
    int b = blockIdx.x;
    int t = threadIdx.x;
    size_t idx = ((size_t)b << 9) + t;
    float msk = mask[idx];
    float x = m[idx] + (msk > 0.f ? 0.f : -1e30f);
    float mx = blockReduce(x, true);
    float e = expf(x - mx);
    float s = blockReduce(e, false);
    a[idx] = (msk > 0.f) ? e / s : 0.f;
}

// out = a[row] * encoding. One block = one row. Dead rows: write zeros.
__global__ void scale_k(const float* a, const float* enc, float* out)
{
    int row = blockIdx.x;
    float s = a[row];
    size_t i = ((size_t)row << 8) + threadIdx.x;   // float4 index
    if (s == 0.f) {
        ((float4*)out)[i] = make_float4(0.f, 0.f, 0.f, 0.f);
        return;
    }
    float4 e = ((const float4*)enc)[i];
    float4 o;
    o.x = e.x * s; o.y = e.y * s; o.z = e.z * s; o.w = e.w * s;
    ((float4*)out)[i] = o;
}

static const int SMEM_H = 3 * 2 * 128 * 144;   // 110592

extern "C" void kernel_launch(void* const* d_in, const int* in_sizes, int n_in,
                              void* d_out, int out_size)
{
    const float* cas_emb     = (const float*)d_in[0];
    const float* cas_mask    = (const float*)d_in[1];
    const float* time_weight = (const float*)d_in[2];
    const float* W1  = (const float*)d_in[3];
    const float* b1  = (const float*)d_in[4];
    const float* Wh  = (const float*)d_in[5];
    const float* bh  = (const float*)d_in[6];
    const float* Wt  = (const float*)d_in[7];
    const float* bt  = (const float*)d_in[8];
    const float* Wg  = (const float*)d_in[9];
    const float* bg  = (const float*)d_in[10];
    const float* Wm1 = (const float*)d_in[11];
    const float* bm1 = (const float*)d_in[12];
    const float* Wti = (const float*)d_in[13];
    const float* bti = (const float*)d_in[14];
    const float* Wm2 = (const float*)d_in[15];
    const float* bm2 = (const float*)d_in[16];
    float* out = (float*)d_out;

    float  *cat, *head, *tail, *logits, *enc, *mvec, *avec;
    __half *cath, *hth, *scoreh, *ench, *embh, *twh, *wth;
    cudaGetSymbolAddress((void**)&cat,    g_cat);
    cudaGetSymbolAddress((void**)&cath,   g_cath);
    cudaGetSymbolAddress((void**)&head,   g_head);
    cudaGetSymbolAddress((void**)&tail,   g_tail);
    cudaGetSymbolAddress((void**)&hth,    g_hth);
    cudaGetSymbolAddress((void**)&logits, g_logits);
    cudaGetSymbolAddress((void**)&scoreh, g_scoreh);
    cudaGetSymbolAddress((void**)&enc,    g_enc);
    cudaGetSymbolAddress((void**)&ench,   g_ench);
    cudaGetSymbolAddress((void**)&embh,   g_embh);
    cudaGetSymbolAddress((void**)&twh,    g_twh);
    cudaGetSymbolAddress((void**)&wth,    g_wth);
    cudaGetSymbolAddress((void**)&mvec,   g_m);
    cudaGetSymbolAddress((void**)&avec,   g_a);

    cudaFuncSetAttribute(gemm_h<0,7,false>, cudaFuncAttributeMaxDynamicSharedMemorySize, SMEM_H);
    cudaFuncSetAttribute(gemm_h<0,9,true >, cudaFuncAttributeMaxDynamicSharedMemorySize, SMEM_H);
    cudaFuncSetAttribute(gemm_h<1,1,true >, cudaFuncAttributeMaxDynamicSharedMemorySize, SMEM_H);
    cudaFuncSetAttribute(gemm_h<2,1,true >, cudaFuncAttributeMaxDynamicSharedMemorySize, SMEM_H);
    cudaFuncSetAttribute(gemm_h<3,1,true >, cudaFuncAttributeMaxDynamicSharedMemorySize, SMEM_H);
    cudaFuncSetAttribute(gemm_h<4,1,true >, cudaFuncAttributeMaxDynamicSharedMemorySize, SMEM_H);
    cudaFuncSetAttribute(gemm_h<5,1,true >, cudaFuncAttributeMaxDynamicSharedMemorySize, SMEM_H);

    dim3 blk(512);

    // 1) one-shot preprocessing: all f32->f16 converts (no transposes)
    prep_k<<<23616, 256>>>(cas_emb, time_weight, W1, Wh, Wt, Wg, Wm1, Wti,
                           embh, twh, wth);

    // 2) cas_hidden = elu(emb @ W1 + b1)*mask -> cat f32 + cath half  [NN]
    gemm_h<2,1,true><<<dim3(8,128,1), blk, SMEM_H>>>(
        embh, wth + OFF_W1, cat, cath, DE, DE, HD, 2048,
        0, 0, 0, b1, nullptr, cas_mask, nullptr, 0, 0, cas_mask, 0);

    // 3) fused head|tail: hth = half(cas_hidden @ [Wh|Wt] + [bh|bt])  [NN, N=2048]
    gemm_h<1,1,true><<<dim3(16,128,1), blk, SMEM_H>>>(
        cath, wth + OFF_Wht, nullptr, hth, HD, 2048, 2048, 2048,
        0, 0, 0, bh, bt, nullptr, nullptr, 0, 0, cas_mask, 0);

    // 4) logits[b] = head_b @ tail_b^T  [NT] — causal skip + row/col gates
    gemm_h<0,7,false><<<dim3(4,4,BSZ), blk, SMEM_H>>>(
        hth, hth + 1024, logits, nullptr, HD, 2048, 2048, SL,
        (long)SL * 2048, (long)SL * 2048, (long)SL * SL,
        nullptr, nullptr, nullptr, nullptr, 0, 0, cas_mask, SL);

    // 5) masked causal softmax -> half scores
    attn_softmax_k<<<ROWS, 256>>>(logits, cas_mask, scoreh);

    // 6) depend[b] = score_b @ hidden_b  [NN, B=cath] — row gate + K-trunc
    gemm_h<0,9,true><<<dim3(8,4,BSZ), blk, SMEM_H>>>(
        scoreh, cath, cat + 1024, cath + 1024, SL, SL, 2048, 2048,
        (long)SL * SL, (long)SL * 2048, (long)SL * 2048,
        nullptr, nullptr, nullptr, nullptr, 0, 0, cas_mask, SL);

    // 7) enc = (g*h + (1-g)*d)*mask -> enc f32 + ench half  [NN, Wg]
    gemm_h<3,1,true><<<dim3(8,128,1), blk, SMEM_H>>>(
        cath, wth + OFF_Wg, enc, ench, 2048, 2048, HD, HD,
        0, 0, 0, bg, nullptr, cas_mask, cat, 2048, 1024, cas_mask, 0);

    // 8) time_inf = elu(tw @ Wti + bti) -> tail f32  [NN]
    gemm_h<4,1,true><<<dim3(8,128,1), blk, SMEM_H>>>(
        twh, wth + OFF_Wti, tail, nullptr, DT, DT, HD, HD,
        0, 0, 0, bti, nullptr, nullptr, nullptr, 0, 0, cas_mask, 0);

    // 9) prod = elu(enc @ Wm1 + bm1) * time_inf -> head f32  [NN]
    gemm_h<5,1,true><<<dim3(8,128,1), blk, SMEM_H>>>(
        ench, wth + OFF_Wm1, head, nullptr, HD, HD, HD, HD,
        0, 0, 0, bm1, nullptr, nullptr, tail, HD, 0, cas_mask, 0);

    // 10) m = prod @ Wm2 + bm2 (warp per row)
    rowdot_k<<<ROWS / 8, 256>>>(head, Wm2, bm2, cas_mask, mvec);

    // 11) a = masked softmax over sequence
    seq_softmax_k<<<BSZ, 512>>>(mvec, cas_mask, avec);

    // 12) out = a * encoding
    scale_k<<<ROWS, 256>>>(avec, enc, out);
}

// round 17
// speedup vs baseline: 8.4300x; 1.1599x over previous
#include <cuda_runtime.h>
#include <cuda_fp16.h>
#include <math.h>
#include <stdint.h>

// Problem constants
#define BSZ 32
#define SL  512
#define HD  1024
#define DE  1024
#define DT  64
#define ROWS (BSZ*SL)          // 16384

// ---------------- scratch (__device__ globals, alloc-free) ----------------
// "packed" = live rows only, batches contiguous: packed row = cum[b]+i, i<len[b]
__device__ float  g_cat[(size_t)ROWS * 2048];     // packed f32: [:, :1024]=hidden, [:,1024:]=depend
__device__ __half g_cath[(size_t)ROWS * 2048];    // packed half copy
__device__ float  g_head[(size_t)ROWS * HD];      // packed f32: prod
__device__ float  g_tail[(size_t)ROWS * HD];      // packed f32: time_inf
__device__ __half g_hth[(size_t)ROWS * 2048];     // packed half: [head | tail]
__device__ float  g_logits[(size_t)BSZ * SL * SL];  // per-batch orig layout
__device__ __half g_scoreh[(size_t)BSZ * SL * SL];  // per-batch orig layout
__device__ float  g_enc[(size_t)ROWS * HD];       // packed
__device__ __half g_ench[(size_t)ROWS * HD];      // packed
__device__ __half g_embh[(size_t)ROWS * DE];      // packed
__device__ __half g_twh[(size_t)ROWS * DT];       // packed
__device__ __half g_wth[6356992];                 // half weights (natural [K,N])
__device__ float  g_m[ROWS];                      // packed
__device__ float  g_a[ROWS];                      // ORIG layout (for scale)
__device__ int    g_ilen[BSZ];
__device__ int    g_icum[BSZ + 1];
__device__ int    g_itot[1];

// half-offsets in g_wth (all [K,N] row-major)
#define OFF_W1   0          // [1024,1024]
#define OFF_Wht  1048576    // [1024,2048] = [Wh | Wt]
#define OFF_Wg   3145728    // [2048,1024]
#define OFF_Wm1  5242880    // [1024,1024]
#define OFF_Wti  6291456    // [64,1024]

__device__ __forceinline__ float eluf(float x) { return x > 0.f ? x : expm1f(x); }

__device__ __forceinline__ void mma_f16(float c[4], const uint32_t a[4], const uint32_t b[2]) {
    asm volatile(
        "mma.sync.aligned.m16n8k16.row.col.f32.f16.f16.f32 "
        "{%0,%1,%2,%3},{%4,%5,%6,%7},{%8,%9},{%0,%1,%2,%3};"
        : "+f"(c[0]), "+f"(c[1]), "+f"(c[2]), "+f"(c[3])
        : "r"(a[0]), "r"(a[1]), "r"(a[2]), "r"(a[3]), "r"(b[0]), "r"(b[1]));
}
#define LDSM4(r0, r1, r2, r3, addr) \
    asm volatile("ldmatrix.sync.aligned.m8n8.x4.shared.b16 {%0,%1,%2,%3}, [%4];" \
                 : "=r"(r0), "=r"(r1), "=r"(r2), "=r"(r3) : "r"(addr))
#define LDSM4T(r0, r1, r2, r3, addr) \
    asm volatile("ldmatrix.sync.aligned.m8n8.x4.trans.shared.b16 {%0,%1,%2,%3}, [%4];" \
                 : "=r"(r0), "=r"(r1), "=r"(r2), "=r"(r3) : "r"(addr))
#define CP16(dst, src) \
    asm volatile("cp.async.cg.shared.global [%0], [%1], 16;" :: "r"(dst), "l"(src))
#define CP_COMMIT asm volatile("cp.async.commit_group;")
#define CP_WAIT2  asm volatile("cp.async.wait_group 2;" ::: "memory")

// ---------------------------------------------------------------------------
// fp16 tensor-core GEMM, 512 threads (16 warps, 4x4 grid, 32x32 warp tile).
//  BNN=false: C = epi(A[M,K] @ B[N,K]^T)   BNN=true: C = epi(A[M,K] @ B[K,N])
// FLAGS: 1=gate row0>=total, 2=gate row0>=len[z], 4=gate col0>=len[z],
//        8=causal tile skip, 16=K-trunc min(row0+128, ceil64(len)),
//        32=A base cum[z]*lda, 64=B base cum[z]*ldb,
//        128=C base cum[z]*ldc + per-row store guard (m<len[z])
// EPI: 0=none, 1=bias(+bias2 for n>=1024), 3=sigmoid-gate-blend, 4=elu, 5=elu*aux
// ---------------------------------------------------------------------------
template<int EPI, int FLAGS, bool BNN>
__global__ __launch_bounds__(512, 2)
void gemm_h(const __half* __restrict__ A, const __half* __restrict__ B,
            float* __restrict__ C, __half* __restrict__ C2,
            int K, int lda, int ldb, int ldc,
            long sA, long sB, long sC,
            const float* __restrict__ bias, const float* __restrict__ bias2,
            const float* __restrict__ aux, int auxld, int auxoff,
            const int* __restrict__ lenA, const int* __restrict__ cumA,
            const int* __restrict__ totA)
{
    const int z = blockIdx.z;
    const int row0 = blockIdx.y * 128;
    const int col0 = blockIdx.x * 128;

    if (FLAGS & 8) { if (blockIdx.x > blockIdx.y) return; }
    if (FLAGS & 1) { if (row0 >= totA[0]) return; }
    int lenz = 0, cumz = 0;
    if (FLAGS & (2 | 4 | 16 | 32 | 64 | 128)) { lenz = lenA[z]; cumz = cumA[z]; }
    if (FLAGS & 2) { if (row0 >= lenz) return; }
    if (FLAGS & 4) { if (col0 >= lenz) return; }

    A += (FLAGS & 32) ? (size_t)cumz * lda : (size_t)z * sA;
    B += (FLAGS & 64) ? (size_t)cumz * ldb : (size_t)z * sB;
    const size_t cb = (FLAGS & 128) ? (size_t)cumz * ldc : (size_t)z * sC;

    int Ke = K;
    if (FLAGS & 16) {
        int kc = row0 + 128; if (kc > Ke) kc = Ke;
        int kl = (lenz + 63) & ~63; if (kl > Ke) kl = Ke;
        Ke = kc < kl ? kc : kl;
    }
    const int nt = Ke >> 6;                     // BK = 64

    constexpr int STAGE_B = 2 * 128 * 144;
    extern __shared__ char smem[];
    uint32_t sb;
    asm("{ .reg .u64 t; cvta.to.shared.u64 t, %1; cvt.u32.u64 %0, t; }" : "=r"(sb) : "l"(smem));

    const int tid = threadIdx.x, lane = tid & 31, wid = tid >> 5;
    const int wr = wid >> 2, wc = wid & 3;
    const int group = lane >> 2, tig = lane & 3;

    float acc[2][4][4];
#pragma unroll
    for (int i = 0; i < 2; i++)
#pragma unroll
        for (int j = 0; j < 4; j++)
#pragma unroll
            for (int c = 0; c < 4; c++) acc[i][j][c] = 0.f;

    auto load = [&](int s, int kt) {
        const int k0 = kt << 6;
        const uint32_t ab = sb + s * STAGE_B;
        const uint32_t bb = ab + 128 * 144;
#pragma unroll
        for (int p = 0; p < 2; p++) {
            int idx = tid + (p << 9);
            int r = idx >> 3;
            int c8 = (idx & 7) << 3;
            CP16(ab + r * 144 + (c8 << 1), A + (size_t)(row0 + r) * lda + k0 + c8);
            if (BNN) {
                int br = idx >> 4;
                int bc16 = (idx & 15) << 4;
                CP16(bb + br * 272 + bc16, B + (size_t)(k0 + br) * ldb + col0 + (bc16 >> 1));
            } else {
                CP16(bb + r * 144 + (c8 << 1), B + (size_t)(col0 + r) * ldb + k0 + c8);
            }
        }
    };

    load(0, 0); CP_COMMIT;
    if (nt > 1) load(1, 1);
    CP_COMMIT;

    for (int t = 0; t < nt; t++) {
        if (t + 2 < nt) load((t + 2) % 3, t + 2);
        CP_COMMIT;
        CP_WAIT2;
        __syncthreads();

        const uint32_t ab = sb + (t % 3) * STAGE_B;
        const uint32_t bb = ab + 128 * 144;
        const uint32_t koff = ((lane >> 4) << 4);
        const int rsel = lane & 15;

#pragma unroll
        for (int kk4 = 0; kk4 < 4; kk4++) {
            uint32_t af[2][4];
            {
                const uint32_t kb = (kk4 << 5) + koff;
#pragma unroll
                for (int mf = 0; mf < 2; mf++) {
                    uint32_t addr = ab + (uint32_t)(wr * 32 + mf * 16 + rsel) * 144 + kb;
                    LDSM4(af[mf][0], af[mf][1], af[mf][2], af[mf][3], addr);
                }
            }
            uint32_t bf[4][2];
#pragma unroll
            for (int g = 0; g < 2; g++) {
                uint32_t r0, r1, r2, r3;
                if (BNN) {
                    uint32_t addr = bb
                        + (uint32_t)(kk4 * 16 + (lane & 7) + ((lane >> 4) << 3)) * 272
                        + (uint32_t)(wc * 32 + g * 16 + ((lane >> 3) & 1) * 8) * 2;
                    LDSM4T(r0, r1, r2, r3, addr);
                } else {
                    const uint32_t kb = (kk4 << 5) + koff;
                    uint32_t addr = bb + (uint32_t)(wc * 32 + g * 16 + rsel) * 144 + kb;
                    LDSM4(r0, r1, r2, r3, addr);
                }
                bf[2 * g][0] = r0; bf[2 * g][1] = r2;
                bf[2 * g + 1][0] = r1; bf[2 * g + 1][1] = r3;
            }
#pragma unroll
            for (int mf = 0; mf < 2; mf++)
#pragma unroll
                for (int nf = 0; nf < 4; nf++)
                    mma_f16(acc[mf][nf], af[mf], bf[nf]);
        }
        __syncthreads();
    }

    // ---- fused epilogue (all packed rows live; no rowmask) ----
#pragma unroll
    for (int mf = 0; mf < 2; mf++) {
        int rbase = row0 + wr * 32 + mf * 16 + group;
#pragma unroll
        for (int half = 0; half < 2; half++) {
            int m = rbase + half * 8;
            bool mlive = true;
            if (FLAGS & 128) mlive = (m < lenz);
#pragma unroll
            for (int nf = 0; nf < 4; nf++) {
                int n = col0 + wc * 32 + nf * 8 + 2 * tig;
                float v0 = acc[mf][nf][half * 2 + 0];
                float v1 = acc[mf][nf][half * 2 + 1];
                if (EPI != 0) {
                    const float* bp = (bias2 && n >= 1024) ? bias2 - 1024 : bias;
                    v0 += bp[n]; v1 += bp[n + 1];
                }
                if (EPI == 3) {
                    float2 h = *(const float2*)&aux[(size_t)m * auxld + n];
                    float2 d = *(const float2*)&aux[(size_t)m * auxld + n + auxoff];
                    float g0 = 1.f / (1.f + expf(-v0));
                    float g1 = 1.f / (1.f + expf(-v1));
                    v0 = g0 * h.x + (1.f - g0) * d.x;
                    v1 = g1 * h.y + (1.f - g1) * d.y;
                } else if (EPI == 4) {
                    v0 = eluf(v0);
                    v1 = eluf(v1);
                } else if (EPI == 5) {
                    float2 ax = *(const float2*)&aux[(size_t)m * auxld + n];
                    v0 = eluf(v0) * ax.x;
                    v1 = eluf(v1) * ax.y;
                }
                if (mlive) {
                    size_t off = cb + (size_t)m * ldc + n;
                    if (C)  *(float2*)&C[off] = make_float2(v0, v1);
                    if (C2) *(__half2*)&C2[off] = __floats2half2_rn(v0, v1);
                }
            }
        }
    }
}

// ---------------------------------------------------------------------------
__device__ __forceinline__ float blockReduce(float v, bool isMax)
{
    __shared__ float sh[32];
    int lane = threadIdx.x & 31;
    int w = threadIdx.x >> 5;
    int nw = blockDim.x >> 5;
#pragma unroll
    for (int o = 16; o; o >>= 1) {
        float u = __shfl_xor_sync(0xffffffffu, v, o);
        v = isMax ? fmaxf(v, u) : v + u;
    }
    if (lane == 0) sh[w] = v;
    __syncthreads();
    if (w == 0) {
        v = (lane < nw) ? sh[lane] : (isMax ? -INFINITY : 0.f);
#pragma unroll
        for (int o = 16; o; o >>= 1) {
            float u = __shfl_xor_sync(0xffffffffu, v, o);
            v = isMax ? fmaxf(v, u) : v + u;
        }
        if (lane == 0) sh[0] = v;
    }
    __syncthreads();
    v = sh[0];
    __syncthreads();
    return v;
}

// len[b] = number of live rows (prefix mask -> count)
__global__ void len_k(const float* __restrict__ mask, int* __restrict__ len)
{
    int b = blockIdx.x;
    float v = mask[((size_t)b << 9) + threadIdx.x];
    float s = blockReduce(v, false);
    if (threadIdx.x == 0) len[b] = (int)(s + 0.5f);
}

// exclusive scan of len -> cum; total -> tot
__global__ void scan_k(const int* __restrict__ len, int* __restrict__ cum,
                       int* __restrict__ tot)
{
    int lane = threadIdx.x;
    int v = len[lane];
    int inc = v;
#pragma unroll
    for (int o = 1; o < 32; o <<= 1) {
        int u = __shfl_up_sync(0xffffffffu, inc, o);
        if (lane >= o) inc += u;
    }
    cum[lane] = inc - v;
    if (lane == 31) { tot[0] = inc; cum[32] = inc; }
}

// One-shot preprocessing: convert to half; emb/tw gather-packed by live rows.
__global__ void prep_k(const float* __restrict__ emb, const float* __restrict__ tw,
                       const float* __restrict__ W1, const float* __restrict__ Wh,
                       const float* __restrict__ Wt, const float* __restrict__ Wg,
                       const float* __restrict__ Wm1, const float* __restrict__ Wti,
                       __half* __restrict__ embh, __half* __restrict__ twh,
                       __half* __restrict__ wth,
                       const int* __restrict__ len, const int* __restrict__ cum)
{
    int b = blockIdx.x;
    const float* src;
    __half* dst;
    size_t i;
    int job = 0;          // 0=plain, 1=emb pack, 2=tw pack, 3=Wh ilv, 4=Wt ilv
    if (b < 16384)      { src = emb; dst = embh;          i = (size_t)b * 256 + threadIdx.x; job = 1; }
    else if (b < 17408) { src = tw;  dst = twh;           i = (size_t)(b - 16384) * 256 + threadIdx.x; job = 2; }
    else if (b < 18432) { src = W1;  dst = wth + OFF_W1;  i = (size_t)(b - 17408) * 256 + threadIdx.x; }
    else if (b < 19456) { src = Wh;  dst = wth + OFF_Wht; i = (size_t)(b - 18432) * 256 + threadIdx.x; job = 3; }
    else if (b < 20480) { src = Wt;  dst = wth + OFF_Wht; i = (size_t)(b - 19456) * 256 + threadIdx.x; job = 4; }
    else if (b < 22528) { src = Wg;  dst = wth + OFF_Wg;  i = (size_t)(b - 20480) * 256 + threadIdx.x; }
    else if (b < 23552) { src = Wm1; dst = wth + OFF_Wm1; i = (size_t)(b - 22528) * 256 + threadIdx.x; }
    else                { src = Wti; dst = wth + OFF_Wti; i = (size_t)(b - 23552) * 256 + threadIdx.x; }

    float4 v = ((const float4*)src)[i];
    __half2 h0 = __floats2half2_rn(v.x, v.y);
    __half2 h1 = __floats2half2_rn(v.z, v.w);
    size_t e = i * 4;
    if (job == 1 || job == 2) {
        int cols = (job == 1) ? 1024 : 64;
        size_t row = e / cols, col = e % cols;
        int bb = (int)(row >> 9), r = (int)(row & 511);
        if (r >= len[bb]) return;                       // dead row: skip
        e = (size_t)(cum[bb] + r) * cols + col;
    } else if (job == 3 || job == 4) {
        size_t k = e >> 10, n = e & 1023;
        e = k * 2048 + (job == 4 ? 1024 : 0) + n;
    }
    *(__half2*)(dst + e)     = h0;
    *(__half2*)(dst + e + 2) = h1;
}

// Masked causal softmax: f32 logits -> half scores (orig per-batch layout).
__global__ void attn_softmax_k(const float* __restrict__ logits,
                               const float* __restrict__ mask,
                               __half* __restrict__ score)
{
    int row = blockIdx.x;
    int b = row >> 9;
    int i = row & 511;
    const float* mrow = mask + ((size_t)b << 9);
    if (mrow[i] == 0.f) return;
    const float* L = logits + ((size_t)row << 9);
    __half* S = score + ((size_t)row << 9);
    int t = threadIdx.x;
    int j0 = t, j1 = t + 256;
    bool a0 = (i > j0) && (mrow[j0] > 0.f);
    bool a1 = (i > j1) && (mrow[j1] > 0.f);
    float x0 = L[j0] + (a0 ? 0.f : -1e30f);
    float x1 = L[j1] + (a1 ? 0.f : -1e30f);
    float mx = blockReduce(fmaxf(x0, x1), true);
    float e0 = expf(x0 - mx);
    float e1 = expf(x1 - mx);
    float s = blockReduce(e0 + e1, false);
    float inv = 1.f / s;
    S[j0] = __float2half_rn(a0 ? e0 * inv : 0.f);
    S[j1] = __float2half_rn(a1 ? e1 * inv : 0.f);
}

// m[packed_row] = dot(prod[packed_row,:], Wm2) + bm2 — one warp per row.
__global__ void rowdot_k(const float* __restrict__ prod, const float* __restrict__ w,
                         const float* __restrict__ b, const int* __restrict__ tot,
                         float* __restrict__ m)
{
    int row = blockIdx.x * 8 + (threadIdx.x >> 5);
    if (row >= tot[0]) return;
    int lane = threadIdx.x & 31;
    const float4* p = (const float4*)(prod + ((size_t)row << 10));
    const float4* wv = (const float4*)w;
    float s = 0.f;
#pragma unroll
    for (int h = lane; h < 256; h += 32) {
        float4 a = p[h], c = wv[h];
        s = fmaf(a.x, c.x, fmaf(a.y, c.y, fmaf(a.z, c.z, fmaf(a.w, c.w, s))));
    }
#pragma unroll
    for (int o = 16; o; o >>= 1) s += __shfl_xor_sync(0xffffffffu, s, o);
    if (lane == 0) m[row] = s + b[0];
}

// Per-batch masked softmax along sequence (reads packed m, writes orig a).
__global__ void seq_softmax_k(const float* __restrict__ m, const int* __restrict__ len,
                              const int* __restrict__ cum, float* __restrict__ a)
{
    int b = blockIdx.x;
    int t = threadIdx.x;
    int L = len[b], Cc = cum[b];
    float x = (t < L) ? m[Cc + t] : -1e30f;
    float mx = blockReduce(x, true);
    float e = (t < L) ? expf(x - mx) : 0.f;
    float s = blockReduce(e, false);
    a[((size_t)b << 9) + t] = (t < L) ? e / s : 0.f;
}

// out[orig] = a[orig] * enc[packed]. One block = one orig row.
__global__ void scale_k(const float* __restrict__ a, const float* __restrict__ enc,
                        const int* __restrict__ len, const int* __restrict__ cum,
                        float* __restrict__ out)
{
    int row = blockIdx.x;
    int b = row >> 9, i = row & 511;
    size_t o = ((size_t)row << 8) + threadIdx.x;
    if (i >= len[b]) {
        ((float4*)out)[o] = make_float4(0.f, 0.f, 0.f, 0.f);
        return;
    }
    float s = a[row];
    float4 e = ((const float4*)enc)[(((size_t)(cum[b] + i)) << 8) + threadIdx.x];
    float4 r;
    r.x = e.x * s; r.y = e.y * s; r.z = e.z * s; r.w = e.w * s;
    ((float4*)out)[o] = r;
}

static const int SMEM_H = 3 * 2 * 128 * 144;   // 110592

extern "C" void kernel_launch(void* const* d_in, const int* in_sizes, int n_in,
                              void* d_out, int out_size)
{
    const float* cas_emb     = (const float*)d_in[0];
    const float* cas_mask    = (const float*)d_in[1];
    const float* time_weight = (const float*)d_in[2];
    const float* W1  = (const float*)d_in[3];
    const float* b1  = (const float*)d_in[4];
    const float* Wh  = (const float*)d_in[5];
    const float* bh  = (const float*)d_in[6];
    const float* Wt  = (const float*)d_in[7];
    const float* bt  = (const float*)d_in[8];
    const float* Wg  = (const float*)d_in[9];
    const float* bg  = (const float*)d_in[10];
    const float* Wm1 = (const float*)d_in[11];
    const float* bm1 = (const float*)d_in[12];
    const float* Wti = (const float*)d_in[13];
    const float* bti = (const float*)d_in[14];
    const float* Wm2 = (const float*)d_in[15];
    const float* bm2 = (const float*)d_in[16];
    float* out = (float*)d_out;

    float  *cat, *head, *tail, *logits, *enc, *mvec, *avec;
    __half *cath, *hth, *scoreh, *ench, *embh, *twh, *wth;
    int *ilen, *icum, *itot;
    cudaGetSymbolAddress((void**)&cat,    g_cat);
    cudaGetSymbolAddress((void**)&cath,   g_cath);
    cudaGetSymbolAddress((void**)&head,   g_head);
    cudaGetSymbolAddress((void**)&tail,   g_tail);
    cudaGetSymbolAddress((void**)&hth,    g_hth);
    cudaGetSymbolAddress((void**)&logits, g_logits);
    cudaGetSymbolAddress((void**)&scoreh, g_scoreh);
    cudaGetSymbolAddress((void**)&enc,    g_enc);
    cudaGetSymbolAddress((void**)&ench,   g_ench);
    cudaGetSymbolAddress((void**)&embh,   g_embh);
    cudaGetSymbolAddress((void**)&twh,    g_twh);
    cudaGetSymbolAddress((void**)&wth,    g_wth);
    cudaGetSymbolAddress((void**)&mvec,   g_m);
    cudaGetSymbolAddress((void**)&avec,   g_a);
    cudaGetSymbolAddress((void**)&ilen,   g_ilen);
    cudaGetSymbolAddress((void**)&icum,   g_icum);
    cudaGetSymbolAddress((void**)&itot,   g_itot);

    cudaFuncSetAttribute(gemm_h<4,1,true >,   cudaFuncAttributeMaxDynamicSharedMemorySize, SMEM_H);
    cudaFuncSetAttribute(gemm_h<1,1,true >,   cudaFuncAttributeMaxDynamicSharedMemorySize, SMEM_H);
    cudaFuncSetAttribute(gemm_h<0,110,false>, cudaFuncAttributeMaxDynamicSharedMemorySize, SMEM_H);
    cudaFuncSetAttribute(gemm_h<0,210,true >, cudaFuncAttributeMaxDynamicSharedMemorySize, SMEM_H);
    cudaFuncSetAttribute(gemm_h<3,1,true >,   cudaFuncAttributeMaxDynamicSharedMemorySize, SMEM_H);
    cudaFuncSetAttribute(gemm_h<5,1,true >,   cudaFuncAttributeMaxDynamicSharedMemorySize, SMEM_H);

    dim3 blk(512);

    // 0) lengths, prefix scan, packed conversion
    len_k<<<BSZ, 512>>>(cas_mask, ilen);
    scan_k<<<1, 32>>>(ilen, icum, itot);
    prep_k<<<23616, 256>>>(cas_emb, time_weight, W1, Wh, Wt, Wg, Wm1, Wti,
                           embh, twh, wth, ilen, icum);

    // 1) cas_hidden = elu(emb @ W1 + b1) -> cat/cath (packed)  [NN]
    gemm_h<4,1,true><<<dim3(8,128,1), blk, SMEM_H>>>(
        embh, wth + OFF_W1, cat, cath, DE, DE, HD, 2048,
        0, 0, 0, b1, nullptr, nullptr, 0, 0, ilen, icum, itot);

    // 2) fused head|tail: hth = half(hidden @ [Wh|Wt] + [bh|bt])  [NN, N=2048]
    gemm_h<1,1,true><<<dim3(16,128,1), blk, SMEM_H>>>(
        cath, wth + OFF_Wht, nullptr, hth, HD, 2048, 2048, 2048,
        0, 0, 0, bh, bt, nullptr, 0, 0, ilen, icum, itot);

    // 3) logits[b] = head_b @ tail_b^T  [NT] — len row/col gates + causal skip
    //    FLAGS = 2|4|8|32|64 = 110; A/B bases cum[z]; C per-batch orig.
    gemm_h<0,110,false><<<dim3(4,4,BSZ), blk, SMEM_H>>>(
        hth, hth + 1024, logits, nullptr, HD, 2048, 2048, SL,
        0, 0, (long)SL * SL,
        nullptr, nullptr, nullptr, 0, 0, ilen, icum, itot);

    // 4) masked causal softmax -> half scores (orig layout)
    attn_softmax_k<<<ROWS, 256>>>(logits, cas_mask, scoreh);

    // 5) depend[b] = score_b @ hidden_b  [NN] — len row gate, K-trunc,
    //    B base cum[z], C packed + guarded.  FLAGS = 2|16|64|128 = 210.
    gemm_h<0,210,true><<<dim3(8,4,BSZ), blk, SMEM_H>>>(
        scoreh, cath, cat + 1024, cath + 1024, SL, SL, 2048, 2048,
        (long)SL * SL, 0, 0,
        nullptr, nullptr, nullptr, 0, 0, ilen, icum, itot);

    // 6) enc = g*h + (1-g)*d -> enc/ench (packed)  [NN, Wg, K=2048]
    gemm_h<3,1,true><<<dim3(8,128,1), blk, SMEM_H>>>(
        cath, wth + OFF_Wg, enc, ench, 2048, 2048, HD, HD,
        0, 0, 0, bg, nullptr, cat, 2048, 1024, ilen, icum, itot);

    // 7) time_inf = elu(tw @ Wti + bti) -> tail (packed)  [NN, K=64]
    gemm_h<4,1,true><<<dim3(8,128,1), blk, SMEM_H>>>(
        twh, wth + OFF_Wti, tail, nullptr, DT, DT, HD, HD,
        0, 0, 0, bti, nullptr, nullptr, 0, 0, ilen, icum, itot);

    // 8) prod = elu(enc @ Wm1 + bm1) * time_inf -> head (packed)  [NN]
    gemm_h<5,1,true><<<dim3(8,128,1), blk, SMEM_H>>>(
        ench, wth + OFF_Wm1, head, nullptr, HD, HD, HD, HD,
        0, 0, 0, bm1, nullptr, tail, HD, 0, ilen, icum, itot);

    // 9) m = prod @ Wm2 + bm2 (warp per packed row)
    rowdot_k<<<ROWS / 8, 256>>>(head, Wm2, bm2, itot, mvec);

    // 10) a = masked softmax over sequence (packed m -> orig a)
    seq_softmax_k<<<BSZ, 512>>>(mvec, ilen, icum, avec);

    // 11) out = a * encoding (orig <- packed)
    scale_k<<<ROWS, 256>>>(avec, enc, ilen, icum, out);
}